// round 4
// baseline (speedup 1.0000x reference)
#include <cuda_runtime.h>
#include <cstdint>
#include <cstddef>

constexpr int kN   = 32;
constexpr int kC   = 256;
constexpr int kT   = 64;
constexpr int kV   = 25;
constexpr int kH   = 8;
constexpr int kWIN = 5;
constexpr int kB   = kN * kT;        // 2048 windows
constexpr int kL   = kWIN * kV;      // 125
constexpr int kU   = kB * kV;        // 51200 unique tokens
constexpr int kM1  = kU + 1;         // + pad row
constexpr int kTV  = kT * kV;        // 1600
constexpr int kXN  = kC * kTV;       // 409600
constexpr float kSCALE = 0.17677669529663687f;  // 1/sqrt(32)

// ---------------- scratch (device globals; reused across stages) ----------------
__device__ float g_nx [(size_t)kM1 * kC];   // nx -> mq -> h1
__device__ float g_q  [(size_t)kM1 * kC];   // q
__device__ float g_k  [(size_t)kM1 * kC];   // k  -> attraw
__device__ float g_v  [(size_t)kM1 * kC];   // v  -> f
__device__ float g_xr [(size_t)kU  * kC];   // gathered x (residual)
__device__ float g_mkv[(size_t)kU  * kC];   // mkv -> y
__device__ float g_ql [(size_t)kM1 * kH];   // q attention logits
__device__ float g_tw [(size_t)kC  * kC];   // t_w @ p_w
__device__ float g_tb [kC];                 // t_b @ p_w + p_b

// ============ prep: tp_w = t_w @ p_w (fp32), tp_b = t_b @ p_w + p_b ============
__global__ void __launch_bounds__(256) k_prep(const float* __restrict__ t_w,
                                              const float* __restrict__ p_w,
                                              const float* __restrict__ t_b,
                                              const float* __restrict__ p_b) {
    __shared__ float srow[kC];
    int j = blockIdx.x, c = threadIdx.x;
    bool isw = (j < kC);
    srow[c] = isw ? t_w[(size_t)j * kC + c] : t_b[c];
    __syncthreads();
    float acc = isw ? 0.f : p_b[c];
#pragma unroll 8
    for (int m = 0; m < kC; m++) acc += srow[m] * p_w[(size_t)m * kC + c];
    if (isw) g_tw[(size_t)j * kC + c] = acc;
    else     g_tb[c] = acc;
}

// ============ LN over C of unique tokens (gather from x) + write raw xr ============
__global__ void __launch_bounds__(256) k_ln_x(const float* __restrict__ x,
                                              const float* __restrict__ g,
                                              const float* __restrict__ b) {
    __shared__ float sx[32][257];
    int tid = threadIdx.x;
    int u0  = blockIdx.x * 32;
    {
        int ur = tid & 31;
        int u  = u0 + ur;
        int cb = tid >> 5;
        bool has = (u < kU);
        size_t base = 0;
        if (has) { int n = u / kTV; base = (size_t)n * kXN + (u - n * kTV); }
#pragma unroll
        for (int j = 0; j < 32; j++) {
            int c = cb * 32 + j;
            sx[ur][c] = has ? x[base + (size_t)c * kTV] : 0.f;
        }
    }
    __syncthreads();
    int lane = tid & 31, warp = tid >> 5;
#pragma unroll
    for (int rr = 0; rr < 4; rr++) {
        int ur = warp * 4 + rr;
        int u  = u0 + ur;
        if (u >= kM1) continue;
        float vals[8];
        float s = 0.f, sq = 0.f;
#pragma unroll
        for (int j = 0; j < 8; j++) {
            float t = sx[ur][lane + 32 * j];
            vals[j] = t; s += t; sq += t * t;
        }
#pragma unroll
        for (int o = 16; o; o >>= 1) {
            s  += __shfl_xor_sync(0xffffffffu, s,  o);
            sq += __shfl_xor_sync(0xffffffffu, sq, o);
        }
        float mean = s * (1.f / kC);
        float var  = sq * (1.f / kC) - mean * mean;
        float rstd = rsqrtf(var + 1e-5f);
#pragma unroll
        for (int j = 0; j < 8; j++) {
            int c = lane + 32 * j;
            g_nx[(size_t)u * kC + c] = (vals[j] - mean) * rstd * g[c] + b[c];
            if (u < kU) g_xr[(size_t)u * kC + c] = vals[j];
        }
    }
}

// ============ tf32 GEMM v3: 3-stage cp.async pipeline, single sync per k-tile ============
// CTA 128(M) x 256(N), 8 warps (2x4), warp tile 64x64.
// NPAIR=2: D = A1@W1 + A2@W2 (K-loop runs twice). EPI: 0 bias; 1 bias+addm; 2 gelu.
constexpr int APITCH = 36;
constexpr int BPITCH = 264;
constexpr int ASZ = 128 * APITCH;   // floats per A stage
constexpr int BSZ = 32 * BPITCH;    // floats per B stage
constexpr int GEMM_SMEM = 3 * (ASZ + BSZ) * 4;  // 156672 bytes

__device__ __forceinline__ uint32_t f2tf(float f) {
    uint32_t r; asm("cvt.rna.tf32.f32 %0, %1;" : "=r"(r) : "f"(f)); return r;
}
__device__ __forceinline__ void mma_tf32(float (&d)[4], const uint32_t (&a)[4],
                                         const uint32_t (&bb)[2]) {
    asm volatile(
        "mma.sync.aligned.m16n8k8.row.col.f32.tf32.tf32.f32 "
        "{%0,%1,%2,%3}, {%4,%5,%6,%7}, {%8,%9}, {%0,%1,%2,%3};\n"
        : "+f"(d[0]), "+f"(d[1]), "+f"(d[2]), "+f"(d[3])
        : "r"(a[0]), "r"(a[1]), "r"(a[2]), "r"(a[3]), "r"(bb[0]), "r"(bb[1]));
}
__device__ __forceinline__ void cpa16(uint32_t dst, const float* src, bool pred) {
    int sz = pred ? 16 : 0;
    asm volatile("cp.async.cg.shared.global [%0], [%1], 16, %2;\n"
                 :: "r"(dst), "l"(src), "r"(sz));
}
__device__ __forceinline__ float gelu_exact(float x) {
    return 0.5f * x * (1.0f + erff(x * 0.70710678118654752f));
}

template<int EPI, int NPAIR>
__global__ void __launch_bounds__(256) k_gemm3(const float* __restrict__ A1,
                                               const float* __restrict__ W1,
                                               const float* __restrict__ A2,
                                               const float* __restrict__ W2,
                                               const float* __restrict__ bias,
                                               const float* __restrict__ addm,
                                               float* __restrict__ D, int M) {
    extern __shared__ float sm[];
    float* As = sm;                 // 3 stages of ASZ
    float* Bs = sm + 3 * ASZ;       // 3 stages of BSZ
    uint32_t sA = (uint32_t)__cvta_generic_to_shared(As);
    uint32_t sB = (uint32_t)__cvta_generic_to_shared(Bs);

    int tid = threadIdx.x, lane = tid & 31, warp = tid >> 5;
    int wm = warp >> 2, wn = warp & 3;          // 2 x 4 warp grid
    int p = lane >> 2, q = lane & 3;
    int row0 = blockIdx.x * 128;

    int ar = tid & 127, ah = tid >> 7;          // A: row ar, k-half ah
    int bk = tid >> 3,  bc = (tid & 7) * 4;     // B: k-row bk, col base bc
    bool arow_ok = (row0 + ar) < M;
    const float* A1g = A1 + (size_t)(row0 + ar) * kC + ah * 16;
    const float* W1g = W1 + (size_t)bk * kC + bc;
    const float* A2g = (NPAIR == 2) ? (A2 + (size_t)(row0 + ar) * kC + ah * 16) : A1g;
    const float* W2g = (NPAIR == 2) ? (W2 + (size_t)bk * kC + bc) : W1g;
    uint32_t adst0 = sA + (uint32_t)((ar * APITCH + ah * 16) * 4);
    uint32_t bdst0 = sB + (uint32_t)((bk * BPITCH + bc) * 4);

    auto issue = [&](int kt) {
        int ktt = kt & 7;
        int buf = kt % 3;
        const float* as = ((NPAIR == 2 && (kt >> 3)) ? A2g : A1g) + ktt * 32;
        const float* bs = ((NPAIR == 2 && (kt >> 3)) ? W2g : W1g) + (size_t)ktt * 32 * kC;
        uint32_t ad = adst0 + (uint32_t)(buf * ASZ * 4);
        uint32_t bd = bdst0 + (uint32_t)(buf * BSZ * 4);
#pragma unroll
        for (int i = 0; i < 4; i++) cpa16(ad + i * 16, as + 4 * i, arow_ok);
#pragma unroll
        for (int i = 0; i < 8; i++) cpa16(bd + i * 128, bs + 32 * i, true);
    };

    float acc[4][8][4] = {};
    const int TOT = 8 * NPAIR;

    issue(0);
    asm volatile("cp.async.commit_group;\n");
    issue(1);
    asm volatile("cp.async.commit_group;\n");

    int mbase = wm * 64, nbase = wn * 64;
#pragma unroll 1
    for (int kt = 0; kt < TOT; kt++) {
        if (kt < TOT - 1) asm volatile("cp.async.wait_group 1;\n");
        else              asm volatile("cp.async.wait_group 0;\n");
        __syncthreads();
        if (kt + 2 < TOT) {
            issue(kt + 2);
            asm volatile("cp.async.commit_group;\n");
        }
        int buf = kt % 3;
        const float* Ab = As + buf * ASZ;
        const float* Bb = Bs + buf * BSZ;
#pragma unroll
        for (int kk = 0; kk < 32; kk += 8) {
            uint32_t af[4][4], bf[8][2];
#pragma unroll
            for (int mi = 0; mi < 4; mi++) {
                const float* a0 = Ab + (mbase + mi * 16 + p) * APITCH + kk + q;
                af[mi][0] = f2tf(a0[0]);
                af[mi][1] = f2tf(a0[8 * APITCH]);
                af[mi][2] = f2tf(a0[4]);
                af[mi][3] = f2tf(a0[8 * APITCH + 4]);
            }
#pragma unroll
            for (int ni = 0; ni < 8; ni++) {
                const float* b0 = Bb + (kk + q) * BPITCH + nbase + ni * 8 + p;
                bf[ni][0] = f2tf(b0[0]);
                bf[ni][1] = f2tf(b0[4 * BPITCH]);
            }
#pragma unroll
            for (int mi = 0; mi < 4; mi++)
#pragma unroll
                for (int ni = 0; ni < 8; ni++)
                    mma_tf32(acc[mi][ni], af[mi], bf[ni]);
        }
    }

    // epilogue
#pragma unroll
    for (int mi = 0; mi < 4; mi++) {
        int r1 = row0 + mbase + mi * 16 + p;
        int r2 = r1 + 8;
#pragma unroll
        for (int ni = 0; ni < 8; ni++) {
            int cc = nbase + ni * 8 + 2 * q;
            float2 bv = *(const float2*)(bias + cc);
            float d0 = acc[mi][ni][0] + bv.x, d1 = acc[mi][ni][1] + bv.y;
            float d2 = acc[mi][ni][2] + bv.x, d3 = acc[mi][ni][3] + bv.y;
            if (EPI == 1) {
                if (r1 < M) { float2 a1 = *(const float2*)(addm + (size_t)r1 * kC + cc); d0 += a1.x; d1 += a1.y; }
                if (r2 < M) { float2 a2 = *(const float2*)(addm + (size_t)r2 * kC + cc); d2 += a2.x; d3 += a2.y; }
            }
            if (EPI == 2) {
                d0 = gelu_exact(d0); d1 = gelu_exact(d1);
                d2 = gelu_exact(d2); d3 = gelu_exact(d3);
            }
            if (r1 < M) { float2 o; o.x = d0; o.y = d1; *(float2*)(D + (size_t)r1 * kC + cc) = o; }
            if (r2 < M) { float2 o; o.x = d2; o.y = d3; *(float2*)(D + (size_t)r2 * kC + cc) = o; }
        }
    }
}

// ============ q attention logits ============
__global__ void __launch_bounds__(256) k_qlog(const float* __restrict__ qa_w,
                                              const float* __restrict__ qa_b, int M) {
    int warp = threadIdx.x >> 5, lane = threadIdx.x & 31;
    int r = blockIdx.x * 8 + warp;
    if (r >= M) return;
    const float* row = g_q + (size_t)r * kC;
    int c0 = lane * 8;
    float4 v0 = *(const float4*)(row + c0);
    float4 v1 = *(const float4*)(row + c0 + 4);
    float vv[8] = {v0.x, v0.y, v0.z, v0.w, v1.x, v1.y, v1.z, v1.w};
    float acc[8] = {};
#pragma unroll
    for (int j = 0; j < 8; j++) {
        const float4* wr = (const float4*)(qa_w + (size_t)(c0 + j) * kH);
        float4 w0 = wr[0], w1 = wr[1];
        acc[0] += vv[j] * w0.x; acc[1] += vv[j] * w0.y;
        acc[2] += vv[j] * w0.z; acc[3] += vv[j] * w0.w;
        acc[4] += vv[j] * w1.x; acc[5] += vv[j] * w1.y;
        acc[6] += vv[j] * w1.z; acc[7] += vv[j] * w1.w;
    }
#pragma unroll
    for (int o = 16; o; o >>= 1)
#pragma unroll
        for (int e = 0; e < 8; e++)
            acc[e] += __shfl_xor_sync(0xffffffffu, acc[e], o);
    if (lane < 8) g_ql[(size_t)r * kH + lane] = (acc[lane] + qa_b[lane]) * kSCALE;
}

// ============ fused per-window pooling ============
__global__ void __launch_bounds__(256) k_pool(const float* __restrict__ ka_w,
                                              const float* __restrict__ ka_b) {
    __shared__ int   su[kL];
    __shared__ float sqw[kH][128];
    __shared__ float skw[kH][128];
    __shared__ float spq[kC];
    int tid = threadIdx.x, lane = tid & 31, h = tid >> 5;
    int b = blockIdx.x, n = b / kT, t = b % kT;

    if (tid < kL) {
        int w = tid / kV, v = tid - w * kV;
        int tp = t + w - 2;
        su[tid] = (tp >= 0 && tp < kT) ? (n * kT + tp) * kV + v : kU;
    }
    float wreg[8][8];
#pragma unroll
    for (int j = 0; j < 8; j++) {
        int c = lane + 32 * j;
        const float4* wr = (const float4*)(ka_w + (size_t)c * kH);
        float4 w0 = wr[0], w1 = wr[1];
        wreg[j][0] = w0.x; wreg[j][1] = w0.y; wreg[j][2] = w0.z; wreg[j][3] = w0.w;
        wreg[j][4] = w1.x; wreg[j][5] = w1.y; wreg[j][6] = w1.z; wreg[j][7] = w1.w;
    }
    float kab = (lane < kH) ? ka_b[lane] : 0.f;
    __syncthreads();

    // ---- q-weight softmax (warp h over l) ----
    {
        float lv[4]; float mx = -1e30f;
#pragma unroll
        for (int i = 0; i < 4; i++) {
            int l = lane + 32 * i;
            lv[i] = (l < kL) ? g_ql[(size_t)su[l] * kH + h] : -1e30f;
            mx = fmaxf(mx, lv[i]);
        }
#pragma unroll
        for (int o = 16; o; o >>= 1) mx = fmaxf(mx, __shfl_xor_sync(0xffffffffu, mx, o));
        float sm = 0.f;
#pragma unroll
        for (int i = 0; i < 4; i++) {
            int l = lane + 32 * i;
            lv[i] = (l < kL) ? expf(lv[i] - mx) : 0.f;
            sm += lv[i];
        }
#pragma unroll
        for (int o = 16; o; o >>= 1) sm += __shfl_xor_sync(0xffffffffu, sm, o);
        float inv = 1.f / sm;
#pragma unroll
        for (int i = 0; i < 4; i++) {
            int l = lane + 32 * i;
            if (l < kL) sqw[h][l] = lv[i] * inv;
        }
    }
    __syncthreads();

    // ---- pass A: pq and mq ----
    float pq = 0.f;
#pragma unroll
    for (int v = 0; v < kV; v++) {
        float a = 0.f;
#pragma unroll
        for (int w = 0; w < kWIN; w++) {
            int l = w * kV + v;
            float val = g_q[(size_t)su[l] * kC + tid];
            pq += sqw[h][l] * val;
            a  += val;
        }
        g_nx[((size_t)b * kV + v) * kC + tid] = a * 0.2f;   // mq
    }
    spq[tid] = pq;
    __syncthreads();

    // ---- pass B: k logits ----
    float pqr[8];
#pragma unroll
    for (int j = 0; j < 8; j++) pqr[j] = spq[lane + 32 * j];
    for (int l = h; l < kL; l += kH) {
        const float* kr = g_k + (size_t)su[l] * kC;
        float acc[8] = {};
#pragma unroll
        for (int j = 0; j < 8; j++) {
            float kp = kr[lane + 32 * j] * pqr[j];
#pragma unroll
            for (int e = 0; e < 8; e++) acc[e] += kp * wreg[j][e];
        }
#pragma unroll
        for (int o = 16; o; o >>= 1)
#pragma unroll
            for (int e = 0; e < 8; e++)
                acc[e] += __shfl_xor_sync(0xffffffffu, acc[e], o);
        if (lane < kH) skw[lane][l] = (acc[lane] + kab) * kSCALE;
    }
    __syncthreads();

    // ---- k-weight softmax ----
    {
        float lv[4]; float mx = -1e30f;
#pragma unroll
        for (int i = 0; i < 4; i++) {
            int l = lane + 32 * i;
            lv[i] = (l < kL) ? skw[h][l] : -1e30f;
            mx = fmaxf(mx, lv[i]);
        }
#pragma unroll
        for (int o = 16; o; o >>= 1) mx = fmaxf(mx, __shfl_xor_sync(0xffffffffu, mx, o));
        float sm = 0.f;
#pragma unroll
        for (int i = 0; i < 4; i++) {
            int l = lane + 32 * i;
            lv[i] = (l < kL) ? expf(lv[i] - mx) : 0.f;
            sm += lv[i];
        }
#pragma unroll
        for (int o = 16; o; o >>= 1) sm += __shfl_xor_sync(0xffffffffu, sm, o);
        float inv = 1.f / sm;
#pragma unroll
        for (int i = 0; i < 4; i++) {
            int l = lane + 32 * i;
            if (l < kL) skw[h][l] = lv[i] * inv;
        }
    }
    __syncthreads();

    // ---- pass C: pk, mv, mkv = pk*mv ----
    float pk = 0.f;
    float mva[kV];
#pragma unroll
    for (int v = 0; v < kV; v++) {
        float a = 0.f;
#pragma unroll
        for (int w = 0; w < kWIN; w++) {
            int l = w * kV + v;
            int u = su[l];
            pk += skw[h][l] * g_k[(size_t)u * kC + tid];
            a  += g_v[(size_t)u * kC + tid];
        }
        mva[v] = a * 0.2f;
    }
#pragma unroll
    for (int v = 0; v < kV; v++)
        g_mkv[((size_t)b * kV + v) * kC + tid] = pk * mva[v];
}

// ============ row LayerNorm (FFN input): g_k(attraw) -> g_v(f) ============
__global__ void __launch_bounds__(256) k_ln_rows(const float* __restrict__ g,
                                                 const float* __restrict__ b) {
    int warp = threadIdx.x >> 5, lane = threadIdx.x & 31;
    int r = blockIdx.x * 8 + warp;
    const float* row = g_k + (size_t)r * kC;
    float vv[8]; float s = 0.f, sq = 0.f;
#pragma unroll
    for (int j = 0; j < 8; j++) {
        float x = row[lane + 32 * j];
        vv[j] = x; s += x; sq += x * x;
    }
#pragma unroll
    for (int o = 16; o; o >>= 1) {
        s  += __shfl_xor_sync(0xffffffffu, s,  o);
        sq += __shfl_xor_sync(0xffffffffu, sq, o);
    }
    float mean = s * (1.f / kC);
    float var  = sq * (1.f / kC) - mean * mean;
    float rstd = rsqrtf(var + 1e-5f);
#pragma unroll
    for (int j = 0; j < 8; j++) {
        int c = lane + 32 * j;
        g_v[(size_t)r * kC + c] = (vv[j] - mean) * rstd * g[c] + b[c];
    }
}

// ============ transpose y (u,c) -> out (n,c,t,v) ============
__global__ void __launch_bounds__(256) k_out(float* __restrict__ out) {
    __shared__ float sy[kV][257];
    int b = blockIdx.x, n = b / kT, t = b % kT;
    int tid = threadIdx.x;
#pragma unroll
    for (int v = 0; v < kV; v++)
        sy[v][tid] = g_mkv[((size_t)b * kV + v) * kC + tid];
    __syncthreads();
    float* ob = out + (size_t)n * kXN + t * kV;
    for (int i = tid; i < kV * kC; i += 256) {
        int c = i / kV, v = i - c * kV;
        ob[(size_t)c * kTV + v] = sy[v][c];
    }
}

// ===================================================================================
extern "C" void kernel_launch(void* const* d_in, const int* in_sizes, int n_in,
                              void* d_out, int out_size) {
    const float* x    = (const float*)d_in[0];
    const float* ln1g = (const float*)d_in[1];
    const float* ln1b = (const float*)d_in[2];
    const float* q_w  = (const float*)d_in[3];
    const float* q_b  = (const float*)d_in[4];
    const float* qa_w = (const float*)d_in[5];
    const float* qa_b = (const float*)d_in[6];
    const float* k_w  = (const float*)d_in[7];
    const float* k_b  = (const float*)d_in[8];
    const float* ka_w = (const float*)d_in[9];
    const float* ka_b = (const float*)d_in[10];
    const float* v_w  = (const float*)d_in[11];
    const float* v_b  = (const float*)d_in[12];
    const float* t_w  = (const float*)d_in[13];
    const float* t_b  = (const float*)d_in[14];
    const float* p_w  = (const float*)d_in[15];
    const float* p_b  = (const float*)d_in[16];
    const float* ffng = (const float*)d_in[17];
    const float* ffnb = (const float*)d_in[18];
    const float* w1   = (const float*)d_in[19];
    const float* b1   = (const float*)d_in[20];
    const float* w2   = (const float*)d_in[21];
    const float* b2   = (const float*)d_in[22];
    float* out = (float*)d_out;

    float *p_nx, *p_q, *p_k, *p_v, *p_xr, *p_mkv, *p_tw, *p_tb;
    cudaGetSymbolAddress((void**)&p_nx,  g_nx);
    cudaGetSymbolAddress((void**)&p_q,   g_q);
    cudaGetSymbolAddress((void**)&p_k,   g_k);
    cudaGetSymbolAddress((void**)&p_v,   g_v);
    cudaGetSymbolAddress((void**)&p_xr,  g_xr);
    cudaGetSymbolAddress((void**)&p_mkv, g_mkv);
    cudaGetSymbolAddress((void**)&p_tw,  g_tw);
    cudaGetSymbolAddress((void**)&p_tb,  g_tb);

    cudaFuncSetAttribute(k_gemm3<0,1>, cudaFuncAttributeMaxDynamicSharedMemorySize, GEMM_SMEM);
    cudaFuncSetAttribute(k_gemm3<1,1>, cudaFuncAttributeMaxDynamicSharedMemorySize, GEMM_SMEM);
    cudaFuncSetAttribute(k_gemm3<2,1>, cudaFuncAttributeMaxDynamicSharedMemorySize, GEMM_SMEM);
    cudaFuncSetAttribute(k_gemm3<1,2>, cudaFuncAttributeMaxDynamicSharedMemorySize, GEMM_SMEM);

    int g1 = (kM1 + 127) / 128;   // 401
    int g2 = (kU  + 127) / 128;   // 400

    // 0) prep: tp_w = t_w@p_w, tp_b = t_b@p_w + p_b
    k_prep<<<kC + 1, 256>>>(t_w, p_w, t_b, p_b);
    // 1) LN of unique tokens (+ raw gather for residual)
    k_ln_x<<<(kM1 + 31) / 32, 256>>>(x, ln1g, ln1b);
    // 2-4) q, k, v projections
    k_gemm3<0,1><<<g1, 256, GEMM_SMEM>>>(p_nx, q_w, nullptr, nullptr, q_b, nullptr, p_q, kM1);
    k_gemm3<0,1><<<g1, 256, GEMM_SMEM>>>(p_nx, k_w, nullptr, nullptr, k_b, nullptr, p_k, kM1);
    k_gemm3<0,1><<<g1, 256, GEMM_SMEM>>>(p_nx, v_w, nullptr, nullptr, v_b, nullptr, p_v, kM1);
    // 5) q attention logits
    k_qlog<<<(kM1 + 7) / 8, 256>>>(qa_w, qa_b, kM1);
    // 6) fused pooling -> mq (in g_nx), mkv
    k_pool<<<kB, 256>>>(ka_w, ka_b);
    // 7) attraw = mkv@tp_w + mq@p_w + tp_b + xr   (-> g_k)  [dual-pair GEMM]
    k_gemm3<1,2><<<g2, 256, GEMM_SMEM>>>(p_mkv, p_tw, p_nx, p_w, p_tb, p_xr, p_k, kU);
    // 8) f = LN(attraw)                           (-> g_v)
    k_ln_rows<<<kU / 8, 256>>>(ffng, ffnb);
    // 9) h1 = gelu(f @ w1 + b1)                   (-> g_nx)
    k_gemm3<2,1><<<g2, 256, GEMM_SMEM>>>(p_v, w1, nullptr, nullptr, b1, nullptr, p_nx, kU);
    // 10) y = h1 @ w2 + b2 + attraw               (-> g_mkv)
    k_gemm3<1,1><<<g2, 256, GEMM_SMEM>>>(p_nx, w2, nullptr, nullptr, b2, p_k, p_mkv, kU);
    // 11) transpose to (N,C,T,V)
    k_out<<<kB, 256>>>(out);
}

// round 6
// speedup vs baseline: 1.1647x; 1.1647x over previous
#include <cuda_runtime.h>
#include <cstdint>
#include <cstddef>

constexpr int kN   = 32;
constexpr int kC   = 256;
constexpr int kT   = 64;
constexpr int kV   = 25;
constexpr int kH   = 8;
constexpr int kWIN = 5;
constexpr int kB   = kN * kT;        // 2048 windows
constexpr int kL   = kWIN * kV;      // 125
constexpr int kU   = kB * kV;        // 51200 unique tokens
constexpr int kM1  = kU + 1;         // + pad row
constexpr int kTV  = kT * kV;        // 1600
constexpr int kXN  = kC * kTV;       // 409600
constexpr float kSCALE = 0.17677669529663687f;  // 1/sqrt(32)

// ---------------- scratch ----------------
__device__ float g_nx [(size_t)kM1 * kC];   // nx -> mq -> h1
__device__ float g_q  [(size_t)kM1 * kC];   // q
__device__ float g_k  [(size_t)kM1 * kC];   // k  -> attraw
__device__ float g_v  [(size_t)kM1 * kC];   // v  -> f
__device__ float g_xr [(size_t)kU  * kC];   // gathered x (residual)
__device__ float g_mkv[(size_t)kU  * kC];   // mkv
__device__ float g_ql [(size_t)kM1 * kH];   // q attention logits
__device__ float g_tw [(size_t)kC  * kC];   // trunc(t_w @ p_w)
__device__ float g_tb [kC];                 // t_b @ p_w + p_b
__device__ float g_wt [6 * 65536];          // trunc copies: q,k,v,p,w1,w2

__device__ __forceinline__ uint32_t f2tf(float f) {
    uint32_t r; asm("cvt.rna.tf32.f32 %0, %1;" : "=r"(r) : "f"(f)); return r;
}
__device__ __forceinline__ float tftrunc(float f) { return __uint_as_float(f2tf(f)); }

// ============ prep: tp_w/tp_b + tf32-truncate all weights ============
__global__ void __launch_bounds__(256) k_prep(const float* __restrict__ t_w,
                                              const float* __restrict__ p_w,
                                              const float* __restrict__ t_b,
                                              const float* __restrict__ p_b,
                                              const float* __restrict__ q_w,
                                              const float* __restrict__ k_w,
                                              const float* __restrict__ v_w,
                                              const float* __restrict__ w1,
                                              const float* __restrict__ w2) {
    int bid = blockIdx.x, c = threadIdx.x;
    if (bid < 257) {
        __shared__ float srow[kC];
        bool isw = (bid < kC);
        srow[c] = isw ? t_w[(size_t)bid * kC + c] : t_b[c];
        __syncthreads();
        float acc = isw ? 0.f : p_b[c];
#pragma unroll 8
        for (int m = 0; m < kC; m++) acc += srow[m] * p_w[(size_t)m * kC + c];
        if (isw) g_tw[(size_t)bid * kC + c] = tftrunc(acc);
        else     g_tb[c] = acc;
    } else {
        int idx = (bid - 257) * 256 + c;      // 0..393215
        int w = idx >> 16, off = idx & 65535;
        const float* s = (w == 0) ? q_w : (w == 1) ? k_w : (w == 2) ? v_w
                       : (w == 3) ? p_w : (w == 4) ? w1 : w2;
        g_wt[idx] = tftrunc(s[off]);
    }
}

// ============ LN of unique tokens (gather) -> trunc nx, raw xr ============
__global__ void __launch_bounds__(256) k_ln_x(const float* __restrict__ x,
                                              const float* __restrict__ g,
                                              const float* __restrict__ b) {
    __shared__ float sx[32][257];
    int tid = threadIdx.x;
    int u0  = blockIdx.x * 32;
    {
        int ur = tid & 31;
        int u  = u0 + ur;
        int cb = tid >> 5;
        bool has = (u < kU);
        size_t base = 0;
        if (has) { int n = u / kTV; base = (size_t)n * kXN + (u - n * kTV); }
#pragma unroll
        for (int j = 0; j < 32; j++) {
            int c = cb * 32 + j;
            sx[ur][c] = has ? x[base + (size_t)c * kTV] : 0.f;
        }
    }
    __syncthreads();
    int lane = tid & 31, warp = tid >> 5;
#pragma unroll
    for (int rr = 0; rr < 4; rr++) {
        int ur = warp * 4 + rr;
        int u  = u0 + ur;
        if (u >= kM1) continue;
        float vals[8];
        float s = 0.f, sq = 0.f;
#pragma unroll
        for (int j = 0; j < 8; j++) {
            float t = sx[ur][lane + 32 * j];
            vals[j] = t; s += t; sq += t * t;
        }
#pragma unroll
        for (int o = 16; o; o >>= 1) {
            s  += __shfl_xor_sync(0xffffffffu, s,  o);
            sq += __shfl_xor_sync(0xffffffffu, sq, o);
        }
        float mean = s * (1.f / kC);
        float var  = sq * (1.f / kC) - mean * mean;
        float rstd = rsqrtf(var + 1e-5f);
#pragma unroll
        for (int j = 0; j < 8; j++) {
            int c = lane + 32 * j;
            g_nx[(size_t)u * kC + c] = tftrunc((vals[j] - mean) * rstd * g[c] + b[c]);
            if (u < kU) g_xr[(size_t)u * kC + c] = vals[j];
        }
    }
}

// ============ tf32 GEMM v4: CTA 64x256, warp 32x64, 2-stage, 2 CTA/SM ============
// EPI: 0 store; 2 gelu+trunc; 3 addm+store+fused-LN(trunc); 4 addm+transposed-out
constexpr int APITCH = 36;
constexpr int BPITCH = 264;
constexpr int ASZ = 64 * APITCH;            // 2304 floats/stage
constexpr int BSZ = 32 * BPITCH;            // 8448 floats/stage
constexpr int GEMM_SMEM = 2 * (ASZ + BSZ) * 4;  // 86016 bytes

__device__ __forceinline__ void mma_tf32(float (&d)[4], const uint32_t (&a)[4],
                                         const uint32_t (&bb)[2]) {
    asm volatile(
        "mma.sync.aligned.m16n8k8.row.col.f32.tf32.tf32.f32 "
        "{%0,%1,%2,%3}, {%4,%5,%6,%7}, {%8,%9}, {%0,%1,%2,%3};\n"
        : "+f"(d[0]), "+f"(d[1]), "+f"(d[2]), "+f"(d[3])
        : "r"(a[0]), "r"(a[1]), "r"(a[2]), "r"(a[3]), "r"(bb[0]), "r"(bb[1]));
}
__device__ __forceinline__ void cpa16(uint32_t dst, const float* src, bool pred) {
    int sz = pred ? 16 : 0;
    asm volatile("cp.async.cg.shared.global [%0], [%1], 16, %2;\n"
                 :: "r"(dst), "l"(src), "r"(sz));
}
__device__ __forceinline__ float gelu_exact(float x) {
    return 0.5f * x * (1.0f + erff(x * 0.70710678118654752f));
}

template<int EPI, int NPAIR>
__global__ void __launch_bounds__(256, 2) k_gemm4(const float* __restrict__ A1,
                                                  const float* __restrict__ W1,
                                                  const float* __restrict__ A2,
                                                  const float* __restrict__ W2,
                                                  const float* __restrict__ bias,
                                                  const float* __restrict__ addm,
                                                  float* __restrict__ D,
                                                  float* __restrict__ D2,
                                                  const float* __restrict__ lng,
                                                  const float* __restrict__ lnb,
                                                  int M) {
    extern __shared__ float sm[];
    float* As = sm;                  // 2 x ASZ
    float* Bs = sm + 2 * ASZ;        // 2 x BSZ
    uint32_t sA = (uint32_t)__cvta_generic_to_shared(As);
    uint32_t sB = (uint32_t)__cvta_generic_to_shared(Bs);

    int tid = threadIdx.x, lane = tid & 31, warp = tid >> 5;
    int wm = warp >> 2, wn = warp & 3;       // 2 x 4
    int p = lane >> 2, q = lane & 3;
    int row0 = blockIdx.x * 64;
    int mbase = wm * 32, nbase = wn * 64;

    int ar = tid & 63, ah = tid >> 6;        // A: row, 8-float chunk (4 of them)
    int bk = tid >> 3, bc = (tid & 7) * 4;   // B: k-row, col base
    bool arow_ok = (row0 + ar) < M;
    const float* A1g = A1 + (size_t)(row0 + ar) * kC + ah * 8;
    const float* W1g = W1 + (size_t)bk * kC + bc;
    const float* A2g = (NPAIR == 2) ? (A2 + (size_t)(row0 + ar) * kC + ah * 8) : A1g;
    const float* W2g = (NPAIR == 2) ? (W2 + (size_t)bk * kC + bc) : W1g;
    uint32_t adst0 = sA + (uint32_t)((ar * APITCH + ah * 8) * 4);
    uint32_t bdst0 = sB + (uint32_t)((bk * BPITCH + bc) * 4);

    auto issue = [&](int kt) {
        int ktt = kt & 7;
        int buf = kt & 1;
        const float* as = ((NPAIR == 2 && (kt >> 3)) ? A2g : A1g) + ktt * 32;
        const float* bs = ((NPAIR == 2 && (kt >> 3)) ? W2g : W1g) + (size_t)ktt * 32 * kC;
        uint32_t ad = adst0 + (uint32_t)(buf * ASZ * 4);
        uint32_t bd = bdst0 + (uint32_t)(buf * BSZ * 4);
        cpa16(ad,      as,     arow_ok);
        cpa16(ad + 16, as + 4, arow_ok);
#pragma unroll
        for (int i = 0; i < 8; i++) cpa16(bd + i * 128, bs + 32 * i, true);
    };

    float acc[2][8][4] = {};
    const int TOT = 8 * NPAIR;

    issue(0);
    asm volatile("cp.async.commit_group;\n");

#pragma unroll 1
    for (int kt = 0; kt < TOT; kt++) {
        asm volatile("cp.async.wait_group 0;\n");
        __syncthreads();
        if (kt + 1 < TOT) {
            issue(kt + 1);
            asm volatile("cp.async.commit_group;\n");
        }
        int buf = kt & 1;
        const float* Ab = As + buf * ASZ;
        const float* Bb = Bs + buf * BSZ;
#pragma unroll
        for (int kk = 0; kk < 32; kk += 8) {
            uint32_t af[2][4], bf[8][2];
#pragma unroll
            for (int mi = 0; mi < 2; mi++) {
                const float* a0 = Ab + (mbase + mi * 16 + p) * APITCH + kk + q;
                af[mi][0] = __float_as_uint(a0[0]);
                af[mi][1] = __float_as_uint(a0[8 * APITCH]);
                af[mi][2] = __float_as_uint(a0[4]);
                af[mi][3] = __float_as_uint(a0[8 * APITCH + 4]);
            }
#pragma unroll
            for (int ni = 0; ni < 8; ni++) {
                const float* b0 = Bb + (kk + q) * BPITCH + nbase + ni * 8 + p;
                bf[ni][0] = __float_as_uint(b0[0]);
                bf[ni][1] = __float_as_uint(b0[4 * BPITCH]);
            }
#pragma unroll
            for (int mi = 0; mi < 2; mi++)
#pragma unroll
                for (int ni = 0; ni < 8; ni++)
                    mma_tf32(acc[mi][ni], af[mi], bf[ni]);
        }
        __syncthreads();
    }

    // ---------------- epilogue ----------------
    float* ep = sm;   // 64 x BPITCH staging (<= GEMM_SMEM)

#pragma unroll
    for (int mi = 0; mi < 2; mi++) {
        int lr1 = mbase + mi * 16 + p;
        int lr2 = lr1 + 8;
        int r1 = row0 + lr1, r2 = row0 + lr2;
#pragma unroll
        for (int ni = 0; ni < 8; ni++) {
            int cc = nbase + ni * 8 + 2 * q;
            float2 bv = *(const float2*)(bias + cc);
            float d0 = acc[mi][ni][0] + bv.x, d1 = acc[mi][ni][1] + bv.y;
            float d2 = acc[mi][ni][2] + bv.x, d3 = acc[mi][ni][3] + bv.y;
            if (EPI == 3 || EPI == 4) {
                float2 a1 = *(const float2*)(addm + (size_t)r1 * kC + cc);
                float2 a2 = *(const float2*)(addm + (size_t)r2 * kC + cc);
                d0 += a1.x; d1 += a1.y; d2 += a2.x; d3 += a2.y;
            }
            if (EPI == 0) {
                if (r1 < M) { float2 o = {d0, d1}; *(float2*)(D + (size_t)r1 * kC + cc) = o; }
                if (r2 < M) { float2 o = {d2, d3}; *(float2*)(D + (size_t)r2 * kC + cc) = o; }
            }
            if (EPI == 2) {
                float2 o1 = {tftrunc(gelu_exact(d0)), tftrunc(gelu_exact(d1))};
                float2 o2 = {tftrunc(gelu_exact(d2)), tftrunc(gelu_exact(d3))};
                if (r1 < M) *(float2*)(D + (size_t)r1 * kC + cc) = o1;
                if (r2 < M) *(float2*)(D + (size_t)r2 * kC + cc) = o2;
            }
            if (EPI == 3) {
                float2 o1 = {d0, d1}, o2 = {d2, d3};
                *(float2*)(D + (size_t)r1 * kC + cc) = o1;   // attraw
                *(float2*)(D + (size_t)r2 * kC + cc) = o2;
                *(float2*)(ep + lr1 * BPITCH + cc) = o1;
                *(float2*)(ep + lr2 * BPITCH + cc) = o2;
            }
            if (EPI == 4) {
                float2 o1 = {d0, d1}, o2 = {d2, d3};
                *(float2*)(ep + lr1 * BPITCH + cc) = o1;
                *(float2*)(ep + lr2 * BPITCH + cc) = o2;
            }
        }
    }

    if (EPI == 3) {   // fused LN over rows -> trunc -> D2
        __syncthreads();
        float gg[8], bb[8];
#pragma unroll
        for (int j = 0; j < 8; j++) {
            int c = lane + 32 * j;
            gg[j] = lng[c]; bb[j] = lnb[c];
        }
#pragma unroll 1
        for (int rr = 0; rr < 8; rr++) {
            int lr = warp * 8 + rr;
            float vals[8]; float s = 0.f, sq = 0.f;
#pragma unroll
            for (int j = 0; j < 8; j++) {
                float t = ep[lr * BPITCH + lane + 32 * j];
                vals[j] = t; s += t; sq += t * t;
            }
#pragma unroll
            for (int o = 16; o; o >>= 1) {
                s  += __shfl_xor_sync(0xffffffffu, s,  o);
                sq += __shfl_xor_sync(0xffffffffu, sq, o);
            }
            float mean = s * (1.f / kC);
            float var  = sq * (1.f / kC) - mean * mean;
            float rstd = rsqrtf(var + 1e-5f);
#pragma unroll
            for (int j = 0; j < 8; j++) {
                int c = lane + 32 * j;
                D2[(size_t)(row0 + lr) * kC + c] = tftrunc((vals[j] - mean) * rstd * gg[j] + bb[j]);
            }
        }
    }

    if (EPI == 4) {   // transposed write to out (n,c,t,v)
        __syncthreads();
#pragma unroll 1
        for (int it = 0; it < 64; it++) {
            int j = it * 256 + tid;
            int c = j >> 6, rr = j & 63;
            unsigned R = (unsigned)(row0 + rr);
            unsigned b = R / 25u;
            unsigned v = R - b * 25u;
            unsigned n = b >> 6, t = b & 63u;
            D[(size_t)n * kXN + (size_t)c * kTV + t * kV + v] = ep[rr * BPITCH + c];
        }
    }
}

// ============ q attention logits ============
__global__ void __launch_bounds__(256) k_qlog(const float* __restrict__ qa_w,
                                              const float* __restrict__ qa_b, int M) {
    int warp = threadIdx.x >> 5, lane = threadIdx.x & 31;
    int r = blockIdx.x * 8 + warp;
    if (r >= M) return;
    const float* row = g_q + (size_t)r * kC;
    int c0 = lane * 8;
    float4 v0 = *(const float4*)(row + c0);
    float4 v1 = *(const float4*)(row + c0 + 4);
    float vv[8] = {v0.x, v0.y, v0.z, v0.w, v1.x, v1.y, v1.z, v1.w};
    float acc[8] = {};
#pragma unroll
    for (int j = 0; j < 8; j++) {
        const float4* wr = (const float4*)(qa_w + (size_t)(c0 + j) * kH);
        float4 w0 = wr[0], w1 = wr[1];
        acc[0] += vv[j] * w0.x; acc[1] += vv[j] * w0.y;
        acc[2] += vv[j] * w0.z; acc[3] += vv[j] * w0.w;
        acc[4] += vv[j] * w1.x; acc[5] += vv[j] * w1.y;
        acc[6] += vv[j] * w1.z; acc[7] += vv[j] * w1.w;
    }
#pragma unroll
    for (int o = 16; o; o >>= 1)
#pragma unroll
        for (int e = 0; e < 8; e++)
            acc[e] += __shfl_xor_sync(0xffffffffu, acc[e], o);
    if (lane < 8) g_ql[(size_t)r * kH + lane] = (acc[lane] + qa_b[lane]) * kSCALE;
}

// ============ fused per-window pooling (de-spilled) ============
constexpr int KAP = 12;   // padded ka_w pitch (floats); 48B stride keeps 16B alignment
__global__ void __launch_bounds__(256) k_pool(const float* __restrict__ ka_w,
                                              const float* __restrict__ ka_b) {
    __shared__ int   su[kL];
    __shared__ float sqw[kH][128];
    __shared__ float skw[kH][128];
    __shared__ float spq[kC];
    __shared__ __align__(16) float skaw[kC * KAP];
    int tid = threadIdx.x, lane = tid & 31, h = tid >> 5;
    int b = blockIdx.x, n = b / kT, t = b % kT;

    // stage ka_w into smem [c][h] with pitch 12
    for (int i = tid; i < kC * kH; i += 256) {
        int c = i >> 3, e = i & 7;
        skaw[c * KAP + e] = ka_w[i];
    }
    if (tid < kL) {
        int w = tid / kV, v = tid - w * kV;
        int tp = t + w - 2;
        su[tid] = (tp >= 0 && tp < kT) ? (n * kT + tp) * kV + v : kU;
    }
    float kab = (lane < kH) ? ka_b[lane] : 0.f;
    __syncthreads();

    // ---- q-weight softmax (warp h over l) ----
    {
        float lv[4]; float mx = -1e30f;
#pragma unroll
        for (int i = 0; i < 4; i++) {
            int l = lane + 32 * i;
            lv[i] = (l < kL) ? g_ql[(size_t)su[l] * kH + h] : -1e30f;
            mx = fmaxf(mx, lv[i]);
        }
#pragma unroll
        for (int o = 16; o; o >>= 1) mx = fmaxf(mx, __shfl_xor_sync(0xffffffffu, mx, o));
        float sm = 0.f;
#pragma unroll
        for (int i = 0; i < 4; i++) {
            int l = lane + 32 * i;
            lv[i] = (l < kL) ? expf(lv[i] - mx) : 0.f;
            sm += lv[i];
        }
#pragma unroll
        for (int o = 16; o; o >>= 1) sm += __shfl_xor_sync(0xffffffffu, sm, o);
        float inv = 1.f / sm;
#pragma unroll
        for (int i = 0; i < 4; i++) {
            int l = lane + 32 * i;
            if (l < kL) sqw[h][l] = lv[i] * inv;
        }
    }
    __syncthreads();

    // ---- pass A: pq + mq ----
    float pq = 0.f;
#pragma unroll 5
    for (int v = 0; v < kV; v++) {
        float a = 0.f;
#pragma unroll
        for (int w = 0; w < kWIN; w++) {
            int l = w * kV + v;
            float val = g_q[(size_t)su[l] * kC + tid];
            pq += sqw[h][l] * val;
            a  += val;
        }
        g_nx[((size_t)b * kV + v) * kC + tid] = tftrunc(a * 0.2f);   // mq
    }
    spq[tid] = pq;
    __syncthreads();

    // ---- pass B: k logits ----
    float pqr[8];
#pragma unroll
    for (int j = 0; j < 8; j++) pqr[j] = spq[lane + 32 * j];
#pragma unroll 1
    for (int l = h; l < kL; l += kH) {
        const float* kr = g_k + (size_t)su[l] * kC;
        float acc[8] = {};
#pragma unroll
        for (int j = 0; j < 8; j++) {
            float kp = kr[lane + 32 * j] * pqr[j];
            const float4* ka = (const float4*)(skaw + (lane + 32 * j) * KAP);
            float4 k0 = ka[0], k1 = ka[1];
            acc[0] += kp * k0.x; acc[1] += kp * k0.y;
            acc[2] += kp * k0.z; acc[3] += kp * k0.w;
            acc[4] += kp * k1.x; acc[5] += kp * k1.y;
            acc[6] += kp * k1.z; acc[7] += kp * k1.w;
        }
#pragma unroll
        for (int o = 16; o; o >>= 1)
#pragma unroll
            for (int e = 0; e < 8; e++)
                acc[e] += __shfl_xor_sync(0xffffffffu, acc[e], o);
        if (lane < kH) skw[lane][l] = (acc[lane] + kab) * kSCALE;
    }
    __syncthreads();

    // ---- k-weight softmax ----
    {
        float lv[4]; float mx = -1e30f;
#pragma unroll
        for (int i = 0; i < 4; i++) {
            int l = lane + 32 * i;
            lv[i] = (l < kL) ? skw[h][l] : -1e30f;
            mx = fmaxf(mx, lv[i]);
        }
#pragma unroll
        for (int o = 16; o; o >>= 1) mx = fmaxf(mx, __shfl_xor_sync(0xffffffffu, mx, o));
        float sm = 0.f;
#pragma unroll
        for (int i = 0; i < 4; i++) {
            int l = lane + 32 * i;
            lv[i] = (l < kL) ? expf(lv[i] - mx) : 0.f;
            sm += lv[i];
        }
#pragma unroll
        for (int o = 16; o; o >>= 1) sm += __shfl_xor_sync(0xffffffffu, sm, o);
        float inv = 1.f / sm;
#pragma unroll
        for (int i = 0; i < 4; i++) {
            int l = lane + 32 * i;
            if (l < kL) skw[h][l] = lv[i] * inv;
        }
    }
    __syncthreads();

    // ---- pass C1: pk ----
    float pk = 0.f;
#pragma unroll 5
    for (int v = 0; v < kV; v++) {
#pragma unroll
        for (int w = 0; w < kWIN; w++) {
            int l = w * kV + v;
            pk += skw[h][l] * g_k[(size_t)su[l] * kC + tid];
        }
    }
    // ---- pass C2: mv -> mkv = pk*mv ----
#pragma unroll 5
    for (int v = 0; v < kV; v++) {
        float a = 0.f;
#pragma unroll
        for (int w = 0; w < kWIN; w++)
            a += g_v[(size_t)su[w * kV + v] * kC + tid];
        g_mkv[((size_t)b * kV + v) * kC + tid] = tftrunc(pk * a * 0.2f);
    }
}

// ===================================================================================
extern "C" void kernel_launch(void* const* d_in, const int* in_sizes, int n_in,
                              void* d_out, int out_size) {
    const float* x    = (const float*)d_in[0];
    const float* ln1g = (const float*)d_in[1];
    const float* ln1b = (const float*)d_in[2];
    const float* q_w  = (const float*)d_in[3];
    const float* q_b  = (const float*)d_in[4];
    const float* qa_w = (const float*)d_in[5];
    const float* qa_b = (const float*)d_in[6];
    const float* k_w  = (const float*)d_in[7];
    const float* k_b  = (const float*)d_in[8];
    const float* ka_w = (const float*)d_in[9];
    const float* ka_b = (const float*)d_in[10];
    const float* v_w  = (const float*)d_in[11];
    const float* v_b  = (const float*)d_in[12];
    const float* t_w  = (const float*)d_in[13];
    const float* t_b  = (const float*)d_in[14];
    const float* p_w  = (const float*)d_in[15];
    const float* p_b  = (const float*)d_in[16];
    const float* ffng = (const float*)d_in[17];
    const float* ffnb = (const float*)d_in[18];
    const float* w1   = (const float*)d_in[19];
    const float* b1   = (const float*)d_in[20];
    const float* w2   = (const float*)d_in[21];
    const float* b2   = (const float*)d_in[22];
    float* out = (float*)d_out;

    float *p_nx, *p_q, *p_k, *p_v, *p_xr, *p_mkv, *p_tw, *p_tb, *p_wt;
    cudaGetSymbolAddress((void**)&p_nx,  g_nx);
    cudaGetSymbolAddress((void**)&p_q,   g_q);
    cudaGetSymbolAddress((void**)&p_k,   g_k);
    cudaGetSymbolAddress((void**)&p_v,   g_v);
    cudaGetSymbolAddress((void**)&p_xr,  g_xr);
    cudaGetSymbolAddress((void**)&p_mkv, g_mkv);
    cudaGetSymbolAddress((void**)&p_tw,  g_tw);
    cudaGetSymbolAddress((void**)&p_tb,  g_tb);
    cudaGetSymbolAddress((void**)&p_wt,  g_wt);

    const float* wt_q = p_wt + 0 * 65536;
    const float* wt_k = p_wt + 1 * 65536;
    const float* wt_v = p_wt + 2 * 65536;
    const float* wt_p = p_wt + 3 * 65536;
    const float* wt_1 = p_wt + 4 * 65536;
    const float* wt_2 = p_wt + 5 * 65536;

    cudaFuncSetAttribute(k_gemm4<0,1>, cudaFuncAttributeMaxDynamicSharedMemorySize, GEMM_SMEM);
    cudaFuncSetAttribute(k_gemm4<2,1>, cudaFuncAttributeMaxDynamicSharedMemorySize, GEMM_SMEM);
    cudaFuncSetAttribute(k_gemm4<3,2>, cudaFuncAttributeMaxDynamicSharedMemorySize, GEMM_SMEM);
    cudaFuncSetAttribute(k_gemm4<4,1>, cudaFuncAttributeMaxDynamicSharedMemorySize, GEMM_SMEM);

    int g1 = (kM1 + 63) / 64;   // 801
    int g2 = kU / 64;           // 800

    // 0) prep: tp_w/tp_b + truncate weights
    k_prep<<<257 + 1536, 256>>>(t_w, p_w, t_b, p_b, q_w, k_w, v_w, w1, w2);
    // 1) LN of unique tokens (trunc nx + raw xr)
    k_ln_x<<<(kM1 + 31) / 32, 256>>>(x, ln1g, ln1b);
    // 2-4) q, k, v projections
    k_gemm4<0,1><<<g1, 256, GEMM_SMEM>>>(p_nx, wt_q, nullptr, nullptr, q_b, nullptr, p_q, nullptr, nullptr, nullptr, kM1);
    k_gemm4<0,1><<<g1, 256, GEMM_SMEM>>>(p_nx, wt_k, nullptr, nullptr, k_b, nullptr, p_k, nullptr, nullptr, nullptr, kM1);
    k_gemm4<0,1><<<g1, 256, GEMM_SMEM>>>(p_nx, wt_v, nullptr, nullptr, v_b, nullptr, p_v, nullptr, nullptr, nullptr, kM1);
    // 5) q attention logits
    k_qlog<<<(kM1 + 7) / 8, 256>>>(qa_w, qa_b, kM1);
    // 6) fused pooling -> mq (g_nx), mkv
    k_pool<<<kB, 256>>>(ka_w, ka_b);
    // 7) attraw = mkv@tp_w + mq@p_w + tp_b + xr -> g_k ; fused LN -> f (g_v)
    k_gemm4<3,2><<<g2, 256, GEMM_SMEM>>>(p_mkv, p_tw, p_nx, wt_p, p_tb, p_xr, p_k, p_v, ffng, ffnb, kU);
    // 8) h1 = trunc(gelu(f @ w1 + b1)) -> g_nx
    k_gemm4<2,1><<<g2, 256, GEMM_SMEM>>>(p_v, wt_1, nullptr, nullptr, b1, nullptr, p_nx, nullptr, nullptr, nullptr, kU);
    // 9) y = h1 @ w2 + b2 + attraw -> transposed out
    k_gemm4<4,1><<<g2, 256, GEMM_SMEM>>>(p_nx, wt_2, nullptr, nullptr, b2, p_k, out, nullptr, nullptr, nullptr, kU);
}

// round 7
// speedup vs baseline: 1.1999x; 1.0302x over previous
#include <cuda_runtime.h>
#include <cstdint>
#include <cstddef>

constexpr int kN   = 32;
constexpr int kC   = 256;
constexpr int kC3  = 768;
constexpr int kT   = 64;
constexpr int kV   = 25;
constexpr int kH   = 8;
constexpr int kWIN = 5;
constexpr int kB   = kN * kT;        // 2048 windows
constexpr int kL   = kWIN * kV;      // 125
constexpr int kU   = kB * kV;        // 51200 unique tokens
constexpr int kM1  = kU + 1;         // + pad row
constexpr int kTV  = kT * kV;        // 1600
constexpr int kXN  = kC * kTV;       // 409600
constexpr float kSCALE = 0.17677669529663687f;  // 1/sqrt(32)

// ---------------- scratch ----------------
__device__ float g_nx  [(size_t)kM1 * kC];    // nx -> mq -> h1
__device__ float g_qkv [(size_t)kM1 * kC3];   // interleaved q|k|v per token
__device__ float g_k   [(size_t)kM1 * kC];    // attraw
__device__ float g_v   [(size_t)kM1 * kC];    // f
__device__ float g_xr  [(size_t)kU  * kC];    // gathered x (residual)
__device__ float g_mkv [(size_t)kU  * kC];    // mkv
__device__ float g_ql  [(size_t)kM1 * kH];    // q attention logits
__device__ float g_tw  [(size_t)kC  * kC];    // trunc(t_w @ p_w)
__device__ float g_tb  [kC];                  // t_b @ p_w + p_b
__device__ float g_wqkv[(size_t)kC * kC3];    // trunc concat [q|k|v] weights
__device__ float g_wt  [3 * 65536];           // trunc copies: p, w1, w2
__device__ float g_qkvb[kC3];                 // concat biases

__device__ __forceinline__ uint32_t f2tf(float f) {
    uint32_t r; asm("cvt.rna.tf32.f32 %0, %1;" : "=r"(r) : "f"(f)); return r;
}
__device__ __forceinline__ float tftrunc(float f) { return __uint_as_float(f2tf(f)); }

// ============ prep: tp_w/tp_b + truncated weight copies + concat ============
__global__ void __launch_bounds__(256) k_prep(const float* __restrict__ t_w,
                                              const float* __restrict__ p_w,
                                              const float* __restrict__ t_b,
                                              const float* __restrict__ p_b,
                                              const float* __restrict__ q_w,
                                              const float* __restrict__ k_w,
                                              const float* __restrict__ v_w,
                                              const float* __restrict__ w1,
                                              const float* __restrict__ w2,
                                              const float* __restrict__ q_b,
                                              const float* __restrict__ k_b,
                                              const float* __restrict__ v_b) {
    int bid = blockIdx.x, c = threadIdx.x;
    if (bid < 257) {
        __shared__ float srow[kC];
        bool isw = (bid < kC);
        srow[c] = isw ? t_w[(size_t)bid * kC + c] : t_b[c];
        __syncthreads();
        float acc = isw ? 0.f : p_b[c];
#pragma unroll 8
        for (int m = 0; m < kC; m++) acc += srow[m] * p_w[(size_t)m * kC + c];
        if (isw) g_tw[(size_t)bid * kC + c] = tftrunc(acc);
        else     g_tb[c] = acc;
    } else if (bid < 257 + 1536) {
        int idx = (bid - 257) * 256 + c;          // 0..393215
        if (idx < kC * kC3) {                     // concat qkv weights
            int row = idx / kC3, col = idx - row * kC3;
            const float* s = (col < 256) ? q_w : (col < 512) ? k_w : v_w;
            g_wqkv[idx] = tftrunc(s[row * kC + (col & 255)]);
        } else {                                  // p, w1, w2
            int j = idx - kC * kC3;
            int w = j >> 16, off = j & 65535;
            const float* s = (w == 0) ? p_w : (w == 1) ? w1 : w2;
            g_wt[j] = tftrunc(s[off]);
        }
    } else {
        int k = bid - (257 + 1536);               // 0..2
        g_qkvb[k * 256 + c] = (k == 0) ? q_b[c] : (k == 1) ? k_b[c] : v_b[c];
    }
}

// ============ LN of unique tokens (gather) -> trunc nx, raw xr ============
__global__ void __launch_bounds__(256) k_ln_x(const float* __restrict__ x,
                                              const float* __restrict__ g,
                                              const float* __restrict__ b) {
    __shared__ float sx[32][257];
    int tid = threadIdx.x;
    int u0  = blockIdx.x * 32;
    {
        int ur = tid & 31;
        int u  = u0 + ur;
        int cb = tid >> 5;
        bool has = (u < kU);
        size_t base = 0;
        if (has) { int n = u / kTV; base = (size_t)n * kXN + (u - n * kTV); }
#pragma unroll
        for (int j = 0; j < 32; j++) {
            int c = cb * 32 + j;
            sx[ur][c] = has ? x[base + (size_t)c * kTV] : 0.f;
        }
    }
    __syncthreads();
    int lane = tid & 31, warp = tid >> 5;
#pragma unroll
    for (int rr = 0; rr < 4; rr++) {
        int ur = warp * 4 + rr;
        int u  = u0 + ur;
        if (u >= kM1) continue;
        float vals[8];
        float s = 0.f, sq = 0.f;
#pragma unroll
        for (int j = 0; j < 8; j++) {
            float t = sx[ur][lane + 32 * j];
            vals[j] = t; s += t; sq += t * t;
        }
#pragma unroll
        for (int o = 16; o; o >>= 1) {
            s  += __shfl_xor_sync(0xffffffffu, s,  o);
            sq += __shfl_xor_sync(0xffffffffu, sq, o);
        }
        float mean = s * (1.f / kC);
        float var  = sq * (1.f / kC) - mean * mean;
        float rstd = rsqrtf(var + 1e-5f);
#pragma unroll
        for (int j = 0; j < 8; j++) {
            int c = lane + 32 * j;
            g_nx[(size_t)u * kC + c] = tftrunc((vals[j] - mean) * rstd * g[c] + b[c]);
            if (u < kU) g_xr[(size_t)u * kC + c] = vals[j];
        }
    }
}

// ============ tf32 GEMM v5: CTA 64x256, runtime ldW/ldD, grid.y = col slab ============
// EPI: 0 store; 2 gelu+trunc; 3 addm+store+fused-LN(trunc)->D2; 4 addm+transposed-out
constexpr int APITCH = 36;
constexpr int BPITCH = 264;
constexpr int ASZ = 64 * APITCH;
constexpr int BSZ = 32 * BPITCH;
constexpr int GEMM_SMEM = 2 * (ASZ + BSZ) * 4;  // 86016 bytes

__device__ __forceinline__ void mma_tf32(float (&d)[4], const uint32_t (&a)[4],
                                         const uint32_t (&bb)[2]) {
    asm volatile(
        "mma.sync.aligned.m16n8k8.row.col.f32.tf32.tf32.f32 "
        "{%0,%1,%2,%3}, {%4,%5,%6,%7}, {%8,%9}, {%0,%1,%2,%3};\n"
        : "+f"(d[0]), "+f"(d[1]), "+f"(d[2]), "+f"(d[3])
        : "r"(a[0]), "r"(a[1]), "r"(a[2]), "r"(a[3]), "r"(bb[0]), "r"(bb[1]));
}
__device__ __forceinline__ void cpa16(uint32_t dst, const float* src, bool pred) {
    int sz = pred ? 16 : 0;
    asm volatile("cp.async.cg.shared.global [%0], [%1], 16, %2;\n"
                 :: "r"(dst), "l"(src), "r"(sz));
}
__device__ __forceinline__ float gelu_exact(float x) {
    return 0.5f * x * (1.0f + erff(x * 0.70710678118654752f));
}

template<int EPI, int NPAIR>
__global__ void __launch_bounds__(256, 2) k_gemm5(const float* __restrict__ A1,
                                                  const float* __restrict__ W1,
                                                  const float* __restrict__ A2,
                                                  const float* __restrict__ W2,
                                                  const float* __restrict__ bias,
                                                  const float* __restrict__ addm,
                                                  float* __restrict__ D,
                                                  float* __restrict__ D2,
                                                  const float* __restrict__ lng,
                                                  const float* __restrict__ lnb,
                                                  int M, int ldW, int ldD) {
    extern __shared__ float sm[];
    float* As = sm;
    float* Bs = sm + 2 * ASZ;
    uint32_t sA = (uint32_t)__cvta_generic_to_shared(As);
    uint32_t sB = (uint32_t)__cvta_generic_to_shared(Bs);

    int coly = blockIdx.y * 256;       // column slab (QKV fused GEMM)
    W1 += coly; bias += coly; D += coly;

    int tid = threadIdx.x, lane = tid & 31, warp = tid >> 5;
    int wm = warp >> 2, wn = warp & 3;
    int p = lane >> 2, q = lane & 3;
    int row0 = blockIdx.x * 64;
    int mbase = wm * 32, nbase = wn * 64;

    int ar = tid & 63, ah = tid >> 6;
    int bk = tid >> 3, bc = (tid & 7) * 4;
    bool arow_ok = (row0 + ar) < M;
    const float* A1g = A1 + (size_t)(row0 + ar) * kC + ah * 8;
    const float* W1g = W1 + (size_t)bk * ldW + bc;
    const float* A2g = (NPAIR == 2) ? (A2 + (size_t)(row0 + ar) * kC + ah * 8) : A1g;
    const float* W2g = (NPAIR == 2) ? (W2 + (size_t)bk * ldW + bc) : W1g;
    uint32_t adst0 = sA + (uint32_t)((ar * APITCH + ah * 8) * 4);
    uint32_t bdst0 = sB + (uint32_t)((bk * BPITCH + bc) * 4);

    auto issue = [&](int kt) {
        int ktt = kt & 7;
        int buf = kt & 1;
        const float* as = ((NPAIR == 2 && (kt >> 3)) ? A2g : A1g) + ktt * 32;
        const float* bs = ((NPAIR == 2 && (kt >> 3)) ? W2g : W1g) + (size_t)ktt * 32 * ldW;
        uint32_t ad = adst0 + (uint32_t)(buf * ASZ * 4);
        uint32_t bd = bdst0 + (uint32_t)(buf * BSZ * 4);
        cpa16(ad,      as,     arow_ok);
        cpa16(ad + 16, as + 4, arow_ok);
#pragma unroll
        for (int i = 0; i < 8; i++) cpa16(bd + i * 128, bs + 32 * i, true);
    };

    float acc[2][8][4] = {};
    const int TOT = 8 * NPAIR;

    issue(0);
    asm volatile("cp.async.commit_group;\n");

#pragma unroll 1
    for (int kt = 0; kt < TOT; kt++) {
        asm volatile("cp.async.wait_group 0;\n");
        __syncthreads();
        if (kt + 1 < TOT) {
            issue(kt + 1);
            asm volatile("cp.async.commit_group;\n");
        }
        int buf = kt & 1;
        const float* Ab = As + buf * ASZ;
        const float* Bb = Bs + buf * BSZ;
#pragma unroll
        for (int kk = 0; kk < 32; kk += 8) {
            uint32_t af[2][4], bf[8][2];
#pragma unroll
            for (int mi = 0; mi < 2; mi++) {
                const float* a0 = Ab + (mbase + mi * 16 + p) * APITCH + kk + q;
                af[mi][0] = __float_as_uint(a0[0]);
                af[mi][1] = __float_as_uint(a0[8 * APITCH]);
                af[mi][2] = __float_as_uint(a0[4]);
                af[mi][3] = __float_as_uint(a0[8 * APITCH + 4]);
            }
#pragma unroll
            for (int ni = 0; ni < 8; ni++) {
                const float* b0 = Bb + (kk + q) * BPITCH + nbase + ni * 8 + p;
                bf[ni][0] = __float_as_uint(b0[0]);
                bf[ni][1] = __float_as_uint(b0[4 * BPITCH]);
            }
#pragma unroll
            for (int mi = 0; mi < 2; mi++)
#pragma unroll
                for (int ni = 0; ni < 8; ni++)
                    mma_tf32(acc[mi][ni], af[mi], bf[ni]);
        }
        __syncthreads();
    }

    // ---------------- epilogue ----------------
    float* ep = sm;

#pragma unroll
    for (int mi = 0; mi < 2; mi++) {
        int lr1 = mbase + mi * 16 + p;
        int lr2 = lr1 + 8;
        int r1 = row0 + lr1, r2 = row0 + lr2;
#pragma unroll
        for (int ni = 0; ni < 8; ni++) {
            int cc = nbase + ni * 8 + 2 * q;
            float2 bv = *(const float2*)(bias + cc);
            float d0 = acc[mi][ni][0] + bv.x, d1 = acc[mi][ni][1] + bv.y;
            float d2 = acc[mi][ni][2] + bv.x, d3 = acc[mi][ni][3] + bv.y;
            if (EPI == 3 || EPI == 4) {
                float2 a1 = *(const float2*)(addm + (size_t)r1 * kC + cc);
                float2 a2 = *(const float2*)(addm + (size_t)r2 * kC + cc);
                d0 += a1.x; d1 += a1.y; d2 += a2.x; d3 += a2.y;
            }
            if (EPI == 0) {
                if (r1 < M) { float2 o = {d0, d1}; *(float2*)(D + (size_t)r1 * ldD + cc) = o; }
                if (r2 < M) { float2 o = {d2, d3}; *(float2*)(D + (size_t)r2 * ldD + cc) = o; }
            }
            if (EPI == 2) {
                float2 o1 = {tftrunc(gelu_exact(d0)), tftrunc(gelu_exact(d1))};
                float2 o2 = {tftrunc(gelu_exact(d2)), tftrunc(gelu_exact(d3))};
                if (r1 < M) *(float2*)(D + (size_t)r1 * ldD + cc) = o1;
                if (r2 < M) *(float2*)(D + (size_t)r2 * ldD + cc) = o2;
            }
            if (EPI == 3) {
                float2 o1 = {d0, d1}, o2 = {d2, d3};
                *(float2*)(D + (size_t)r1 * ldD + cc) = o1;   // attraw
                *(float2*)(D + (size_t)r2 * ldD + cc) = o2;
                *(float2*)(ep + lr1 * BPITCH + cc) = o1;
                *(float2*)(ep + lr2 * BPITCH + cc) = o2;
            }
            if (EPI == 4) {
                float2 o1 = {d0, d1}, o2 = {d2, d3};
                *(float2*)(ep + lr1 * BPITCH + cc) = o1;
                *(float2*)(ep + lr2 * BPITCH + cc) = o2;
            }
        }
    }

    if (EPI == 3) {   // fused LN -> trunc -> D2
        __syncthreads();
        float gg[8], bb[8];
#pragma unroll
        for (int j = 0; j < 8; j++) {
            int c = lane + 32 * j;
            gg[j] = lng[c]; bb[j] = lnb[c];
        }
#pragma unroll 1
        for (int rr = 0; rr < 8; rr++) {
            int lr = warp * 8 + rr;
            float vals[8]; float s = 0.f, sq = 0.f;
#pragma unroll
            for (int j = 0; j < 8; j++) {
                float t = ep[lr * BPITCH + lane + 32 * j];
                vals[j] = t; s += t; sq += t * t;
            }
#pragma unroll
            for (int o = 16; o; o >>= 1) {
                s  += __shfl_xor_sync(0xffffffffu, s,  o);
                sq += __shfl_xor_sync(0xffffffffu, sq, o);
            }
            float mean = s * (1.f / kC);
            float var  = sq * (1.f / kC) - mean * mean;
            float rstd = rsqrtf(var + 1e-5f);
#pragma unroll
            for (int j = 0; j < 8; j++) {
                int c = lane + 32 * j;
                D2[(size_t)(row0 + lr) * kC + c] = tftrunc((vals[j] - mean) * rstd * gg[j] + bb[j]);
            }
        }
    }

    if (EPI == 4) {   // transposed write to out (n,c,t,v)
        __syncthreads();
#pragma unroll 1
        for (int it = 0; it < 64; it++) {
            int j = it * 256 + tid;
            int c = j >> 6, rr = j & 63;
            unsigned R = (unsigned)(row0 + rr);
            unsigned b = R / 25u;
            unsigned v = R - b * 25u;
            unsigned n = b >> 6, t = b & 63u;
            D[(size_t)n * kXN + (size_t)c * kTV + t * kV + v] = ep[rr * BPITCH + c];
        }
    }
}

// ============ q attention logits (reads q slice of qkv) ============
__global__ void __launch_bounds__(256) k_qlog(const float* __restrict__ qa_w,
                                              const float* __restrict__ qa_b, int M) {
    int warp = threadIdx.x >> 5, lane = threadIdx.x & 31;
    int r = blockIdx.x * 8 + warp;
    if (r >= M) return;
    const float* row = g_qkv + (size_t)r * kC3;
    int c0 = lane * 8;
    float4 v0 = *(const float4*)(row + c0);
    float4 v1 = *(const float4*)(row + c0 + 4);
    float vv[8] = {v0.x, v0.y, v0.z, v0.w, v1.x, v1.y, v1.z, v1.w};
    float acc[8] = {};
#pragma unroll
    for (int j = 0; j < 8; j++) {
        const float4* wr = (const float4*)(qa_w + (size_t)(c0 + j) * kH);
        float4 w0 = wr[0], w1 = wr[1];
        acc[0] += vv[j] * w0.x; acc[1] += vv[j] * w0.y;
        acc[2] += vv[j] * w0.z; acc[3] += vv[j] * w0.w;
        acc[4] += vv[j] * w1.x; acc[5] += vv[j] * w1.y;
        acc[6] += vv[j] * w1.z; acc[7] += vv[j] * w1.w;
    }
#pragma unroll
    for (int o = 16; o; o >>= 1)
#pragma unroll
        for (int e = 0; e < 8; e++)
            acc[e] += __shfl_xor_sync(0xffffffffu, acc[e], o);
    if (lane < 8) g_ql[(size_t)r * kH + lane] = (acc[lane] + qa_b[lane]) * kSCALE;
}

// ============ fused per-window pooling (qkv-interleaved reads) ============
constexpr int KAP = 12;
__global__ void __launch_bounds__(256) k_pool(const float* __restrict__ ka_w,
                                              const float* __restrict__ ka_b) {
    __shared__ int   su[kL];
    __shared__ float sqw[kH][128];
    __shared__ float skw[kH][128];
    __shared__ float spq[kC];
    __shared__ __align__(16) float skaw[kC * KAP];
    __shared__ float smv[kV * 256];
    int tid = threadIdx.x, lane = tid & 31, h = tid >> 5;
    int b = blockIdx.x, n = b / kT, t = b % kT;

    for (int i = tid; i < kC * kH; i += 256) {
        int c = i >> 3, e = i & 7;
        skaw[c * KAP + e] = ka_w[i];
    }
    if (tid < kL) {
        int w = tid / kV, v = tid - w * kV;
        int tp = t + w - 2;
        su[tid] = (tp >= 0 && tp < kT) ? (n * kT + tp) * kV + v : kU;
    }
    float kab = (lane < kH) ? ka_b[lane] : 0.f;
    __syncthreads();

    // ---- q-weight softmax (warp h over l) ----
    {
        float lv[4]; float mx = -1e30f;
#pragma unroll
        for (int i = 0; i < 4; i++) {
            int l = lane + 32 * i;
            lv[i] = (l < kL) ? g_ql[(size_t)su[l] * kH + h] : -1e30f;
            mx = fmaxf(mx, lv[i]);
        }
#pragma unroll
        for (int o = 16; o; o >>= 1) mx = fmaxf(mx, __shfl_xor_sync(0xffffffffu, mx, o));
        float sm = 0.f;
#pragma unroll
        for (int i = 0; i < 4; i++) {
            int l = lane + 32 * i;
            lv[i] = (l < kL) ? expf(lv[i] - mx) : 0.f;
            sm += lv[i];
        }
#pragma unroll
        for (int o = 16; o; o >>= 1) sm += __shfl_xor_sync(0xffffffffu, sm, o);
        float inv = 1.f / sm;
#pragma unroll
        for (int i = 0; i < 4; i++) {
            int l = lane + 32 * i;
            if (l < kL) sqw[h][l] = lv[i] * inv;
        }
    }
    __syncthreads();

    // ---- pass A: pq + mq (q slice: offset 0) ----
    float pq = 0.f;
#pragma unroll 5
    for (int v = 0; v < kV; v++) {
        float a = 0.f;
#pragma unroll
        for (int w = 0; w < kWIN; w++) {
            int l = w * kV + v;
            float val = g_qkv[(size_t)su[l] * kC3 + tid];
            pq += sqw[h][l] * val;
            a  += val;
        }
        g_nx[((size_t)b * kV + v) * kC + tid] = tftrunc(a * 0.2f);   // mq
    }
    spq[tid] = pq;
    __syncthreads();

    // ---- pass B: k logits (k slice: offset 256) ----
    float pqr[8];
#pragma unroll
    for (int j = 0; j < 8; j++) pqr[j] = spq[lane + 32 * j];
#pragma unroll 1
    for (int l = h; l < kL; l += kH) {
        const float* kr = g_qkv + (size_t)su[l] * kC3 + 256;
        float acc[8] = {};
#pragma unroll
        for (int j = 0; j < 8; j++) {
            float kp = kr[lane + 32 * j] * pqr[j];
            const float4* ka = (const float4*)(skaw + (lane + 32 * j) * KAP);
            float4 k0 = ka[0], k1 = ka[1];
            acc[0] += kp * k0.x; acc[1] += kp * k0.y;
            acc[2] += kp * k0.z; acc[3] += kp * k0.w;
            acc[4] += kp * k1.x; acc[5] += kp * k1.y;
            acc[6] += kp * k1.z; acc[7] += kp * k1.w;
        }
#pragma unroll
        for (int o = 16; o; o >>= 1)
#pragma unroll
            for (int e = 0; e < 8; e++)
                acc[e] += __shfl_xor_sync(0xffffffffu, acc[e], o);
        if (lane < kH) skw[lane][l] = (acc[lane] + kab) * kSCALE;
    }
    __syncthreads();

    // ---- k-weight softmax ----
    {
        float lv[4]; float mx = -1e30f;
#pragma unroll
        for (int i = 0; i < 4; i++) {
            int l = lane + 32 * i;
            lv[i] = (l < kL) ? skw[h][l] : -1e30f;
            mx = fmaxf(mx, lv[i]);
        }
#pragma unroll
        for (int o = 16; o; o >>= 1) mx = fmaxf(mx, __shfl_xor_sync(0xffffffffu, mx, o));
        float sm = 0.f;
#pragma unroll
        for (int i = 0; i < 4; i++) {
            int l = lane + 32 * i;
            lv[i] = (l < kL) ? expf(lv[i] - mx) : 0.f;
            sm += lv[i];
        }
#pragma unroll
        for (int o = 16; o; o >>= 1) sm += __shfl_xor_sync(0xffffffffu, sm, o);
        float inv = 1.f / sm;
#pragma unroll
        for (int i = 0; i < 4; i++) {
            int l = lane + 32 * i;
            if (l < kL) skw[h][l] = lv[i] * inv;
        }
    }
    __syncthreads();

    // ---- pass C (merged): pk from k, mv into smem, then mkv = pk*mv ----
    float pk = 0.f;
#pragma unroll 5
    for (int v = 0; v < kV; v++) {
        float a = 0.f;
#pragma unroll
        for (int w = 0; w < kWIN; w++) {
            int l = w * kV + v;
            const float* rw = g_qkv + (size_t)su[l] * kC3;
            pk += skw[h][l] * rw[256 + tid];
            a  += rw[512 + tid];
        }
        smv[v * 256 + tid] = a;
    }
#pragma unroll 5
    for (int v = 0; v < kV; v++)
        g_mkv[((size_t)b * kV + v) * kC + tid] = tftrunc(pk * smv[v * 256 + tid] * 0.2f);
}

// ===================================================================================
extern "C" void kernel_launch(void* const* d_in, const int* in_sizes, int n_in,
                              void* d_out, int out_size) {
    const float* x    = (const float*)d_in[0];
    const float* ln1g = (const float*)d_in[1];
    const float* ln1b = (const float*)d_in[2];
    const float* q_w  = (const float*)d_in[3];
    const float* q_b  = (const float*)d_in[4];
    const float* qa_w = (const float*)d_in[5];
    const float* qa_b = (const float*)d_in[6];
    const float* k_w  = (const float*)d_in[7];
    const float* k_b  = (const float*)d_in[8];
    const float* ka_w = (const float*)d_in[9];
    const float* ka_b = (const float*)d_in[10];
    const float* v_w  = (const float*)d_in[11];
    const float* v_b  = (const float*)d_in[12];
    const float* t_w  = (const float*)d_in[13];
    const float* t_b  = (const float*)d_in[14];
    const float* p_w  = (const float*)d_in[15];
    const float* p_b  = (const float*)d_in[16];
    const float* ffng = (const float*)d_in[17];
    const float* ffnb = (const float*)d_in[18];
    const float* w1   = (const float*)d_in[19];
    const float* b1   = (const float*)d_in[20];
    const float* w2   = (const float*)d_in[21];
    const float* b2   = (const float*)d_in[22];
    float* out = (float*)d_out;

    float *p_nx, *p_qkv, *p_k, *p_v, *p_xr, *p_mkv, *p_tw, *p_tb, *p_wqkv, *p_wt, *p_qkvb;
    cudaGetSymbolAddress((void**)&p_nx,   g_nx);
    cudaGetSymbolAddress((void**)&p_qkv,  g_qkv);
    cudaGetSymbolAddress((void**)&p_k,    g_k);
    cudaGetSymbolAddress((void**)&p_v,    g_v);
    cudaGetSymbolAddress((void**)&p_xr,   g_xr);
    cudaGetSymbolAddress((void**)&p_mkv,  g_mkv);
    cudaGetSymbolAddress((void**)&p_tw,   g_tw);
    cudaGetSymbolAddress((void**)&p_tb,   g_tb);
    cudaGetSymbolAddress((void**)&p_wqkv, g_wqkv);
    cudaGetSymbolAddress((void**)&p_wt,   g_wt);
    cudaGetSymbolAddress((void**)&p_qkvb, g_qkvb);

    const float* wt_p = p_wt + 0 * 65536;
    const float* wt_1 = p_wt + 1 * 65536;
    const float* wt_2 = p_wt + 2 * 65536;

    cudaFuncSetAttribute(k_gemm5<0,1>, cudaFuncAttributeMaxDynamicSharedMemorySize, GEMM_SMEM);
    cudaFuncSetAttribute(k_gemm5<2,1>, cudaFuncAttributeMaxDynamicSharedMemorySize, GEMM_SMEM);
    cudaFuncSetAttribute(k_gemm5<3,2>, cudaFuncAttributeMaxDynamicSharedMemorySize, GEMM_SMEM);
    cudaFuncSetAttribute(k_gemm5<4,1>, cudaFuncAttributeMaxDynamicSharedMemorySize, GEMM_SMEM);

    dim3 gqkv((kM1 + 63) / 64, 3);   // 801 x 3
    int g2 = kU / 64;                // 800

    // 0) prep
    k_prep<<<257 + 1536 + 3, 256>>>(t_w, p_w, t_b, p_b, q_w, k_w, v_w, w1, w2, q_b, k_b, v_b);
    // 1) LN of unique tokens
    k_ln_x<<<(kM1 + 31) / 32, 256>>>(x, ln1g, ln1b);
    // 2) fused q|k|v projection -> g_qkv (row pitch 768)
    k_gemm5<0,1><<<gqkv, 256, GEMM_SMEM>>>(p_nx, p_wqkv, nullptr, nullptr, p_qkvb, nullptr,
                                           p_qkv, nullptr, nullptr, nullptr, kM1, kC3, kC3);
    // 3) q attention logits
    k_qlog<<<(kM1 + 7) / 8, 256>>>(qa_w, qa_b, kM1);
    // 4) fused pooling -> mq (g_nx), mkv
    k_pool<<<kB, 256>>>(ka_w, ka_b);
    // 5) attraw = mkv@tp_w + mq@p_w + tp_b + xr -> g_k ; fused LN -> f (g_v)
    k_gemm5<3,2><<<g2, 256, GEMM_SMEM>>>(p_mkv, p_tw, p_nx, wt_p, p_tb, p_xr,
                                         p_k, p_v, ffng, ffnb, kU, kC, kC);
    // 6) h1 = trunc(gelu(f @ w1 + b1)) -> g_nx
    k_gemm5<2,1><<<g2, 256, GEMM_SMEM>>>(p_v, wt_1, nullptr, nullptr, b1, nullptr,
                                         p_nx, nullptr, nullptr, nullptr, kU, kC, kC);
    // 7) y = h1 @ w2 + b2 + attraw -> transposed out
    k_gemm5<4,1><<<g2, 256, GEMM_SMEM>>>(p_nx, wt_2, nullptr, nullptr, b2, p_k,
                                         out, nullptr, nullptr, nullptr, kU, kC, kC);
}

// round 8
// speedup vs baseline: 1.2404x; 1.0337x over previous
#include <cuda_runtime.h>
#include <cstdint>
#include <cstddef>

constexpr int kN   = 32;
constexpr int kC   = 256;
constexpr int kC3  = 768;
constexpr int kT   = 64;
constexpr int kV   = 25;
constexpr int kH   = 8;
constexpr int kWIN = 5;
constexpr int kB   = kN * kT;        // 2048 windows
constexpr int kL   = kWIN * kV;      // 125
constexpr int kU   = kB * kV;        // 51200 unique tokens
constexpr int kM1  = kU + 1;         // + pad row
constexpr int kTV  = kT * kV;        // 1600
constexpr int kXN  = kC * kTV;       // 409600
constexpr float kSCALE = 0.17677669529663687f;  // 1/sqrt(32)

// ---------------- scratch ----------------
__device__ float g_nx  [(size_t)kM1 * kC];    // nx -> mq -> h1
__device__ float g_qkv [(size_t)kM1 * kC3];   // interleaved q|k|v per token
__device__ float g_k   [(size_t)kM1 * kC];    // attraw
__device__ float g_v   [(size_t)kM1 * kC];    // f
__device__ float g_xr  [(size_t)kU  * kC];    // gathered x (residual)
__device__ float g_mkv [(size_t)kU  * kC];    // mkv
__device__ float g_ql  [(size_t)kM1 * kH];    // q attention logits
__device__ float g_tw  [(size_t)kC  * kC];    // trunc(t_w @ p_w)
__device__ float g_tb  [kC];                  // t_b @ p_w + p_b
__device__ float g_wqkv[(size_t)kC * kC3];    // trunc concat [q|k|v] weights
__device__ float g_wt  [3 * 65536];           // trunc copies: p, w1, w2
__device__ float g_qkvb[kC3];                 // concat biases

__device__ __forceinline__ uint32_t f2tf(float f) {
    uint32_t r; asm("cvt.rna.tf32.f32 %0, %1;" : "=r"(r) : "f"(f)); return r;
}
__device__ __forceinline__ float tftrunc(float f) { return __uint_as_float(f2tf(f)); }

// ============ prep: tp_w/tp_b + truncated weight copies + concat ============
__global__ void __launch_bounds__(256) k_prep(const float* __restrict__ t_w,
                                              const float* __restrict__ p_w,
                                              const float* __restrict__ t_b,
                                              const float* __restrict__ p_b,
                                              const float* __restrict__ q_w,
                                              const float* __restrict__ k_w,
                                              const float* __restrict__ v_w,
                                              const float* __restrict__ w1,
                                              const float* __restrict__ w2,
                                              const float* __restrict__ q_b,
                                              const float* __restrict__ k_b,
                                              const float* __restrict__ v_b) {
    int bid = blockIdx.x, c = threadIdx.x;
    if (bid < 257) {
        __shared__ float srow[kC];
        bool isw = (bid < kC);
        srow[c] = isw ? t_w[(size_t)bid * kC + c] : t_b[c];
        __syncthreads();
        float acc = isw ? 0.f : p_b[c];
#pragma unroll 8
        for (int m = 0; m < kC; m++) acc += srow[m] * p_w[(size_t)m * kC + c];
        if (isw) g_tw[(size_t)bid * kC + c] = tftrunc(acc);
        else     g_tb[c] = acc;
    } else if (bid < 257 + 1536) {
        int idx = (bid - 257) * 256 + c;          // 0..393215
        if (idx < kC * kC3) {                     // concat qkv weights
            int row = idx / kC3, col = idx - row * kC3;
            const float* s = (col < 256) ? q_w : (col < 512) ? k_w : v_w;
            g_wqkv[idx] = tftrunc(s[row * kC + (col & 255)]);
        } else {                                  // p, w1, w2
            int j = idx - kC * kC3;
            int w = j >> 16, off = j & 65535;
            const float* s = (w == 0) ? p_w : (w == 1) ? w1 : w2;
            g_wt[j] = tftrunc(s[off]);
        }
    } else {
        int k = bid - (257 + 1536);               // 0..2
        g_qkvb[k * 256 + c] = (k == 0) ? q_b[c] : (k == 1) ? k_b[c] : v_b[c];
    }
}

// ============ LN of unique tokens (gather) -> trunc nx, raw xr ============
__global__ void __launch_bounds__(256) k_ln_x(const float* __restrict__ x,
                                              const float* __restrict__ g,
                                              const float* __restrict__ b) {
    __shared__ float sx[32][257];
    int tid = threadIdx.x;
    int u0  = blockIdx.x * 32;
    {
        int ur = tid & 31;
        int u  = u0 + ur;
        int cb = tid >> 5;
        bool has = (u < kU);
        size_t base = 0;
        if (has) { int n = u / kTV; base = (size_t)n * kXN + (u - n * kTV); }
#pragma unroll
        for (int j = 0; j < 32; j++) {
            int c = cb * 32 + j;
            sx[ur][c] = has ? x[base + (size_t)c * kTV] : 0.f;
        }
    }
    __syncthreads();
    int lane = tid & 31, warp = tid >> 5;
#pragma unroll
    for (int rr = 0; rr < 4; rr++) {
        int ur = warp * 4 + rr;
        int u  = u0 + ur;
        if (u >= kM1) continue;
        float vals[8];
        float s = 0.f, sq = 0.f;
#pragma unroll
        for (int j = 0; j < 8; j++) {
            float t = sx[ur][lane + 32 * j];
            vals[j] = t; s += t; sq += t * t;
        }
#pragma unroll
        for (int o = 16; o; o >>= 1) {
            s  += __shfl_xor_sync(0xffffffffu, s,  o);
            sq += __shfl_xor_sync(0xffffffffu, sq, o);
        }
        float mean = s * (1.f / kC);
        float var  = sq * (1.f / kC) - mean * mean;
        float rstd = rsqrtf(var + 1e-5f);
#pragma unroll
        for (int j = 0; j < 8; j++) {
            int c = lane + 32 * j;
            g_nx[(size_t)u * kC + c] = tftrunc((vals[j] - mean) * rstd * g[c] + b[c]);
            if (u < kU) g_xr[(size_t)u * kC + c] = vals[j];
        }
    }
}

// ============ tf32 GEMM v6: CTA 128x256, 512 threads, 1 CTA/SM ============
// EPI: 0 store; 2 gelu+trunc; 3 addm+store+fused-LN(trunc)->D2; 4 addm+transposed-out
constexpr int APITCH = 36;
constexpr int BPITCH = 264;
constexpr int ASZ = 128 * APITCH;           // 4608 floats/stage
constexpr int BSZ = 32 * BPITCH;            // 8448 floats/stage
constexpr int GEMM_SMEM = 2 * (ASZ + BSZ) * 4;  // 104448 bytes

__device__ __forceinline__ void mma_tf32(float (&d)[4], const uint32_t (&a)[4],
                                         const uint32_t (&bb)[2]) {
    asm volatile(
        "mma.sync.aligned.m16n8k8.row.col.f32.tf32.tf32.f32 "
        "{%0,%1,%2,%3}, {%4,%5,%6,%7}, {%8,%9}, {%0,%1,%2,%3};\n"
        : "+f"(d[0]), "+f"(d[1]), "+f"(d[2]), "+f"(d[3])
        : "r"(a[0]), "r"(a[1]), "r"(a[2]), "r"(a[3]), "r"(bb[0]), "r"(bb[1]));
}
__device__ __forceinline__ void cpa16(uint32_t dst, const float* src, bool pred) {
    int sz = pred ? 16 : 0;
    asm volatile("cp.async.cg.shared.global [%0], [%1], 16, %2;\n"
                 :: "r"(dst), "l"(src), "r"(sz));
}
__device__ __forceinline__ float gelu_exact(float x) {
    return 0.5f * x * (1.0f + erff(x * 0.70710678118654752f));
}

template<int EPI, int NPAIR>
__global__ void __launch_bounds__(512, 1) k_gemm6(const float* __restrict__ A1,
                                                  const float* __restrict__ W1,
                                                  const float* __restrict__ A2,
                                                  const float* __restrict__ W2,
                                                  const float* __restrict__ bias,
                                                  const float* __restrict__ addm,
                                                  float* __restrict__ D,
                                                  float* __restrict__ D2,
                                                  const float* __restrict__ lng,
                                                  const float* __restrict__ lnb,
                                                  int M, int ldW, int ldD) {
    extern __shared__ float sm[];
    float* As = sm;
    float* Bs = sm + 2 * ASZ;
    uint32_t sA = (uint32_t)__cvta_generic_to_shared(As);
    uint32_t sB = (uint32_t)__cvta_generic_to_shared(Bs);

    int coly = blockIdx.y * 256;       // column slab (QKV fused GEMM)
    W1 += coly; bias += coly; D += coly;

    int tid = threadIdx.x, lane = tid & 31, warp = tid >> 5;
    int wm = warp >> 2, wn = warp & 3;       // 4 x 4 warp grid, warp tile 32x64
    int p = lane >> 2, q = lane & 3;
    int row0 = blockIdx.x * 128;
    int mbase = wm * 32, nbase = wn * 64;

    int ar = tid & 127, ah = tid >> 7;       // A: row, 8-float chunk (4 chunks)
    int bk = tid >> 4,  bc = (tid & 15) * 4; // B: k-row, col base (+64*i)
    bool arow_ok = (row0 + ar) < M;
    const float* A1g = A1 + (size_t)(row0 + ar) * kC + ah * 8;
    const float* W1g = W1 + (size_t)bk * ldW + bc;
    const float* A2g = (NPAIR == 2) ? (A2 + (size_t)(row0 + ar) * kC + ah * 8) : A1g;
    const float* W2g = (NPAIR == 2) ? (W2 + (size_t)bk * ldW + bc) : W1g;
    uint32_t adst0 = sA + (uint32_t)((ar * APITCH + ah * 8) * 4);
    uint32_t bdst0 = sB + (uint32_t)((bk * BPITCH + bc) * 4);

    auto issue = [&](int kt) {
        int ktt = kt & 7;
        int buf = kt & 1;
        const float* as = ((NPAIR == 2 && (kt >> 3)) ? A2g : A1g) + ktt * 32;
        const float* bs = ((NPAIR == 2 && (kt >> 3)) ? W2g : W1g) + (size_t)ktt * 32 * ldW;
        uint32_t ad = adst0 + (uint32_t)(buf * ASZ * 4);
        uint32_t bd = bdst0 + (uint32_t)(buf * BSZ * 4);
        cpa16(ad,      as,     arow_ok);
        cpa16(ad + 16, as + 4, arow_ok);
#pragma unroll
        for (int i = 0; i < 4; i++) cpa16(bd + i * 256, bs + 64 * i, true);
    };

    float acc[2][8][4] = {};
    const int TOT = 8 * NPAIR;

    issue(0);
    asm volatile("cp.async.commit_group;\n");

#pragma unroll 1
    for (int kt = 0; kt < TOT; kt++) {
        asm volatile("cp.async.wait_group 0;\n");
        __syncthreads();
        if (kt + 1 < TOT) {
            issue(kt + 1);
            asm volatile("cp.async.commit_group;\n");
        }
        int buf = kt & 1;
        const float* Ab = As + buf * ASZ;
        const float* Bb = Bs + buf * BSZ;
#pragma unroll
        for (int kk = 0; kk < 32; kk += 8) {
            uint32_t af[2][4], bf[8][2];
#pragma unroll
            for (int mi = 0; mi < 2; mi++) {
                const float* a0 = Ab + (mbase + mi * 16 + p) * APITCH + kk + q;
                af[mi][0] = __float_as_uint(a0[0]);
                af[mi][1] = __float_as_uint(a0[8 * APITCH]);
                af[mi][2] = __float_as_uint(a0[4]);
                af[mi][3] = __float_as_uint(a0[8 * APITCH + 4]);
            }
#pragma unroll
            for (int ni = 0; ni < 8; ni++) {
                const float* b0 = Bb + (kk + q) * BPITCH + nbase + ni * 8 + p;
                bf[ni][0] = __float_as_uint(b0[0]);
                bf[ni][1] = __float_as_uint(b0[4 * BPITCH]);
            }
#pragma unroll
            for (int mi = 0; mi < 2; mi++)
#pragma unroll
                for (int ni = 0; ni < 8; ni++)
                    mma_tf32(acc[mi][ni], af[mi], bf[ni]);
        }
        if (kt + 1 < TOT) __syncthreads();   // protect buf^1 before its reuse
    }

    // ---------------- epilogue ----------------
    if (EPI == 0 || EPI == 2) {
#pragma unroll
        for (int mi = 0; mi < 2; mi++) {
            int r1 = row0 + mbase + mi * 16 + p;
            int r2 = r1 + 8;
#pragma unroll
            for (int ni = 0; ni < 8; ni++) {
                int cc = nbase + ni * 8 + 2 * q;
                float2 bv = *(const float2*)(bias + cc);
                float d0 = acc[mi][ni][0] + bv.x, d1 = acc[mi][ni][1] + bv.y;
                float d2 = acc[mi][ni][2] + bv.x, d3 = acc[mi][ni][3] + bv.y;
                if (EPI == 2) {
                    d0 = tftrunc(gelu_exact(d0)); d1 = tftrunc(gelu_exact(d1));
                    d2 = tftrunc(gelu_exact(d2)); d3 = tftrunc(gelu_exact(d3));
                }
                if (r1 < M) { float2 o = {d0, d1}; *(float2*)(D + (size_t)r1 * ldD + cc) = o; }
                if (r2 < M) { float2 o = {d2, d3}; *(float2*)(D + (size_t)r2 * ldD + cc) = o; }
            }
        }
    } else {
        // EPI 3 / 4: two 64-row halves through smem staging (M multiple of 128 here)
        float* ep = sm;
#pragma unroll 1
        for (int half = 0; half < 2; half++) {
            __syncthreads();
            if ((wm >> 1) == half) {
#pragma unroll
                for (int mi = 0; mi < 2; mi++) {
                    int lr1 = mbase + mi * 16 + p;
                    int lr2 = lr1 + 8;
                    int r1 = row0 + lr1, r2 = row0 + lr2;
                    int e1 = lr1 - half * 64, e2 = lr2 - half * 64;
#pragma unroll
                    for (int ni = 0; ni < 8; ni++) {
                        int cc = nbase + ni * 8 + 2 * q;
                        float2 bv = *(const float2*)(bias + cc);
                        float2 a1 = *(const float2*)(addm + (size_t)r1 * kC + cc);
                        float2 a2 = *(const float2*)(addm + (size_t)r2 * kC + cc);
                        float2 o1 = {acc[mi][ni][0] + bv.x + a1.x, acc[mi][ni][1] + bv.y + a1.y};
                        float2 o2 = {acc[mi][ni][2] + bv.x + a2.x, acc[mi][ni][3] + bv.y + a2.y};
                        if (EPI == 3) {
                            *(float2*)(D + (size_t)r1 * ldD + cc) = o1;   // attraw
                            *(float2*)(D + (size_t)r2 * ldD + cc) = o2;
                        }
                        *(float2*)(ep + e1 * BPITCH + cc) = o1;
                        *(float2*)(ep + e2 * BPITCH + cc) = o2;
                    }
                }
            }
            __syncthreads();
            if (EPI == 3) {   // fused LN over 64 staged rows -> trunc -> D2
                float gg[8], bb[8];
#pragma unroll
                for (int j = 0; j < 8; j++) {
                    int c = lane + 32 * j;
                    gg[j] = lng[c]; bb[j] = lnb[c];
                }
#pragma unroll
                for (int rr = 0; rr < 4; rr++) {
                    int lr = warp * 4 + rr;            // 0..63
                    float vals[8]; float s = 0.f, sq = 0.f;
#pragma unroll
                    for (int j = 0; j < 8; j++) {
                        float t = ep[lr * BPITCH + lane + 32 * j];
                        vals[j] = t; s += t; sq += t * t;
                    }
#pragma unroll
                    for (int o = 16; o; o >>= 1) {
                        s  += __shfl_xor_sync(0xffffffffu, s,  o);
                        sq += __shfl_xor_sync(0xffffffffu, sq, o);
                    }
                    float mean = s * (1.f / kC);
                    float var  = sq * (1.f / kC) - mean * mean;
                    float rstd = rsqrtf(var + 1e-5f);
                    int gr = row0 + half * 64 + lr;
#pragma unroll
                    for (int j = 0; j < 8; j++) {
                        int c = lane + 32 * j;
                        D2[(size_t)gr * kC + c] = tftrunc((vals[j] - mean) * rstd * gg[j] + bb[j]);
                    }
                }
            } else {          // EPI 4: transposed write to out (n,c,t,v)
#pragma unroll 1
                for (int it = 0; it < 32; it++) {
                    int j = it * 512 + tid;
                    int c = j >> 6, rr = j & 63;
                    unsigned R = (unsigned)(row0 + half * 64 + rr);
                    unsigned b = R / 25u;
                    unsigned v = R - b * 25u;
                    unsigned n = b >> 6, t = b & 63u;
                    D[(size_t)n * kXN + (size_t)c * kTV + t * kV + v] = ep[rr * BPITCH + c];
                }
            }
        }
    }
}

// ============ q attention logits v2: 8 rows per warp, qa_w reg-cached ============
__global__ void __launch_bounds__(256) k_qlog(const float* __restrict__ qa_w,
                                              const float* __restrict__ qa_b, int M) {
    int warp = threadIdx.x >> 5, lane = threadIdx.x & 31;
    int r0 = (blockIdx.x * 8 + warp) * 8;
    int c0 = lane * 8;
    float wreg[8][8];
#pragma unroll
    for (int j = 0; j < 8; j++) {
        const float4* wr = (const float4*)(qa_w + (size_t)(c0 + j) * kH);
        float4 w0 = wr[0], w1 = wr[1];
        wreg[j][0] = w0.x; wreg[j][1] = w0.y; wreg[j][2] = w0.z; wreg[j][3] = w0.w;
        wreg[j][4] = w1.x; wreg[j][5] = w1.y; wreg[j][6] = w1.z; wreg[j][7] = w1.w;
    }
    float qab = (lane < kH) ? qa_b[lane] : 0.f;
#pragma unroll 1
    for (int rr = 0; rr < 8; rr++) {
        int r = r0 + rr;
        if (r >= M) return;
        const float* row = g_qkv + (size_t)r * kC3;
        float4 v0 = *(const float4*)(row + c0);
        float4 v1 = *(const float4*)(row + c0 + 4);
        float vv[8] = {v0.x, v0.y, v0.z, v0.w, v1.x, v1.y, v1.z, v1.w};
        float acc[8] = {};
#pragma unroll
        for (int j = 0; j < 8; j++)
#pragma unroll
            for (int e = 0; e < 8; e++)
                acc[e] += vv[j] * wreg[j][e];
#pragma unroll
        for (int o = 16; o; o >>= 1)
#pragma unroll
            for (int e = 0; e < 8; e++)
                acc[e] += __shfl_xor_sync(0xffffffffu, acc[e], o);
        if (lane < kH) g_ql[(size_t)r * kH + lane] = (acc[lane] + qab) * kSCALE;
    }
}

// ============ fused per-window pooling (qkv-interleaved reads) ============
constexpr int KAP = 12;
__global__ void __launch_bounds__(256) k_pool(const float* __restrict__ ka_w,
                                              const float* __restrict__ ka_b) {
    __shared__ int   su[kL];
    __shared__ float sqw[kH][128];
    __shared__ float skw[kH][128];
    __shared__ float spq[kC];
    __shared__ __align__(16) float skaw[kC * KAP];
    __shared__ float smv[kV * 256];
    int tid = threadIdx.x, lane = tid & 31, h = tid >> 5;
    int b = blockIdx.x, n = b / kT, t = b % kT;

    for (int i = tid; i < kC * kH; i += 256) {
        int c = i >> 3, e = i & 7;
        skaw[c * KAP + e] = ka_w[i];
    }
    if (tid < kL) {
        int w = tid / kV, v = tid - w * kV;
        int tp = t + w - 2;
        su[tid] = (tp >= 0 && tp < kT) ? (n * kT + tp) * kV + v : kU;
    }
    float kab = (lane < kH) ? ka_b[lane] : 0.f;
    __syncthreads();

    // ---- q-weight softmax (warp h over l) ----
    {
        float lv[4]; float mx = -1e30f;
#pragma unroll
        for (int i = 0; i < 4; i++) {
            int l = lane + 32 * i;
            lv[i] = (l < kL) ? g_ql[(size_t)su[l] * kH + h] : -1e30f;
            mx = fmaxf(mx, lv[i]);
        }
#pragma unroll
        for (int o = 16; o; o >>= 1) mx = fmaxf(mx, __shfl_xor_sync(0xffffffffu, mx, o));
        float sm = 0.f;
#pragma unroll
        for (int i = 0; i < 4; i++) {
            int l = lane + 32 * i;
            lv[i] = (l < kL) ? expf(lv[i] - mx) : 0.f;
            sm += lv[i];
        }
#pragma unroll
        for (int o = 16; o; o >>= 1) sm += __shfl_xor_sync(0xffffffffu, sm, o);
        float inv = 1.f / sm;
#pragma unroll
        for (int i = 0; i < 4; i++) {
            int l = lane + 32 * i;
            if (l < kL) sqw[h][l] = lv[i] * inv;
        }
    }
    __syncthreads();

    // ---- pass A: pq + mq (q slice: offset 0) ----
    float pq = 0.f;
#pragma unroll 5
    for (int v = 0; v < kV; v++) {
        float a = 0.f;
#pragma unroll
        for (int w = 0; w < kWIN; w++) {
            int l = w * kV + v;
            float val = g_qkv[(size_t)su[l] * kC3 + tid];
            pq += sqw[h][l] * val;
            a  += val;
        }
        g_nx[((size_t)b * kV + v) * kC + tid] = tftrunc(a * 0.2f);   // mq
    }
    spq[tid] = pq;
    __syncthreads();

    // ---- pass B: k logits (k slice: offset 256) ----
    float pqr[8];
#pragma unroll
    for (int j = 0; j < 8; j++) pqr[j] = spq[lane + 32 * j];
#pragma unroll 1
    for (int l = h; l < kL; l += kH) {
        const float* kr = g_qkv + (size_t)su[l] * kC3 + 256;
        float acc[8] = {};
#pragma unroll
        for (int j = 0; j < 8; j++) {
            float kp = kr[lane + 32 * j] * pqr[j];
            const float4* ka = (const float4*)(skaw + (lane + 32 * j) * KAP);
            float4 k0 = ka[0], k1 = ka[1];
            acc[0] += kp * k0.x; acc[1] += kp * k0.y;
            acc[2] += kp * k0.z; acc[3] += kp * k0.w;
            acc[4] += kp * k1.x; acc[5] += kp * k1.y;
            acc[6] += kp * k1.z; acc[7] += kp * k1.w;
        }
#pragma unroll
        for (int o = 16; o; o >>= 1)
#pragma unroll
            for (int e = 0; e < 8; e++)
                acc[e] += __shfl_xor_sync(0xffffffffu, acc[e], o);
        if (lane < kH) skw[lane][l] = (acc[lane] + kab) * kSCALE;
    }
    __syncthreads();

    // ---- k-weight softmax ----
    {
        float lv[4]; float mx = -1e30f;
#pragma unroll
        for (int i = 0; i < 4; i++) {
            int l = lane + 32 * i;
            lv[i] = (l < kL) ? skw[h][l] : -1e30f;
            mx = fmaxf(mx, lv[i]);
        }
#pragma unroll
        for (int o = 16; o; o >>= 1) mx = fmaxf(mx, __shfl_xor_sync(0xffffffffu, mx, o));
        float sm = 0.f;
#pragma unroll
        for (int i = 0; i < 4; i++) {
            int l = lane + 32 * i;
            lv[i] = (l < kL) ? expf(lv[i] - mx) : 0.f;
            sm += lv[i];
        }
#pragma unroll
        for (int o = 16; o; o >>= 1) sm += __shfl_xor_sync(0xffffffffu, sm, o);
        float inv = 1.f / sm;
#pragma unroll
        for (int i = 0; i < 4; i++) {
            int l = lane + 32 * i;
            if (l < kL) skw[h][l] = lv[i] * inv;
        }
    }
    __syncthreads();

    // ---- pass C (merged): pk from k, mv into smem, then mkv = pk*mv ----
    float pk = 0.f;
#pragma unroll 5
    for (int v = 0; v < kV; v++) {
        float a = 0.f;
#pragma unroll
        for (int w = 0; w < kWIN; w++) {
            int l = w * kV + v;
            const float* rw = g_qkv + (size_t)su[l] * kC3;
            pk += skw[h][l] * rw[256 + tid];
            a  += rw[512 + tid];
        }
        smv[v * 256 + tid] = a;
    }
#pragma unroll 5
    for (int v = 0; v < kV; v++)
        g_mkv[((size_t)b * kV + v) * kC + tid] = tftrunc(pk * smv[v * 256 + tid] * 0.2f);
}

// ===================================================================================
extern "C" void kernel_launch(void* const* d_in, const int* in_sizes, int n_in,
                              void* d_out, int out_size) {
    const float* x    = (const float*)d_in[0];
    const float* ln1g = (const float*)d_in[1];
    const float* ln1b = (const float*)d_in[2];
    const float* q_w  = (const float*)d_in[3];
    const float* q_b  = (const float*)d_in[4];
    const float* qa_w = (const float*)d_in[5];
    const float* qa_b = (const float*)d_in[6];
    const float* k_w  = (const float*)d_in[7];
    const float* k_b  = (const float*)d_in[8];
    const float* ka_w = (const float*)d_in[9];
    const float* ka_b = (const float*)d_in[10];
    const float* v_w  = (const float*)d_in[11];
    const float* v_b  = (const float*)d_in[12];
    const float* t_w  = (const float*)d_in[13];
    const float* t_b  = (const float*)d_in[14];
    const float* p_w  = (const float*)d_in[15];
    const float* p_b  = (const float*)d_in[16];
    const float* ffng = (const float*)d_in[17];
    const float* ffnb = (const float*)d_in[18];
    const float* w1   = (const float*)d_in[19];
    const float* b1   = (const float*)d_in[20];
    const float* w2   = (const float*)d_in[21];
    const float* b2   = (const float*)d_in[22];
    float* out = (float*)d_out;

    float *p_nx, *p_qkv, *p_k, *p_v, *p_xr, *p_mkv, *p_tw, *p_tb, *p_wqkv, *p_wt, *p_qkvb;
    cudaGetSymbolAddress((void**)&p_nx,   g_nx);
    cudaGetSymbolAddress((void**)&p_qkv,  g_qkv);
    cudaGetSymbolAddress((void**)&p_k,    g_k);
    cudaGetSymbolAddress((void**)&p_v,    g_v);
    cudaGetSymbolAddress((void**)&p_xr,   g_xr);
    cudaGetSymbolAddress((void**)&p_mkv,  g_mkv);
    cudaGetSymbolAddress((void**)&p_tw,   g_tw);
    cudaGetSymbolAddress((void**)&p_tb,   g_tb);
    cudaGetSymbolAddress((void**)&p_wqkv, g_wqkv);
    cudaGetSymbolAddress((void**)&p_wt,   g_wt);
    cudaGetSymbolAddress((void**)&p_qkvb, g_qkvb);

    const float* wt_p = p_wt + 0 * 65536;
    const float* wt_1 = p_wt + 1 * 65536;
    const float* wt_2 = p_wt + 2 * 65536;

    cudaFuncSetAttribute(k_gemm6<0,1>, cudaFuncAttributeMaxDynamicSharedMemorySize, GEMM_SMEM);
    cudaFuncSetAttribute(k_gemm6<2,1>, cudaFuncAttributeMaxDynamicSharedMemorySize, GEMM_SMEM);
    cudaFuncSetAttribute(k_gemm6<3,2>, cudaFuncAttributeMaxDynamicSharedMemorySize, GEMM_SMEM);
    cudaFuncSetAttribute(k_gemm6<4,1>, cudaFuncAttributeMaxDynamicSharedMemorySize, GEMM_SMEM);

    dim3 gqkv((kM1 + 127) / 128, 3);   // 401 x 3
    int g2 = kU / 128;                 // 400

    // 0) prep
    k_prep<<<257 + 1536 + 3, 256>>>(t_w, p_w, t_b, p_b, q_w, k_w, v_w, w1, w2, q_b, k_b, v_b);
    // 1) LN of unique tokens
    k_ln_x<<<(kM1 + 31) / 32, 256>>>(x, ln1g, ln1b);
    // 2) fused q|k|v projection -> g_qkv (row pitch 768)
    k_gemm6<0,1><<<gqkv, 512, GEMM_SMEM>>>(p_nx, p_wqkv, nullptr, nullptr, p_qkvb, nullptr,
                                           p_qkv, nullptr, nullptr, nullptr, kM1, kC3, kC3);
    // 3) q attention logits
    k_qlog<<<(kM1 + 63) / 64, 256>>>(qa_w, qa_b, kM1);
    // 4) fused pooling -> mq (g_nx), mkv
    k_pool<<<kB, 256>>>(ka_w, ka_b);
    // 5) attraw = mkv@tp_w + mq@p_w + tp_b + xr -> g_k ; fused LN -> f (g_v)
    k_gemm6<3,2><<<g2, 512, GEMM_SMEM>>>(p_mkv, p_tw, p_nx, wt_p, p_tb, p_xr,
                                         p_k, p_v, ffng, ffnb, kU, kC, kC);
    // 6) h1 = trunc(gelu(f @ w1 + b1)) -> g_nx
    k_gemm6<2,1><<<g2, 512, GEMM_SMEM>>>(p_v, wt_1, nullptr, nullptr, b1, nullptr,
                                         p_nx, nullptr, nullptr, nullptr, kU, kC, kC);
    // 7) y = h1 @ w2 + b2 + attraw -> transposed out
    k_gemm6<4,1><<<g2, 512, GEMM_SMEM>>>(p_nx, wt_2, nullptr, nullptr, b2, p_k,
                                         out, nullptr, nullptr, nullptr, kU, kC, kC);
}

// round 9
// speedup vs baseline: 1.4019x; 1.1302x over previous
#include <cuda_runtime.h>
#include <cuda_bf16.h>
#include <cstdint>
#include <cstddef>

constexpr int kN   = 32;
constexpr int kC   = 256;
constexpr int kC3  = 768;
constexpr int kT   = 64;
constexpr int kV   = 25;
constexpr int kH   = 8;
constexpr int kWIN = 5;
constexpr int kB   = kN * kT;        // 2048 windows
constexpr int kL   = kWIN * kV;      // 125
constexpr int kU   = kB * kV;        // 51200 unique tokens
constexpr int kM1  = kU + 1;         // + pad row
constexpr int kTV  = kT * kV;        // 1600
constexpr int kXN  = kC * kTV;       // 409600
constexpr float kSCALE = 0.17677669529663687f;  // 1/sqrt(32)

// ---------------- scratch ----------------
__device__ __nv_bfloat16 g_nxh [(size_t)kM1 * kC];   // LN(x) bf16 (GEMM A)
__device__ float         g_qkv [(size_t)kM1 * kC3];  // q|k|v fp32
__device__ float         g_k   [(size_t)kM1 * kC];   // attraw fp32
__device__ __nv_bfloat16 g_fh  [(size_t)kU  * kC];   // f = LN(attraw) bf16
__device__ float         g_xr  [(size_t)kU  * kC];   // gathered x (residual)
__device__ __nv_bfloat16 g_mkvh[(size_t)kU  * kC];   // mkv bf16
__device__ __nv_bfloat16 g_mqh [(size_t)kU  * kC];   // mq bf16
__device__ __nv_bfloat16 g_h1h [(size_t)kU  * kC];   // h1 bf16
__device__ float         g_ql  [(size_t)kM1 * kH];   // q attention logits
__device__ __nv_bfloat16 g_twT [65536];              // (t_w@p_w)^T bf16 [n][k]
__device__ float         g_tb  [kC];                 // t_b @ p_w + p_b
__device__ __nv_bfloat16 g_wqkvT[(size_t)kC3 * kC];  // concat [q|k|v]^T bf16
__device__ __nv_bfloat16 g_wpT [65536];              // p_w^T bf16
__device__ __nv_bfloat16 g_w1T [65536];              // w1^T bf16
__device__ __nv_bfloat16 g_w2T [65536];              // w2^T bf16
__device__ float         g_qkvb[kC3];                // concat biases

// ============ prep: tp_w/tp_b, transposed bf16 weights, concat biases ============
__global__ void __launch_bounds__(256) k_prep(const float* __restrict__ t_w,
                                              const float* __restrict__ p_w,
                                              const float* __restrict__ t_b,
                                              const float* __restrict__ p_b,
                                              const float* __restrict__ q_w,
                                              const float* __restrict__ k_w,
                                              const float* __restrict__ v_w,
                                              const float* __restrict__ w1,
                                              const float* __restrict__ w2,
                                              const float* __restrict__ q_b,
                                              const float* __restrict__ k_b,
                                              const float* __restrict__ v_b) {
    int bid = blockIdx.x, tid = threadIdx.x;
    if (bid < 257) {
        // tp row bid (or bias row): acc over m of srow[m]*p_w[m][c]
        __shared__ float srow[kC];
        bool isw = (bid < kC);
        srow[tid] = isw ? t_w[(size_t)bid * kC + tid] : t_b[tid];
        __syncthreads();
        float acc = isw ? 0.f : p_b[tid];
#pragma unroll 8
        for (int m = 0; m < kC; m++) acc += srow[m] * p_w[(size_t)m * kC + tid];
        if (isw) g_twT[(size_t)tid * kC + bid] = __float2bfloat16(acc);  // transposed
        else     g_tb[tid] = acc;
    } else if (bid < 257 + 384) {
        // tiled transpose-convert: 6 weights x 64 tiles of 32x32
        __shared__ float tile[32][33];
        int t = bid - 257;
        int w = t >> 6; t &= 63;
        int k0 = (t >> 3) * 32, n0 = (t & 7) * 32;
        const float* s = (w == 0) ? q_w : (w == 1) ? k_w : (w == 2) ? v_w
                       : (w == 3) ? p_w : (w == 4) ? w1 : w2;
        __nv_bfloat16* dT = (w < 3) ? (g_wqkvT + (size_t)w * 256 * kC)
                          : (w == 3) ? g_wpT : (w == 4) ? g_w1T : g_w2T;
        int tx = tid & 31, ty = tid >> 5;   // 32 x 8
#pragma unroll
        for (int j = 0; j < 4; j++)
            tile[ty + 8 * j][tx] = s[(size_t)(k0 + ty + 8 * j) * kC + n0 + tx];
        __syncthreads();
#pragma unroll
        for (int j = 0; j < 4; j++)
            dT[(size_t)(n0 + ty + 8 * j) * kC + k0 + tx] = __float2bfloat16(tile[tx][ty + 8 * j]);
    } else {
        int k = bid - (257 + 384);          // 0..2
        g_qkvb[k * 256 + tid] = (k == 0) ? q_b[tid] : (k == 1) ? k_b[tid] : v_b[tid];
    }
}

// ============ LN of unique tokens (gather) -> bf16 nx, raw xr ============
__global__ void __launch_bounds__(256) k_ln_x(const float* __restrict__ x,
                                              const float* __restrict__ g,
                                              const float* __restrict__ b) {
    __shared__ float sx[32][257];
    int tid = threadIdx.x;
    int u0  = blockIdx.x * 32;
    {
        int ur = tid & 31;
        int u  = u0 + ur;
        int cb = tid >> 5;
        bool has = (u < kU);
        size_t base = 0;
        if (has) { int n = u / kTV; base = (size_t)n * kXN + (u - n * kTV); }
#pragma unroll
        for (int j = 0; j < 32; j++) {
            int c = cb * 32 + j;
            sx[ur][c] = has ? x[base + (size_t)c * kTV] : 0.f;
        }
    }
    __syncthreads();
    int lane = tid & 31, warp = tid >> 5;
#pragma unroll
    for (int rr = 0; rr < 4; rr++) {
        int ur = warp * 4 + rr;
        int u  = u0 + ur;
        if (u >= kM1) continue;
        float vals[8];
        float s = 0.f, sq = 0.f;
#pragma unroll
        for (int j = 0; j < 8; j++) {
            float t = sx[ur][lane + 32 * j];
            vals[j] = t; s += t; sq += t * t;
        }
#pragma unroll
        for (int o = 16; o; o >>= 1) {
            s  += __shfl_xor_sync(0xffffffffu, s,  o);
            sq += __shfl_xor_sync(0xffffffffu, sq, o);
        }
        float mean = s * (1.f / kC);
        float var  = sq * (1.f / kC) - mean * mean;
        float rstd = rsqrtf(var + 1e-5f);
#pragma unroll
        for (int j = 0; j < 8; j++) {
            int c = lane + 32 * j;
            g_nxh[(size_t)u * kC + c] = __float2bfloat16((vals[j] - mean) * rstd * g[c] + b[c]);
            if (u < kU) g_xr[(size_t)u * kC + c] = vals[j];
        }
    }
}

// ============ bf16 GEMM v7: CTA 128x256, 512 thr, 3-stage, W pre-transposed [n][k] ============
// EPI: 0 fp32 store; 2 gelu->bf16 Dh; 3 addm+fp32 D + fused-LN->bf16 Dh; 4 addm+transposed out
constexpr int HP   = 40;                    // bf16 row pitch (32 + pad)
constexpr int ASZH = 128 * HP;              // A stage elems
constexpr int BSZH = 256 * HP;              // B stage elems
constexpr int GEMM_SMEM = 3 * (ASZH + BSZH) * 2;   // 92160 bytes
constexpr int BPITCH = 264;                 // fp32 epilogue staging pitch

__device__ __forceinline__ void mma_bf16(float (&d)[4], const uint32_t (&a)[4],
                                         const uint32_t (&bb)[2]) {
    asm volatile(
        "mma.sync.aligned.m16n8k16.row.col.f32.bf16.bf16.f32 "
        "{%0,%1,%2,%3}, {%4,%5,%6,%7}, {%8,%9}, {%0,%1,%2,%3};\n"
        : "+f"(d[0]), "+f"(d[1]), "+f"(d[2]), "+f"(d[3])
        : "r"(a[0]), "r"(a[1]), "r"(a[2]), "r"(a[3]), "r"(bb[0]), "r"(bb[1]));
}
__device__ __forceinline__ void cpa16(uint32_t dst, const void* src, bool pred) {
    int sz = pred ? 16 : 0;
    asm volatile("cp.async.cg.shared.global [%0], [%1], 16, %2;\n"
                 :: "r"(dst), "l"(src), "r"(sz));
}
__device__ __forceinline__ float gelu_exact(float x) {
    return 0.5f * x * (1.0f + erff(x * 0.70710678118654752f));
}

template<int EPI, int NPAIR>
__global__ void __launch_bounds__(512, 1) k_gemm7(const __nv_bfloat16* __restrict__ A1,
                                                  const __nv_bfloat16* __restrict__ W1,
                                                  const __nv_bfloat16* __restrict__ A2,
                                                  const __nv_bfloat16* __restrict__ W2,
                                                  const float* __restrict__ bias,
                                                  const float* __restrict__ addm,
                                                  float* __restrict__ D,
                                                  __nv_bfloat16* __restrict__ Dh,
                                                  const float* __restrict__ lng,
                                                  const float* __restrict__ lnb,
                                                  int M, int ldD) {
    extern __shared__ char smc[];
    __nv_bfloat16* As = (__nv_bfloat16*)smc;          // 3 x ASZH
    __nv_bfloat16* Bs = As + 3 * ASZH;                // 3 x BSZH
    float* ep = (float*)smc;                          // epilogue staging
    uint32_t sA = (uint32_t)__cvta_generic_to_shared(As);
    uint32_t sB = (uint32_t)__cvta_generic_to_shared(Bs);

    int coly = blockIdx.y * 256;        // column slab (QKV fused GEMM)
    bias += coly; D += coly;

    int tid = threadIdx.x, lane = tid & 31, warp = tid >> 5;
    int wm = warp >> 2, wn = warp & 3;  // 4 x 4 warp grid, warp tile 32x64
    int p = lane >> 2, q = lane & 3;
    int row0 = blockIdx.x * 128;
    int mbase = wm * 32, nbase = wn * 64;

    int ar = tid & 127, ah = tid >> 7;       // A: row, 8-elem chunk (4 chunks)
    int bn = tid & 255, bh = tid >> 8;       // B: n-row, chunk-pair (2 each)
    bool arow_ok = (row0 + ar) < M;
    const __nv_bfloat16* A1g = A1 + (size_t)(row0 + ar) * kC + ah * 8;
    const __nv_bfloat16* W1g = W1 + (size_t)(coly + bn) * kC + bh * 16;
    const __nv_bfloat16* A2g = (NPAIR == 2) ? (A2 + (size_t)(row0 + ar) * kC + ah * 8) : A1g;
    const __nv_bfloat16* W2g = (NPAIR == 2) ? (W2 + (size_t)(coly + bn) * kC + bh * 16) : W1g;
    uint32_t adst0 = sA + (uint32_t)((ar * HP + ah * 8) * 2);
    uint32_t bdst0 = sB + (uint32_t)((bn * HP + bh * 16) * 2);

    auto issue = [&](int kt) {
        int ktt = kt & 7;
        int buf = kt % 3;
        const __nv_bfloat16* as = ((NPAIR == 2 && (kt >> 3)) ? A2g : A1g) + ktt * 32;
        const __nv_bfloat16* bs = ((NPAIR == 2 && (kt >> 3)) ? W2g : W1g) + ktt * 32;
        cpa16(adst0 + (uint32_t)(buf * ASZH * 2), as, arow_ok);
        uint32_t bd = bdst0 + (uint32_t)(buf * BSZH * 2);
        cpa16(bd,      bs,     true);
        cpa16(bd + 16, bs + 8, true);
    };

    float acc[2][8][4] = {};
    const int TOT = 8 * NPAIR;

    issue(0);
    asm volatile("cp.async.commit_group;\n");
    issue(1);
    asm volatile("cp.async.commit_group;\n");

#pragma unroll 1
    for (int kt = 0; kt < TOT; kt++) {
        if (kt < TOT - 1) asm volatile("cp.async.wait_group 1;\n");
        else              asm volatile("cp.async.wait_group 0;\n");
        __syncthreads();
        if (kt + 2 < TOT) {
            issue(kt + 2);
            asm volatile("cp.async.commit_group;\n");
        }
        int buf = kt % 3;
        const __nv_bfloat16* Ab = As + buf * ASZH;
        const __nv_bfloat16* Bb = Bs + buf * BSZH;
#pragma unroll
        for (int kk = 0; kk < 32; kk += 16) {
            uint32_t af[2][4], bf[8][2];
#pragma unroll
            for (int mi = 0; mi < 2; mi++) {
                const __nv_bfloat16* a0 = Ab + (mbase + mi * 16 + p) * HP + kk + 2 * q;
                af[mi][0] = *(const uint32_t*)(a0);
                af[mi][1] = *(const uint32_t*)(a0 + 8 * HP);
                af[mi][2] = *(const uint32_t*)(a0 + 8);
                af[mi][3] = *(const uint32_t*)(a0 + 8 * HP + 8);
            }
#pragma unroll
            for (int ni = 0; ni < 8; ni++) {
                const __nv_bfloat16* b0 = Bb + (nbase + ni * 8 + p) * HP + kk + 2 * q;
                bf[ni][0] = *(const uint32_t*)(b0);
                bf[ni][1] = *(const uint32_t*)(b0 + 8);
            }
#pragma unroll
            for (int mi = 0; mi < 2; mi++)
#pragma unroll
                for (int ni = 0; ni < 8; ni++)
                    mma_bf16(acc[mi][ni], af[mi], bf[ni]);
        }
    }
    __syncthreads();

    // ---------------- epilogue ----------------
    if (EPI == 0 || EPI == 2) {
#pragma unroll
        for (int mi = 0; mi < 2; mi++) {
            int r1 = row0 + mbase + mi * 16 + p;
            int r2 = r1 + 8;
#pragma unroll
            for (int ni = 0; ni < 8; ni++) {
                int cc = nbase + ni * 8 + 2 * q;
                float2 bv = *(const float2*)(bias + cc);
                float d0 = acc[mi][ni][0] + bv.x, d1 = acc[mi][ni][1] + bv.y;
                float d2 = acc[mi][ni][2] + bv.x, d3 = acc[mi][ni][3] + bv.y;
                if (EPI == 0) {
                    if (r1 < M) { float2 o = {d0, d1}; *(float2*)(D + (size_t)r1 * ldD + cc) = o; }
                    if (r2 < M) { float2 o = {d2, d3}; *(float2*)(D + (size_t)r2 * ldD + cc) = o; }
                } else {
                    __nv_bfloat162 o1 = {__float2bfloat16(gelu_exact(d0)), __float2bfloat16(gelu_exact(d1))};
                    __nv_bfloat162 o2 = {__float2bfloat16(gelu_exact(d2)), __float2bfloat16(gelu_exact(d3))};
                    if (r1 < M) *(__nv_bfloat162*)(Dh + (size_t)r1 * kC + cc) = o1;
                    if (r2 < M) *(__nv_bfloat162*)(Dh + (size_t)r2 * kC + cc) = o2;
                }
            }
        }
    } else {
        // EPI 3 / 4: two 64-row halves through smem staging (M multiple of 128)
#pragma unroll 1
        for (int half = 0; half < 2; half++) {
            __syncthreads();
            if ((wm >> 1) == half) {
#pragma unroll
                for (int mi = 0; mi < 2; mi++) {
                    int lr1 = mbase + mi * 16 + p;
                    int lr2 = lr1 + 8;
                    int r1 = row0 + lr1, r2 = row0 + lr2;
                    int e1 = lr1 - half * 64, e2 = lr2 - half * 64;
#pragma unroll
                    for (int ni = 0; ni < 8; ni++) {
                        int cc = nbase + ni * 8 + 2 * q;
                        float2 bv = *(const float2*)(bias + cc);
                        float2 a1 = *(const float2*)(addm + (size_t)r1 * kC + cc);
                        float2 a2 = *(const float2*)(addm + (size_t)r2 * kC + cc);
                        float2 o1 = {acc[mi][ni][0] + bv.x + a1.x, acc[mi][ni][1] + bv.y + a1.y};
                        float2 o2 = {acc[mi][ni][2] + bv.x + a2.x, acc[mi][ni][3] + bv.y + a2.y};
                        if (EPI == 3) {
                            *(float2*)(D + (size_t)r1 * ldD + cc) = o1;   // attraw
                            *(float2*)(D + (size_t)r2 * ldD + cc) = o2;
                        }
                        *(float2*)(ep + e1 * BPITCH + cc) = o1;
                        *(float2*)(ep + e2 * BPITCH + cc) = o2;
                    }
                }
            }
            __syncthreads();
            if (EPI == 3) {   // fused LN over 64 staged rows -> bf16 Dh
                float gg[8], bb[8];
#pragma unroll
                for (int j = 0; j < 8; j++) {
                    int c = lane + 32 * j;
                    gg[j] = lng[c]; bb[j] = lnb[c];
                }
#pragma unroll
                for (int rr = 0; rr < 4; rr++) {
                    int lr = warp * 4 + rr;            // 0..63
                    float vals[8]; float s = 0.f, sq = 0.f;
#pragma unroll
                    for (int j = 0; j < 8; j++) {
                        float t = ep[lr * BPITCH + lane + 32 * j];
                        vals[j] = t; s += t; sq += t * t;
                    }
#pragma unroll
                    for (int o = 16; o; o >>= 1) {
                        s  += __shfl_xor_sync(0xffffffffu, s,  o);
                        sq += __shfl_xor_sync(0xffffffffu, sq, o);
                    }
                    float mean = s * (1.f / kC);
                    float var  = sq * (1.f / kC) - mean * mean;
                    float rstd = rsqrtf(var + 1e-5f);
                    int gr = row0 + half * 64 + lr;
#pragma unroll
                    for (int j = 0; j < 8; j++) {
                        int c = lane + 32 * j;
                        Dh[(size_t)gr * kC + c] = __float2bfloat16((vals[j] - mean) * rstd * gg[j] + bb[j]);
                    }
                }
            } else {          // EPI 4: transposed write to out (n,c,t,v)
#pragma unroll 1
                for (int it = 0; it < 32; it++) {
                    int j = it * 512 + tid;
                    int c = j >> 6, rr = j & 63;
                    unsigned R = (unsigned)(row0 + half * 64 + rr);
                    unsigned b = R / 25u;
                    unsigned v = R - b * 25u;
                    unsigned n = b >> 6, t = b & 63u;
                    D[(size_t)n * kXN + (size_t)c * kTV + t * kV + v] = ep[rr * BPITCH + c];
                }
            }
        }
    }
}

// ============ q attention logits: 8 rows per warp, qa_w reg-cached ============
__global__ void __launch_bounds__(256) k_qlog(const float* __restrict__ qa_w,
                                              const float* __restrict__ qa_b, int M) {
    int warp = threadIdx.x >> 5, lane = threadIdx.x & 31;
    int r0 = (blockIdx.x * 8 + warp) * 8;
    int c0 = lane * 8;
    float wreg[8][8];
#pragma unroll
    for (int j = 0; j < 8; j++) {
        const float4* wr = (const float4*)(qa_w + (size_t)(c0 + j) * kH);
        float4 w0 = wr[0], w1 = wr[1];
        wreg[j][0] = w0.x; wreg[j][1] = w0.y; wreg[j][2] = w0.z; wreg[j][3] = w0.w;
        wreg[j][4] = w1.x; wreg[j][5] = w1.y; wreg[j][6] = w1.z; wreg[j][7] = w1.w;
    }
    float qab = (lane < kH) ? qa_b[lane] : 0.f;
#pragma unroll 1
    for (int rr = 0; rr < 8; rr++) {
        int r = r0 + rr;
        if (r >= M) return;
        const float* row = g_qkv + (size_t)r * kC3;
        float4 v0 = *(const float4*)(row + c0);
        float4 v1 = *(const float4*)(row + c0 + 4);
        float vv[8] = {v0.x, v0.y, v0.z, v0.w, v1.x, v1.y, v1.z, v1.w};
        float acc[8] = {};
#pragma unroll
        for (int j = 0; j < 8; j++)
#pragma unroll
            for (int e = 0; e < 8; e++)
                acc[e] += vv[j] * wreg[j][e];
#pragma unroll
        for (int o = 16; o; o >>= 1)
#pragma unroll
            for (int e = 0; e < 8; e++)
                acc[e] += __shfl_xor_sync(0xffffffffu, acc[e], o);
        if (lane < kH) g_ql[(size_t)r * kH + lane] = (acc[lane] + qab) * kSCALE;
    }
}

// ============ fused per-window pooling (qkv-interleaved reads) ============
constexpr int KAP = 12;
__global__ void __launch_bounds__(256) k_pool(const float* __restrict__ ka_w,
                                              const float* __restrict__ ka_b) {
    __shared__ int   su[kL];
    __shared__ float sqw[kH][128];
    __shared__ float skw[kH][128];
    __shared__ float spq[kC];
    __shared__ __align__(16) float skaw[kC * KAP];
    __shared__ float smv[kV * 256];
    int tid = threadIdx.x, lane = tid & 31, h = tid >> 5;
    int b = blockIdx.x, n = b / kT, t = b % kT;

    for (int i = tid; i < kC * kH; i += 256) {
        int c = i >> 3, e = i & 7;
        skaw[c * KAP + e] = ka_w[i];
    }
    if (tid < kL) {
        int w = tid / kV, v = tid - w * kV;
        int tp = t + w - 2;
        su[tid] = (tp >= 0 && tp < kT) ? (n * kT + tp) * kV + v : kU;
    }
    float kab = (lane < kH) ? ka_b[lane] : 0.f;
    __syncthreads();

    // ---- q-weight softmax (warp h over l) ----
    {
        float lv[4]; float mx = -1e30f;
#pragma unroll
        for (int i = 0; i < 4; i++) {
            int l = lane + 32 * i;
            lv[i] = (l < kL) ? g_ql[(size_t)su[l] * kH + h] : -1e30f;
            mx = fmaxf(mx, lv[i]);
        }
#pragma unroll
        for (int o = 16; o; o >>= 1) mx = fmaxf(mx, __shfl_xor_sync(0xffffffffu, mx, o));
        float sm = 0.f;
#pragma unroll
        for (int i = 0; i < 4; i++) {
            int l = lane + 32 * i;
            lv[i] = (l < kL) ? expf(lv[i] - mx) : 0.f;
            sm += lv[i];
        }
#pragma unroll
        for (int o = 16; o; o >>= 1) sm += __shfl_xor_sync(0xffffffffu, sm, o);
        float inv = 1.f / sm;
#pragma unroll
        for (int i = 0; i < 4; i++) {
            int l = lane + 32 * i;
            if (l < kL) sqw[h][l] = lv[i] * inv;
        }
    }
    __syncthreads();

    // ---- pass A: pq + mq (q slice) ----
    float pq = 0.f;
#pragma unroll 5
    for (int v = 0; v < kV; v++) {
        float a = 0.f;
#pragma unroll
        for (int w = 0; w < kWIN; w++) {
            int l = w * kV + v;
            float val = g_qkv[(size_t)su[l] * kC3 + tid];
            pq += sqw[h][l] * val;
            a  += val;
        }
        g_mqh[((size_t)b * kV + v) * kC + tid] = __float2bfloat16(a * 0.2f);
    }
    spq[tid] = pq;
    __syncthreads();

    // ---- pass B: k logits (k slice) ----
    float pqr[8];
#pragma unroll
    for (int j = 0; j < 8; j++) pqr[j] = spq[lane + 32 * j];
#pragma unroll 1
    for (int l = h; l < kL; l += kH) {
        const float* kr = g_qkv + (size_t)su[l] * kC3 + 256;
        float acc[8] = {};
#pragma unroll
        for (int j = 0; j < 8; j++) {
            float kp = kr[lane + 32 * j] * pqr[j];
            const float4* ka = (const float4*)(skaw + (lane + 32 * j) * KAP);
            float4 k0 = ka[0], k1 = ka[1];
            acc[0] += kp * k0.x; acc[1] += kp * k0.y;
            acc[2] += kp * k0.z; acc[3] += kp * k0.w;
            acc[4] += kp * k1.x; acc[5] += kp * k1.y;
            acc[6] += kp * k1.z; acc[7] += kp * k1.w;
        }
#pragma unroll
        for (int o = 16; o; o >>= 1)
#pragma unroll
            for (int e = 0; e < 8; e++)
                acc[e] += __shfl_xor_sync(0xffffffffu, acc[e], o);
        if (lane < kH) skw[lane][l] = (acc[lane] + kab) * kSCALE;
    }
    __syncthreads();

    // ---- k-weight softmax ----
    {
        float lv[4]; float mx = -1e30f;
#pragma unroll
        for (int i = 0; i < 4; i++) {
            int l = lane + 32 * i;
            lv[i] = (l < kL) ? skw[h][l] : -1e30f;
            mx = fmaxf(mx, lv[i]);
        }
#pragma unroll
        for (int o = 16; o; o >>= 1) mx = fmaxf(mx, __shfl_xor_sync(0xffffffffu, mx, o));
        float sm = 0.f;
#pragma unroll
        for (int i = 0; i < 4; i++) {
            int l = lane + 32 * i;
            lv[i] = (l < kL) ? expf(lv[i] - mx) : 0.f;
            sm += lv[i];
        }
#pragma unroll
        for (int o = 16; o; o >>= 1) sm += __shfl_xor_sync(0xffffffffu, sm, o);
        float inv = 1.f / sm;
#pragma unroll
        for (int i = 0; i < 4; i++) {
            int l = lane + 32 * i;
            if (l < kL) skw[h][l] = lv[i] * inv;
        }
    }
    __syncthreads();

    // ---- pass C (merged): pk from k, mv into smem, then mkv = pk*mv ----
    float pk = 0.f;
#pragma unroll 5
    for (int v = 0; v < kV; v++) {
        float a = 0.f;
#pragma unroll
        for (int w = 0; w < kWIN; w++) {
            int l = w * kV + v;
            const float* rw = g_qkv + (size_t)su[l] * kC3;
            pk += skw[h][l] * rw[256 + tid];
            a  += rw[512 + tid];
        }
        smv[v * 256 + tid] = a;
    }
#pragma unroll 5
    for (int v = 0; v < kV; v++)
        g_mkvh[((size_t)b * kV + v) * kC + tid] = __float2bfloat16(pk * smv[v * 256 + tid] * 0.2f);
}

// ===================================================================================
extern "C" void kernel_launch(void* const* d_in, const int* in_sizes, int n_in,
                              void* d_out, int out_size) {
    const float* x    = (const float*)d_in[0];
    const float* ln1g = (const float*)d_in[1];
    const float* ln1b = (const float*)d_in[2];
    const float* q_w  = (const float*)d_in[3];
    const float* q_b  = (const float*)d_in[4];
    const float* qa_w = (const float*)d_in[5];
    const float* qa_b = (const float*)d_in[6];
    const float* k_w  = (const float*)d_in[7];
    const float* k_b  = (const float*)d_in[8];
    const float* ka_w = (const float*)d_in[9];
    const float* ka_b = (const float*)d_in[10];
    const float* v_w  = (const float*)d_in[11];
    const float* v_b  = (const float*)d_in[12];
    const float* t_w  = (const float*)d_in[13];
    const float* t_b  = (const float*)d_in[14];
    const float* p_w  = (const float*)d_in[15];
    const float* p_b  = (const float*)d_in[16];
    const float* ffng = (const float*)d_in[17];
    const float* ffnb = (const float*)d_in[18];
    const float* w1   = (const float*)d_in[19];
    const float* b1   = (const float*)d_in[20];
    const float* w2   = (const float*)d_in[21];
    const float* b2   = (const float*)d_in[22];
    float* out = (float*)d_out;

    float *p_qkv, *p_k, *p_xr, *p_tb, *p_qkvb;
    __nv_bfloat16 *p_nxh, *p_fh, *p_mkvh, *p_mqh, *p_h1h, *p_twT, *p_wqkvT, *p_wpT, *p_w1T, *p_w2T;
    cudaGetSymbolAddress((void**)&p_qkv,   g_qkv);
    cudaGetSymbolAddress((void**)&p_k,     g_k);
    cudaGetSymbolAddress((void**)&p_xr,    g_xr);
    cudaGetSymbolAddress((void**)&p_tb,    g_tb);
    cudaGetSymbolAddress((void**)&p_qkvb,  g_qkvb);
    cudaGetSymbolAddress((void**)&p_nxh,   g_nxh);
    cudaGetSymbolAddress((void**)&p_fh,    g_fh);
    cudaGetSymbolAddress((void**)&p_mkvh,  g_mkvh);
    cudaGetSymbolAddress((void**)&p_mqh,   g_mqh);
    cudaGetSymbolAddress((void**)&p_h1h,   g_h1h);
    cudaGetSymbolAddress((void**)&p_twT,   g_twT);
    cudaGetSymbolAddress((void**)&p_wqkvT, g_wqkvT);
    cudaGetSymbolAddress((void**)&p_wpT,   g_wpT);
    cudaGetSymbolAddress((void**)&p_w1T,   g_w1T);
    cudaGetSymbolAddress((void**)&p_w2T,   g_w2T);

    cudaFuncSetAttribute(k_gemm7<0,1>, cudaFuncAttributeMaxDynamicSharedMemorySize, GEMM_SMEM);
    cudaFuncSetAttribute(k_gemm7<2,1>, cudaFuncAttributeMaxDynamicSharedMemorySize, GEMM_SMEM);
    cudaFuncSetAttribute(k_gemm7<3,2>, cudaFuncAttributeMaxDynamicSharedMemorySize, GEMM_SMEM);
    cudaFuncSetAttribute(k_gemm7<4,1>, cudaFuncAttributeMaxDynamicSharedMemorySize, GEMM_SMEM);

    dim3 gqkv((kM1 + 127) / 128, 3);   // 401 x 3
    int g2 = kU / 128;                 // 400

    // 0) prep: tp_w/tp_b + transposed bf16 weights + biases
    k_prep<<<257 + 384 + 3, 256>>>(t_w, p_w, t_b, p_b, q_w, k_w, v_w, w1, w2, q_b, k_b, v_b);
    // 1) LN of unique tokens -> bf16 nx + fp32 xr
    k_ln_x<<<(kM1 + 31) / 32, 256>>>(x, ln1g, ln1b);
    // 2) fused q|k|v projection -> g_qkv fp32 (row pitch 768)
    k_gemm7<0,1><<<gqkv, 512, GEMM_SMEM>>>(p_nxh, p_wqkvT, nullptr, nullptr, p_qkvb, nullptr,
                                           p_qkv, nullptr, nullptr, nullptr, kM1, kC3);
    // 3) q attention logits
    k_qlog<<<(kM1 + 63) / 64, 256>>>(qa_w, qa_b, kM1);
    // 4) fused pooling -> mq (bf16), mkv (bf16)
    k_pool<<<kB, 256>>>(ka_w, ka_b);
    // 5) attraw = mkv@tp_w + mq@p_w + tp_b + xr -> g_k fp32 ; fused LN -> f bf16
    k_gemm7<3,2><<<g2, 512, GEMM_SMEM>>>(p_mkvh, p_twT, p_mqh, p_wpT, p_tb, p_xr,
                                         p_k, p_fh, ffng, ffnb, kU, kC);
    // 6) h1 = gelu(f @ w1 + b1) -> bf16
    k_gemm7<2,1><<<g2, 512, GEMM_SMEM>>>(p_fh, p_w1T, nullptr, nullptr, b1, nullptr,
                                         nullptr, p_h1h, nullptr, nullptr, kU, kC);
    // 7) y = h1 @ w2 + b2 + attraw -> transposed out
    k_gemm7<4,1><<<g2, 512, GEMM_SMEM>>>(p_h1h, p_w2T, nullptr, nullptr, b2, p_k,
                                         out, nullptr, nullptr, nullptr, kU, kC);
}

// round 10
// speedup vs baseline: 1.4136x; 1.0083x over previous
#include <cuda_runtime.h>
#include <cuda_bf16.h>
#include <cstdint>
#include <cstddef>

constexpr int kN   = 32;
constexpr int kC   = 256;
constexpr int kC3  = 768;
constexpr int kT   = 64;
constexpr int kV   = 25;
constexpr int kH   = 8;
constexpr int kWIN = 5;
constexpr int kB   = kN * kT;        // 2048 windows
constexpr int kL   = kWIN * kV;      // 125
constexpr int kU   = kB * kV;        // 51200 unique tokens
constexpr int kM1  = kU + 1;         // + pad row
constexpr int kTV  = kT * kV;        // 1600
constexpr int kXN  = kC * kTV;       // 409600
constexpr float kSCALE = 0.17677669529663687f;  // 1/sqrt(32)

// ---------------- scratch ----------------
__device__ __nv_bfloat16 g_nxh [(size_t)kM1 * kC];   // LN(x) bf16 (GEMM A)
__device__ __nv_bfloat16 g_qkvh[(size_t)kM1 * kC3];  // q|k|v bf16
__device__ float         g_k   [(size_t)kM1 * kC];   // attraw fp32
__device__ __nv_bfloat16 g_fh  [(size_t)kU  * kC];   // f = LN(attraw) bf16
__device__ float         g_xr  [(size_t)kU  * kC];   // gathered x (residual)
__device__ __nv_bfloat16 g_mkvh[(size_t)kU  * kC];   // mkv bf16
__device__ __nv_bfloat16 g_mqh [(size_t)kU  * kC];   // mq bf16
__device__ __nv_bfloat16 g_h1h [(size_t)kU  * kC];   // h1 bf16
__device__ float         g_ql  [(size_t)kM1 * kH];   // q attention logits
__device__ __nv_bfloat16 g_twT [65536];              // (t_w@p_w)^T bf16 [n][k]
__device__ float         g_tb  [kC];                 // t_b @ p_w + p_b
__device__ __nv_bfloat16 g_wqkvT[(size_t)kC3 * kC];  // concat [q|k|v]^T bf16
__device__ __nv_bfloat16 g_wpT [65536];              // p_w^T bf16
__device__ __nv_bfloat16 g_w1T [65536];              // w1^T bf16
__device__ __nv_bfloat16 g_w2T [65536];              // w2^T bf16
__device__ float         g_qkvb[kC3];                // concat biases
__device__ float         g_qaw [kC * kH];            // q_w @ qa_w (fp32)
__device__ float         g_qab [kH];                 // q_b @ qa_w + qa_b

// ============ prep: tp_w/tp_b, transposed bf16 weights, qaw', biases ============
__global__ void __launch_bounds__(256) k_prep(const float* __restrict__ t_w,
                                              const float* __restrict__ p_w,
                                              const float* __restrict__ t_b,
                                              const float* __restrict__ p_b,
                                              const float* __restrict__ q_w,
                                              const float* __restrict__ k_w,
                                              const float* __restrict__ v_w,
                                              const float* __restrict__ w1,
                                              const float* __restrict__ w2,
                                              const float* __restrict__ q_b,
                                              const float* __restrict__ k_b,
                                              const float* __restrict__ v_b,
                                              const float* __restrict__ qa_w,
                                              const float* __restrict__ qa_b) {
    int bid = blockIdx.x, tid = threadIdx.x;
    if (bid < 257) {
        __shared__ float srow[kC];
        bool isw = (bid < kC);
        srow[tid] = isw ? t_w[(size_t)bid * kC + tid] : t_b[tid];
        __syncthreads();
        float acc = isw ? 0.f : p_b[tid];
#pragma unroll 8
        for (int m = 0; m < kC; m++) acc += srow[m] * p_w[(size_t)m * kC + tid];
        if (isw) g_twT[(size_t)tid * kC + bid] = __float2bfloat16(acc);  // transposed
        else     g_tb[tid] = acc;
    } else if (bid < 257 + 384) {
        // tiled transpose-convert: 6 weights x 64 tiles of 32x32
        __shared__ float tile[32][33];
        int t = bid - 257;
        int w = t >> 6; t &= 63;
        int k0 = (t >> 3) * 32, n0 = (t & 7) * 32;
        const float* s = (w == 0) ? q_w : (w == 1) ? k_w : (w == 2) ? v_w
                       : (w == 3) ? p_w : (w == 4) ? w1 : w2;
        __nv_bfloat16* dT = (w < 3) ? (g_wqkvT + (size_t)w * 256 * kC)
                          : (w == 3) ? g_wpT : (w == 4) ? g_w1T : g_w2T;
        int tx = tid & 31, ty = tid >> 5;   // 32 x 8
#pragma unroll
        for (int j = 0; j < 4; j++)
            tile[ty + 8 * j][tx] = s[(size_t)(k0 + ty + 8 * j) * kC + n0 + tx];
        __syncthreads();
#pragma unroll
        for (int j = 0; j < 4; j++)
            dT[(size_t)(n0 + ty + 8 * j) * kC + k0 + tx] = __float2bfloat16(tile[tx][ty + 8 * j]);
    } else if (bid < 257 + 384 + 3) {
        int k = bid - (257 + 384);          // 0..2
        g_qkvb[k * 256 + tid] = (k == 0) ? q_b[tid] : (k == 1) ? k_b[tid] : v_b[tid];
    } else {
        // qaw'[c][e] = sum_j q_w[c][j] * qa_w[j][e] ; qab'[e] = q_b@qa_w[:,e] + qa_b[e]
        __shared__ float sqa[kC][kH];
        for (int i = tid; i < kC * kH; i += 256) sqa[i >> 3][i & 7] = qa_w[i];
        __syncthreads();
        int c = tid;
        float acc[8] = {};
        const float* qr = q_w + (size_t)c * kC;
#pragma unroll 4
        for (int j = 0; j < kC; j++) {
            float qv = qr[j];
#pragma unroll
            for (int e = 0; e < 8; e++) acc[e] += qv * sqa[j][e];
        }
#pragma unroll
        for (int e = 0; e < 8; e++) g_qaw[c * kH + e] = acc[e];
        if (tid < kH) {
            float a = qa_b[tid];
            for (int j = 0; j < kC; j++) a += q_b[j] * sqa[j][tid];
            g_qab[tid] = a;
        }
    }
}

// ============ LN of unique tokens -> bf16 nx, raw xr, fused qlog ============
__global__ void __launch_bounds__(256) k_ln_x(const float* __restrict__ x,
                                              const float* __restrict__ g,
                                              const float* __restrict__ b) {
    __shared__ float sx[32][257];
    int tid = threadIdx.x;
    int u0  = blockIdx.x * 32;
    {
        int ur = tid & 31;
        int u  = u0 + ur;
        int cb = tid >> 5;
        bool has = (u < kU);
        size_t base = 0;
        if (has) { int n = u / kTV; base = (size_t)n * kXN + (u - n * kTV); }
#pragma unroll
        for (int j = 0; j < 32; j++) {
            int c = cb * 32 + j;
            sx[ur][c] = has ? x[base + (size_t)c * kTV] : 0.f;
        }
    }
    __syncthreads();
    int lane = tid & 31, warp = tid >> 5;
    // per-warp cache of qaw' columns for this lane's channels (c = lane + 32j)
    float wreg[8][8];
#pragma unroll
    for (int j = 0; j < 8; j++) {
        const float4* wr = (const float4*)(g_qaw + (size_t)(lane + 32 * j) * kH);
        float4 w0 = wr[0], w1 = wr[1];
        wreg[j][0] = w0.x; wreg[j][1] = w0.y; wreg[j][2] = w0.z; wreg[j][3] = w0.w;
        wreg[j][4] = w1.x; wreg[j][5] = w1.y; wreg[j][6] = w1.z; wreg[j][7] = w1.w;
    }
    float qab = (lane < kH) ? g_qab[lane] : 0.f;
#pragma unroll 1
    for (int rr = 0; rr < 4; rr++) {
        int ur = warp * 4 + rr;
        int u  = u0 + ur;
        if (u >= kM1) continue;
        float vals[8];
        float s = 0.f, sq = 0.f;
#pragma unroll
        for (int j = 0; j < 8; j++) {
            float t = sx[ur][lane + 32 * j];
            vals[j] = t; s += t; sq += t * t;
        }
#pragma unroll
        for (int o = 16; o; o >>= 1) {
            s  += __shfl_xor_sync(0xffffffffu, s,  o);
            sq += __shfl_xor_sync(0xffffffffu, sq, o);
        }
        float mean = s * (1.f / kC);
        float var  = sq * (1.f / kC) - mean * mean;
        float rstd = rsqrtf(var + 1e-5f);
        float nxv[8];
        float acc[8] = {};
#pragma unroll
        for (int j = 0; j < 8; j++) {
            int c = lane + 32 * j;
            float nv = (vals[j] - mean) * rstd * g[c] + b[c];
            nxv[j] = nv;
            g_nxh[(size_t)u * kC + c] = __float2bfloat16(nv);
            if (u < kU) g_xr[(size_t)u * kC + c] = vals[j];
#pragma unroll
            for (int e = 0; e < 8; e++) acc[e] += nv * wreg[j][e];
        }
#pragma unroll
        for (int o = 16; o; o >>= 1)
#pragma unroll
            for (int e = 0; e < 8; e++)
                acc[e] += __shfl_xor_sync(0xffffffffu, acc[e], o);
        if (lane < kH) g_ql[(size_t)u * kH + lane] = (acc[lane] + qab) * kSCALE;
        (void)nxv;
    }
}

// ============ bf16 GEMM: CTA 128x256, 512 thr, 3-stage, W pre-transposed [n][k] ============
// EPI: 0 bias->bf16 Dh(ldD); 2 gelu->bf16 Dh; 3 addm+fp32 D + fused-LN->bf16 Dh; 4 addm+transposed out
constexpr int HP   = 40;
constexpr int ASZH = 128 * HP;
constexpr int BSZH = 256 * HP;
constexpr int GEMM_SMEM = 3 * (ASZH + BSZH) * 2;   // 92160 bytes
constexpr int BPITCH = 264;

__device__ __forceinline__ void mma_bf16(float (&d)[4], const uint32_t (&a)[4],
                                         const uint32_t (&bb)[2]) {
    asm volatile(
        "mma.sync.aligned.m16n8k16.row.col.f32.bf16.bf16.f32 "
        "{%0,%1,%2,%3}, {%4,%5,%6,%7}, {%8,%9}, {%0,%1,%2,%3};\n"
        : "+f"(d[0]), "+f"(d[1]), "+f"(d[2]), "+f"(d[3])
        : "r"(a[0]), "r"(a[1]), "r"(a[2]), "r"(a[3]), "r"(bb[0]), "r"(bb[1]));
}
__device__ __forceinline__ void cpa16(uint32_t dst, const void* src, bool pred) {
    int sz = pred ? 16 : 0;
    asm volatile("cp.async.cg.shared.global [%0], [%1], 16, %2;\n"
                 :: "r"(dst), "l"(src), "r"(sz));
}
__device__ __forceinline__ float gelu_exact(float x) {
    return 0.5f * x * (1.0f + erff(x * 0.70710678118654752f));
}

template<int EPI, int NPAIR>
__global__ void __launch_bounds__(512, 1) k_gemm7(const __nv_bfloat16* __restrict__ A1,
                                                  const __nv_bfloat16* __restrict__ W1,
                                                  const __nv_bfloat16* __restrict__ A2,
                                                  const __nv_bfloat16* __restrict__ W2,
                                                  const float* __restrict__ bias,
                                                  const float* __restrict__ addm,
                                                  float* __restrict__ D,
                                                  __nv_bfloat16* __restrict__ Dh,
                                                  const float* __restrict__ lng,
                                                  const float* __restrict__ lnb,
                                                  int M, int ldD) {
    extern __shared__ char smc[];
    __nv_bfloat16* As = (__nv_bfloat16*)smc;          // 3 x ASZH
    __nv_bfloat16* Bs = As + 3 * ASZH;                // 3 x BSZH
    float* ep = (float*)smc;                          // epilogue staging
    uint32_t sA = (uint32_t)__cvta_generic_to_shared(As);
    uint32_t sB = (uint32_t)__cvta_generic_to_shared(Bs);

    int coly = blockIdx.y * 256;        // column slab (QKV fused GEMM)
    bias += coly;
    if (D)  D  += coly;
    if (Dh) Dh += coly;

    int tid = threadIdx.x, lane = tid & 31, warp = tid >> 5;
    int wm = warp >> 2, wn = warp & 3;  // 4 x 4 warp grid, warp tile 32x64
    int p = lane >> 2, q = lane & 3;
    int row0 = blockIdx.x * 128;
    int mbase = wm * 32, nbase = wn * 64;

    int ar = tid & 127, ah = tid >> 7;       // A: row, 8-elem chunk (4 chunks)
    int bn = tid & 255, bh = tid >> 8;       // B: n-row, chunk-pair (2 each)
    bool arow_ok = (row0 + ar) < M;
    const __nv_bfloat16* A1g = A1 + (size_t)(row0 + ar) * kC + ah * 8;
    const __nv_bfloat16* W1g = W1 + (size_t)(coly + bn) * kC + bh * 16;
    const __nv_bfloat16* A2g = (NPAIR == 2) ? (A2 + (size_t)(row0 + ar) * kC + ah * 8) : A1g;
    const __nv_bfloat16* W2g = (NPAIR == 2) ? (W2 + (size_t)(coly + bn) * kC + bh * 16) : W1g;
    uint32_t adst0 = sA + (uint32_t)((ar * HP + ah * 8) * 2);
    uint32_t bdst0 = sB + (uint32_t)((bn * HP + bh * 16) * 2);

    auto issue = [&](int kt) {
        int ktt = kt & 7;
        int buf = kt % 3;
        const __nv_bfloat16* as = ((NPAIR == 2 && (kt >> 3)) ? A2g : A1g) + ktt * 32;
        const __nv_bfloat16* bs = ((NPAIR == 2 && (kt >> 3)) ? W2g : W1g) + ktt * 32;
        cpa16(adst0 + (uint32_t)(buf * ASZH * 2), as, arow_ok);
        uint32_t bd = bdst0 + (uint32_t)(buf * BSZH * 2);
        cpa16(bd,      bs,     true);
        cpa16(bd + 16, bs + 8, true);
    };

    float acc[2][8][4] = {};
    const int TOT = 8 * NPAIR;

    issue(0);
    asm volatile("cp.async.commit_group;\n");
    issue(1);
    asm volatile("cp.async.commit_group;\n");

#pragma unroll 1
    for (int kt = 0; kt < TOT; kt++) {
        if (kt < TOT - 1) asm volatile("cp.async.wait_group 1;\n");
        else              asm volatile("cp.async.wait_group 0;\n");
        __syncthreads();
        if (kt + 2 < TOT) {
            issue(kt + 2);
            asm volatile("cp.async.commit_group;\n");
        }
        int buf = kt % 3;
        const __nv_bfloat16* Ab = As + buf * ASZH;
        const __nv_bfloat16* Bb = Bs + buf * BSZH;
#pragma unroll
        for (int kk = 0; kk < 32; kk += 16) {
            uint32_t af[2][4], bf[8][2];
#pragma unroll
            for (int mi = 0; mi < 2; mi++) {
                const __nv_bfloat16* a0 = Ab + (mbase + mi * 16 + p) * HP + kk + 2 * q;
                af[mi][0] = *(const uint32_t*)(a0);
                af[mi][1] = *(const uint32_t*)(a0 + 8 * HP);
                af[mi][2] = *(const uint32_t*)(a0 + 8);
                af[mi][3] = *(const uint32_t*)(a0 + 8 * HP + 8);
            }
#pragma unroll
            for (int ni = 0; ni < 8; ni++) {
                const __nv_bfloat16* b0 = Bb + (nbase + ni * 8 + p) * HP + kk + 2 * q;
                bf[ni][0] = *(const uint32_t*)(b0);
                bf[ni][1] = *(const uint32_t*)(b0 + 8);
            }
#pragma unroll
            for (int mi = 0; mi < 2; mi++)
#pragma unroll
                for (int ni = 0; ni < 8; ni++)
                    mma_bf16(acc[mi][ni], af[mi], bf[ni]);
        }
    }
    __syncthreads();

    // ---------------- epilogue ----------------
    if (EPI == 0 || EPI == 2) {
#pragma unroll
        for (int mi = 0; mi < 2; mi++) {
            int r1 = row0 + mbase + mi * 16 + p;
            int r2 = r1 + 8;
#pragma unroll
            for (int ni = 0; ni < 8; ni++) {
                int cc = nbase + ni * 8 + 2 * q;
                float2 bv = *(const float2*)(bias + cc);
                float d0 = acc[mi][ni][0] + bv.x, d1 = acc[mi][ni][1] + bv.y;
                float d2 = acc[mi][ni][2] + bv.x, d3 = acc[mi][ni][3] + bv.y;
                if (EPI == 2) {
                    d0 = gelu_exact(d0); d1 = gelu_exact(d1);
                    d2 = gelu_exact(d2); d3 = gelu_exact(d3);
                }
                __nv_bfloat162 o1 = {__float2bfloat16(d0), __float2bfloat16(d1)};
                __nv_bfloat162 o2 = {__float2bfloat16(d2), __float2bfloat16(d3)};
                if (r1 < M) *(__nv_bfloat162*)(Dh + (size_t)r1 * ldD + cc) = o1;
                if (r2 < M) *(__nv_bfloat162*)(Dh + (size_t)r2 * ldD + cc) = o2;
            }
        }
    } else {
        // EPI 3 / 4: two 64-row halves through smem staging (M multiple of 128)
#pragma unroll 1
        for (int half = 0; half < 2; half++) {
            __syncthreads();
            if ((wm >> 1) == half) {
#pragma unroll
                for (int mi = 0; mi < 2; mi++) {
                    int lr1 = mbase + mi * 16 + p;
                    int lr2 = lr1 + 8;
                    int r1 = row0 + lr1, r2 = row0 + lr2;
                    int e1 = lr1 - half * 64, e2 = lr2 - half * 64;
#pragma unroll
                    for (int ni = 0; ni < 8; ni++) {
                        int cc = nbase + ni * 8 + 2 * q;
                        float2 bv = *(const float2*)(bias + cc);
                        float2 a1 = *(const float2*)(addm + (size_t)r1 * kC + cc);
                        float2 a2 = *(const float2*)(addm + (size_t)r2 * kC + cc);
                        float2 o1 = {acc[mi][ni][0] + bv.x + a1.x, acc[mi][ni][1] + bv.y + a1.y};
                        float2 o2 = {acc[mi][ni][2] + bv.x + a2.x, acc[mi][ni][3] + bv.y + a2.y};
                        if (EPI == 3) {
                            *(float2*)(D + (size_t)r1 * ldD + cc) = o1;   // attraw
                            *(float2*)(D + (size_t)r2 * ldD + cc) = o2;
                        }
                        *(float2*)(ep + e1 * BPITCH + cc) = o1;
                        *(float2*)(ep + e2 * BPITCH + cc) = o2;
                    }
                }
            }
            __syncthreads();
            if (EPI == 3) {   // fused LN over 64 staged rows -> bf16 Dh
                float gg[8], bb[8];
#pragma unroll
                for (int j = 0; j < 8; j++) {
                    int c = lane + 32 * j;
                    gg[j] = lng[c]; bb[j] = lnb[c];
                }
#pragma unroll
                for (int rr = 0; rr < 4; rr++) {
                    int lr = warp * 4 + rr;            // 0..63
                    float vals[8]; float s = 0.f, sq = 0.f;
#pragma unroll
                    for (int j = 0; j < 8; j++) {
                        float t = ep[lr * BPITCH + lane + 32 * j];
                        vals[j] = t; s += t; sq += t * t;
                    }
#pragma unroll
                    for (int o = 16; o; o >>= 1) {
                        s  += __shfl_xor_sync(0xffffffffu, s,  o);
                        sq += __shfl_xor_sync(0xffffffffu, sq, o);
                    }
                    float mean = s * (1.f / kC);
                    float var  = sq * (1.f / kC) - mean * mean;
                    float rstd = rsqrtf(var + 1e-5f);
                    int gr = row0 + half * 64 + lr;
#pragma unroll
                    for (int j = 0; j < 8; j++) {
                        int c = lane + 32 * j;
                        Dh[(size_t)gr * kC + c] = __float2bfloat16((vals[j] - mean) * rstd * gg[j] + bb[j]);
                    }
                }
            } else {          // EPI 4: transposed write to out (n,c,t,v)
#pragma unroll 1
                for (int it = 0; it < 32; it++) {
                    int j = it * 512 + tid;
                    int c = j >> 6, rr = j & 63;
                    unsigned R = (unsigned)(row0 + half * 64 + rr);
                    unsigned b = R / 25u;
                    unsigned v = R - b * 25u;
                    unsigned n = b >> 6, t = b & 63u;
                    D[(size_t)n * kXN + (size_t)c * kTV + t * kV + v] = ep[rr * BPITCH + c];
                }
            }
        }
    }
}

// ============ fused per-window pooling (bf16 qkv reads) ============
constexpr int KAP = 12;
__global__ void __launch_bounds__(256) k_pool(const float* __restrict__ ka_w,
                                              const float* __restrict__ ka_b) {
    __shared__ int   su[kL];
    __shared__ float sqw[kH][128];
    __shared__ float skw[kH][128];
    __shared__ float spq[kC];
    __shared__ __align__(16) float skaw[kC * KAP];
    __shared__ float smv[kV * 256];
    int tid = threadIdx.x, lane = tid & 31, h = tid >> 5;
    int b = blockIdx.x, n = b / kT, t = b % kT;

    for (int i = tid; i < kC * kH; i += 256) {
        int c = i >> 3, e = i & 7;
        skaw[c * KAP + e] = ka_w[i];
    }
    if (tid < kL) {
        int w = tid / kV, v = tid - w * kV;
        int tp = t + w - 2;
        su[tid] = (tp >= 0 && tp < kT) ? (n * kT + tp) * kV + v : kU;
    }
    float kab = (lane < kH) ? ka_b[lane] : 0.f;
    __syncthreads();

    // ---- q-weight softmax (warp h over l) ----
    {
        float lv[4]; float mx = -1e30f;
#pragma unroll
        for (int i = 0; i < 4; i++) {
            int l = lane + 32 * i;
            lv[i] = (l < kL) ? g_ql[(size_t)su[l] * kH + h] : -1e30f;
            mx = fmaxf(mx, lv[i]);
        }
#pragma unroll
        for (int o = 16; o; o >>= 1) mx = fmaxf(mx, __shfl_xor_sync(0xffffffffu, mx, o));
        float sm = 0.f;
#pragma unroll
        for (int i = 0; i < 4; i++) {
            int l = lane + 32 * i;
            lv[i] = (l < kL) ? expf(lv[i] - mx) : 0.f;
            sm += lv[i];
        }
#pragma unroll
        for (int o = 16; o; o >>= 1) sm += __shfl_xor_sync(0xffffffffu, sm, o);
        float inv = 1.f / sm;
#pragma unroll
        for (int i = 0; i < 4; i++) {
            int l = lane + 32 * i;
            if (l < kL) sqw[h][l] = lv[i] * inv;
        }
    }
    __syncthreads();

    // ---- pass A: pq + mq (q slice) ----
    float pq = 0.f;
#pragma unroll 5
    for (int v = 0; v < kV; v++) {
        float a = 0.f;
#pragma unroll
        for (int w = 0; w < kWIN; w++) {
            int l = w * kV + v;
            float val = __bfloat162float(g_qkvh[(size_t)su[l] * kC3 + tid]);
            pq += sqw[h][l] * val;
            a  += val;
        }
        g_mqh[((size_t)b * kV + v) * kC + tid] = __float2bfloat16(a * 0.2f);
    }
    spq[tid] = pq;
    __syncthreads();

    // ---- pass B: k logits (k slice) ----
    float pqr[8];
#pragma unroll
    for (int j = 0; j < 8; j++) pqr[j] = spq[lane + 32 * j];
#pragma unroll 1
    for (int l = h; l < kL; l += kH) {
        const __nv_bfloat16* kr = g_qkvh + (size_t)su[l] * kC3 + 256;
        float acc[8] = {};
#pragma unroll
        for (int j = 0; j < 8; j++) {
            float kp = __bfloat162float(kr[lane + 32 * j]) * pqr[j];
            const float4* ka = (const float4*)(skaw + (lane + 32 * j) * KAP);
            float4 k0 = ka[0], k1 = ka[1];
            acc[0] += kp * k0.x; acc[1] += kp * k0.y;
            acc[2] += kp * k0.z; acc[3] += kp * k0.w;
            acc[4] += kp * k1.x; acc[5] += kp * k1.y;
            acc[6] += kp * k1.z; acc[7] += kp * k1.w;
        }
#pragma unroll
        for (int o = 16; o; o >>= 1)
#pragma unroll
            for (int e = 0; e < 8; e++)
                acc[e] += __shfl_xor_sync(0xffffffffu, acc[e], o);
        if (lane < kH) skw[lane][l] = (acc[lane] + kab) * kSCALE;
    }
    __syncthreads();

    // ---- k-weight softmax ----
    {
        float lv[4]; float mx = -1e30f;
#pragma unroll
        for (int i = 0; i < 4; i++) {
            int l = lane + 32 * i;
            lv[i] = (l < kL) ? skw[h][l] : -1e30f;
            mx = fmaxf(mx, lv[i]);
        }
#pragma unroll
        for (int o = 16; o; o >>= 1) mx = fmaxf(mx, __shfl_xor_sync(0xffffffffu, mx, o));
        float sm = 0.f;
#pragma unroll
        for (int i = 0; i < 4; i++) {
            int l = lane + 32 * i;
            lv[i] = (l < kL) ? expf(lv[i] - mx) : 0.f;
            sm += lv[i];
        }
#pragma unroll
        for (int o = 16; o; o >>= 1) sm += __shfl_xor_sync(0xffffffffu, sm, o);
        float inv = 1.f / sm;
#pragma unroll
        for (int i = 0; i < 4; i++) {
            int l = lane + 32 * i;
            if (l < kL) skw[h][l] = lv[i] * inv;
        }
    }
    __syncthreads();

    // ---- pass C (merged): pk from k, mv into smem, then mkv = pk*mv ----
    float pk = 0.f;
#pragma unroll 5
    for (int v = 0; v < kV; v++) {
        float a = 0.f;
#pragma unroll
        for (int w = 0; w < kWIN; w++) {
            int l = w * kV + v;
            const __nv_bfloat16* rw = g_qkvh + (size_t)su[l] * kC3;
            pk += skw[h][l] * __bfloat162float(rw[256 + tid]);
            a  += __bfloat162float(rw[512 + tid]);
        }
        smv[v * 256 + tid] = a;
    }
#pragma unroll 5
    for (int v = 0; v < kV; v++)
        g_mkvh[((size_t)b * kV + v) * kC + tid] = __float2bfloat16(pk * smv[v * 256 + tid] * 0.2f);
}

// ===================================================================================
extern "C" void kernel_launch(void* const* d_in, const int* in_sizes, int n_in,
                              void* d_out, int out_size) {
    const float* x    = (const float*)d_in[0];
    const float* ln1g = (const float*)d_in[1];
    const float* ln1b = (const float*)d_in[2];
    const float* q_w  = (const float*)d_in[3];
    const float* q_b  = (const float*)d_in[4];
    const float* qa_w = (const float*)d_in[5];
    const float* qa_b = (const float*)d_in[6];
    const float* k_w  = (const float*)d_in[7];
    const float* k_b  = (const float*)d_in[8];
    const float* ka_w = (const float*)d_in[9];
    const float* ka_b = (const float*)d_in[10];
    const float* v_w  = (const float*)d_in[11];
    const float* v_b  = (const float*)d_in[12];
    const float* t_w  = (const float*)d_in[13];
    const float* t_b  = (const float*)d_in[14];
    const float* p_w  = (const float*)d_in[15];
    const float* p_b  = (const float*)d_in[16];
    const float* ffng = (const float*)d_in[17];
    const float* ffnb = (const float*)d_in[18];
    const float* w1   = (const float*)d_in[19];
    const float* b1   = (const float*)d_in[20];
    const float* w2   = (const float*)d_in[21];
    const float* b2   = (const float*)d_in[22];
    float* out = (float*)d_out;

    float *p_k, *p_xr, *p_tb, *p_qkvb;
    __nv_bfloat16 *p_nxh, *p_qkvh, *p_fh, *p_mkvh, *p_mqh, *p_h1h, *p_twT, *p_wqkvT, *p_wpT, *p_w1T, *p_w2T;
    cudaGetSymbolAddress((void**)&p_k,     g_k);
    cudaGetSymbolAddress((void**)&p_xr,    g_xr);
    cudaGetSymbolAddress((void**)&p_tb,    g_tb);
    cudaGetSymbolAddress((void**)&p_qkvb,  g_qkvb);
    cudaGetSymbolAddress((void**)&p_nxh,   g_nxh);
    cudaGetSymbolAddress((void**)&p_qkvh,  g_qkvh);
    cudaGetSymbolAddress((void**)&p_fh,    g_fh);
    cudaGetSymbolAddress((void**)&p_mkvh,  g_mkvh);
    cudaGetSymbolAddress((void**)&p_mqh,   g_mqh);
    cudaGetSymbolAddress((void**)&p_h1h,   g_h1h);
    cudaGetSymbolAddress((void**)&p_twT,   g_twT);
    cudaGetSymbolAddress((void**)&p_wqkvT, g_wqkvT);
    cudaGetSymbolAddress((void**)&p_wpT,   g_wpT);
    cudaGetSymbolAddress((void**)&p_w1T,   g_w1T);
    cudaGetSymbolAddress((void**)&p_w2T,   g_w2T);

    cudaFuncSetAttribute(k_gemm7<0,1>, cudaFuncAttributeMaxDynamicSharedMemorySize, GEMM_SMEM);
    cudaFuncSetAttribute(k_gemm7<2,1>, cudaFuncAttributeMaxDynamicSharedMemorySize, GEMM_SMEM);
    cudaFuncSetAttribute(k_gemm7<3,2>, cudaFuncAttributeMaxDynamicSharedMemorySize, GEMM_SMEM);
    cudaFuncSetAttribute(k_gemm7<4,1>, cudaFuncAttributeMaxDynamicSharedMemorySize, GEMM_SMEM);

    dim3 gqkv((kM1 + 127) / 128, 3);   // 401 x 3
    int g2 = kU / 128;                 // 400

    // 0) prep: tp_w/tp_b + transposed bf16 weights + qaw' + biases
    k_prep<<<257 + 384 + 3 + 1, 256>>>(t_w, p_w, t_b, p_b, q_w, k_w, v_w, w1, w2,
                                       q_b, k_b, v_b, qa_w, qa_b);
    // 1) LN of unique tokens -> bf16 nx + fp32 xr + fused qlog
    k_ln_x<<<(kM1 + 31) / 32, 256>>>(x, ln1g, ln1b);
    // 2) fused q|k|v projection -> g_qkvh bf16 (row pitch 768)
    k_gemm7<0,1><<<gqkv, 512, GEMM_SMEM>>>(p_nxh, p_wqkvT, nullptr, nullptr, p_qkvb, nullptr,
                                           nullptr, p_qkvh, nullptr, nullptr, kM1, kC3);
    // 3) fused pooling -> mq (bf16), mkv (bf16)
    k_pool<<<kB, 256>>>(ka_w, ka_b);
    // 4) attraw = mkv@tp_w + mq@p_w + tp_b + xr -> g_k fp32 ; fused LN -> f bf16
    k_gemm7<3,2><<<g2, 512, GEMM_SMEM>>>(p_mkvh, p_twT, p_mqh, p_wpT, p_tb, p_xr,
                                         p_k, p_fh, ffng, ffnb, kU, kC);
    // 5) h1 = gelu(f @ w1 + b1) -> bf16
    k_gemm7<2,1><<<g2, 512, GEMM_SMEM>>>(p_fh, p_w1T, nullptr, nullptr, b1, nullptr,
                                         nullptr, p_h1h, nullptr, nullptr, kU, kC);
    // 6) y = h1 @ w2 + b2 + attraw -> transposed out
    k_gemm7<4,1><<<g2, 512, GEMM_SMEM>>>(p_h1h, p_w2T, nullptr, nullptr, b2, p_k,
                                         out, nullptr, nullptr, nullptr, kU, kC);
}

// round 11
// speedup vs baseline: 1.5246x; 1.0786x over previous
#include <cuda_runtime.h>
#include <cuda_bf16.h>
#include <cstdint>
#include <cstddef>

constexpr int kN   = 32;
constexpr int kC   = 256;
constexpr int kC3  = 768;
constexpr int kT   = 64;
constexpr int kV   = 25;
constexpr int kH   = 8;
constexpr int kWIN = 5;
constexpr int kB   = kN * kT;        // 2048 windows
constexpr int kL   = kWIN * kV;      // 125
constexpr int kU   = kB * kV;        // 51200 unique tokens
constexpr int kM1  = kU + 1;         // + pad row
constexpr int kTV  = kT * kV;        // 1600
constexpr int kXN  = kC * kTV;       // 409600
constexpr float kSCALE = 0.17677669529663687f;  // 1/sqrt(32)

// ---------------- scratch ----------------
__device__ __nv_bfloat16 g_nxh [(size_t)kM1 * kC];   // LN(x) bf16 (GEMM A)
__device__ __nv_bfloat16 g_qkvh[(size_t)kM1 * kC3];  // q|k|v bf16
__device__ float         g_k   [(size_t)kM1 * kC];   // attraw fp32
__device__ __nv_bfloat16 g_fh  [(size_t)kU  * kC];   // f = LN(attraw) bf16
__device__ float         g_xr  [(size_t)kU  * kC];   // gathered x (residual)
__device__ __nv_bfloat16 g_mkvh[(size_t)kU  * kC];   // mkv bf16
__device__ __nv_bfloat16 g_mqh [(size_t)kU  * kC];   // mq bf16
__device__ __nv_bfloat16 g_h1h [(size_t)kU  * kC];   // h1 bf16
__device__ float         g_ql  [(size_t)kM1 * kH];   // q attention logits
__device__ __nv_bfloat16 g_twT [65536];              // (t_w@p_w)^T bf16 [n][k]
__device__ float         g_tb  [kC];                 // t_b @ p_w + p_b
__device__ __nv_bfloat16 g_wqkvT[(size_t)kC3 * kC];  // concat [q|k|v]^T bf16
__device__ __nv_bfloat16 g_wpT [65536];              // p_w^T bf16
__device__ __nv_bfloat16 g_w1T [65536];              // w1^T bf16
__device__ __nv_bfloat16 g_w2T [65536];              // w2^T bf16
__device__ float         g_qkvb[kC3];                // concat biases
__device__ float         g_qaw [kC * kH];            // q_w @ qa_w (fp32)
__device__ float         g_qab [kH];                 // q_b @ qa_w + qa_b

// ============ prep: tp_w/tp_b, transposed bf16 weights, qaw', biases ============
__global__ void __launch_bounds__(256) k_prep(const float* __restrict__ t_w,
                                              const float* __restrict__ p_w,
                                              const float* __restrict__ t_b,
                                              const float* __restrict__ p_b,
                                              const float* __restrict__ q_w,
                                              const float* __restrict__ k_w,
                                              const float* __restrict__ v_w,
                                              const float* __restrict__ w1,
                                              const float* __restrict__ w2,
                                              const float* __restrict__ q_b,
                                              const float* __restrict__ k_b,
                                              const float* __restrict__ v_b,
                                              const float* __restrict__ qa_w,
                                              const float* __restrict__ qa_b) {
    int bid = blockIdx.x, tid = threadIdx.x;
    if (bid < 257) {
        __shared__ float srow[kC];
        bool isw = (bid < kC);
        srow[tid] = isw ? t_w[(size_t)bid * kC + tid] : t_b[tid];
        __syncthreads();
        float acc = isw ? 0.f : p_b[tid];
#pragma unroll 8
        for (int m = 0; m < kC; m++) acc += srow[m] * p_w[(size_t)m * kC + tid];
        if (isw) g_twT[(size_t)tid * kC + bid] = __float2bfloat16(acc);  // transposed
        else     g_tb[tid] = acc;
    } else if (bid < 257 + 384) {
        // tiled transpose-convert: 6 weights x 64 tiles of 32x32
        __shared__ float tile[32][33];
        int t = bid - 257;
        int w = t >> 6; t &= 63;
        int k0 = (t >> 3) * 32, n0 = (t & 7) * 32;
        const float* s = (w == 0) ? q_w : (w == 1) ? k_w : (w == 2) ? v_w
                       : (w == 3) ? p_w : (w == 4) ? w1 : w2;
        __nv_bfloat16* dT = (w < 3) ? (g_wqkvT + (size_t)w * 256 * kC)
                          : (w == 3) ? g_wpT : (w == 4) ? g_w1T : g_w2T;
        int tx = tid & 31, ty = tid >> 5;   // 32 x 8
#pragma unroll
        for (int j = 0; j < 4; j++)
            tile[ty + 8 * j][tx] = s[(size_t)(k0 + ty + 8 * j) * kC + n0 + tx];
        __syncthreads();
#pragma unroll
        for (int j = 0; j < 4; j++)
            dT[(size_t)(n0 + ty + 8 * j) * kC + k0 + tx] = __float2bfloat16(tile[tx][ty + 8 * j]);
    } else if (bid < 257 + 384 + 3) {
        int k = bid - (257 + 384);          // 0..2
        g_qkvb[k * 256 + tid] = (k == 0) ? q_b[tid] : (k == 1) ? k_b[tid] : v_b[tid];
    } else {
        // qaw'[c][e] = sum_j q_w[c][j] * qa_w[j][e] ; qab'[e] = q_b@qa_w[:,e] + qa_b[e]
        __shared__ float sqa[kC][kH];
        for (int i = tid; i < kC * kH; i += 256) sqa[i >> 3][i & 7] = qa_w[i];
        __syncthreads();
        int c = tid;
        float acc[8] = {};
        const float* qr = q_w + (size_t)c * kC;
#pragma unroll 4
        for (int j = 0; j < kC; j++) {
            float qv = qr[j];
#pragma unroll
            for (int e = 0; e < 8; e++) acc[e] += qv * sqa[j][e];
        }
#pragma unroll
        for (int e = 0; e < 8; e++) g_qaw[c * kH + e] = acc[e];
        if (tid < kH) {
            float a = qa_b[tid];
            for (int j = 0; j < kC; j++) a += q_b[j] * sqa[j][tid];
            g_qab[tid] = a;
        }
    }
}

// ============ LN of unique tokens -> bf16 nx, raw xr, fused qlog ============
__global__ void __launch_bounds__(256) k_ln_x(const float* __restrict__ x,
                                              const float* __restrict__ g,
                                              const float* __restrict__ b) {
    __shared__ float sx[32][257];
    int tid = threadIdx.x;
    int u0  = blockIdx.x * 32;
    {
        int ur = tid & 31;
        int u  = u0 + ur;
        int cb = tid >> 5;
        bool has = (u < kU);
        size_t base = 0;
        if (has) { int n = u / kTV; base = (size_t)n * kXN + (u - n * kTV); }
#pragma unroll
        for (int j = 0; j < 32; j++) {
            int c = cb * 32 + j;
            sx[ur][c] = has ? x[base + (size_t)c * kTV] : 0.f;
        }
    }
    __syncthreads();
    int lane = tid & 31, warp = tid >> 5;
    float wreg[8][8];
#pragma unroll
    for (int j = 0; j < 8; j++) {
        const float4* wr = (const float4*)(g_qaw + (size_t)(lane + 32 * j) * kH);
        float4 w0 = wr[0], w1 = wr[1];
        wreg[j][0] = w0.x; wreg[j][1] = w0.y; wreg[j][2] = w0.z; wreg[j][3] = w0.w;
        wreg[j][4] = w1.x; wreg[j][5] = w1.y; wreg[j][6] = w1.z; wreg[j][7] = w1.w;
    }
    float qab = (lane < kH) ? g_qab[lane] : 0.f;
#pragma unroll 1
    for (int rr = 0; rr < 4; rr++) {
        int ur = warp * 4 + rr;
        int u  = u0 + ur;
        if (u >= kM1) continue;
        float vals[8];
        float s = 0.f, sq = 0.f;
#pragma unroll
        for (int j = 0; j < 8; j++) {
            float t = sx[ur][lane + 32 * j];
            vals[j] = t; s += t; sq += t * t;
        }
#pragma unroll
        for (int o = 16; o; o >>= 1) {
            s  += __shfl_xor_sync(0xffffffffu, s,  o);
            sq += __shfl_xor_sync(0xffffffffu, sq, o);
        }
        float mean = s * (1.f / kC);
        float var  = sq * (1.f / kC) - mean * mean;
        float rstd = rsqrtf(var + 1e-5f);
        float acc[8] = {};
#pragma unroll
        for (int j = 0; j < 8; j++) {
            int c = lane + 32 * j;
            float nv = (vals[j] - mean) * rstd * g[c] + b[c];
            g_nxh[(size_t)u * kC + c] = __float2bfloat16(nv);
            if (u < kU) g_xr[(size_t)u * kC + c] = vals[j];
#pragma unroll
            for (int e = 0; e < 8; e++) acc[e] += nv * wreg[j][e];
        }
#pragma unroll
        for (int o = 16; o; o >>= 1)
#pragma unroll
            for (int e = 0; e < 8; e++)
                acc[e] += __shfl_xor_sync(0xffffffffu, acc[e], o);
        if (lane < kH) g_ql[(size_t)u * kH + lane] = (acc[lane] + qab) * kSCALE;
    }
}

// ============ bf16 GEMM: CTA 128x256, 512 thr, 3-stage, W pre-transposed [n][k] ============
constexpr int HP   = 40;
constexpr int ASZH = 128 * HP;
constexpr int BSZH = 256 * HP;
constexpr int GEMM_SMEM = 3 * (ASZH + BSZH) * 2;   // 92160 bytes
constexpr int BPITCH = 264;

__device__ __forceinline__ void mma_bf16(float (&d)[4], const uint32_t (&a)[4],
                                         const uint32_t (&bb)[2]) {
    asm volatile(
        "mma.sync.aligned.m16n8k16.row.col.f32.bf16.bf16.f32 "
        "{%0,%1,%2,%3}, {%4,%5,%6,%7}, {%8,%9}, {%0,%1,%2,%3};\n"
        : "+f"(d[0]), "+f"(d[1]), "+f"(d[2]), "+f"(d[3])
        : "r"(a[0]), "r"(a[1]), "r"(a[2]), "r"(a[3]), "r"(bb[0]), "r"(bb[1]));
}
__device__ __forceinline__ void cpa16(uint32_t dst, const void* src, bool pred) {
    int sz = pred ? 16 : 0;
    asm volatile("cp.async.cg.shared.global [%0], [%1], 16, %2;\n"
                 :: "r"(dst), "l"(src), "r"(sz));
}
__device__ __forceinline__ float gelu_exact(float x) {
    return 0.5f * x * (1.0f + erff(x * 0.70710678118654752f));
}

template<int EPI, int NPAIR>
__global__ void __launch_bounds__(512, 1) k_gemm7(const __nv_bfloat16* __restrict__ A1,
                                                  const __nv_bfloat16* __restrict__ W1,
                                                  const __nv_bfloat16* __restrict__ A2,
                                                  const __nv_bfloat16* __restrict__ W2,
                                                  const float* __restrict__ bias,
                                                  const float* __restrict__ addm,
                                                  float* __restrict__ D,
                                                  __nv_bfloat16* __restrict__ Dh,
                                                  const float* __restrict__ lng,
                                                  const float* __restrict__ lnb,
                                                  int M, int ldD) {
    extern __shared__ char smc[];
    __nv_bfloat16* As = (__nv_bfloat16*)smc;          // 3 x ASZH
    __nv_bfloat16* Bs = As + 3 * ASZH;                // 3 x BSZH
    float* ep = (float*)smc;                          // epilogue staging
    uint32_t sA = (uint32_t)__cvta_generic_to_shared(As);
    uint32_t sB = (uint32_t)__cvta_generic_to_shared(Bs);

    int coly = blockIdx.y * 256;        // column slab (QKV fused GEMM)
    bias += coly;
    if (D)  D  += coly;
    if (Dh) Dh += coly;

    int tid = threadIdx.x, lane = tid & 31, warp = tid >> 5;
    int wm = warp >> 2, wn = warp & 3;  // 4 x 4 warp grid, warp tile 32x64
    int p = lane >> 2, q = lane & 3;
    int row0 = blockIdx.x * 128;
    int mbase = wm * 32, nbase = wn * 64;

    int ar = tid & 127, ah = tid >> 7;       // A: row, 8-elem chunk
    int bn = tid & 255, bh = tid >> 8;       // B: n-row, chunk-pair
    bool arow_ok = (row0 + ar) < M;
    const __nv_bfloat16* A1g = A1 + (size_t)(row0 + ar) * kC + ah * 8;
    const __nv_bfloat16* W1g = W1 + (size_t)(coly + bn) * kC + bh * 16;
    const __nv_bfloat16* A2g = (NPAIR == 2) ? (A2 + (size_t)(row0 + ar) * kC + ah * 8) : A1g;
    const __nv_bfloat16* W2g = (NPAIR == 2) ? (W2 + (size_t)(coly + bn) * kC + bh * 16) : W1g;
    uint32_t adst0 = sA + (uint32_t)((ar * HP + ah * 8) * 2);
    uint32_t bdst0 = sB + (uint32_t)((bn * HP + bh * 16) * 2);

    auto issue = [&](int kt) {
        int ktt = kt & 7;
        int buf = kt % 3;
        const __nv_bfloat16* as = ((NPAIR == 2 && (kt >> 3)) ? A2g : A1g) + ktt * 32;
        const __nv_bfloat16* bs = ((NPAIR == 2 && (kt >> 3)) ? W2g : W1g) + ktt * 32;
        cpa16(adst0 + (uint32_t)(buf * ASZH * 2), as, arow_ok);
        uint32_t bd = bdst0 + (uint32_t)(buf * BSZH * 2);
        cpa16(bd,      bs,     true);
        cpa16(bd + 16, bs + 8, true);
    };

    float acc[2][8][4] = {};
    const int TOT = 8 * NPAIR;

    issue(0);
    asm volatile("cp.async.commit_group;\n");
    issue(1);
    asm volatile("cp.async.commit_group;\n");

#pragma unroll 1
    for (int kt = 0; kt < TOT; kt++) {
        if (kt < TOT - 1) asm volatile("cp.async.wait_group 1;\n");
        else              asm volatile("cp.async.wait_group 0;\n");
        __syncthreads();
        if (kt + 2 < TOT) {
            issue(kt + 2);
            asm volatile("cp.async.commit_group;\n");
        }
        int buf = kt % 3;
        const __nv_bfloat16* Ab = As + buf * ASZH;
        const __nv_bfloat16* Bb = Bs + buf * BSZH;
#pragma unroll
        for (int kk = 0; kk < 32; kk += 16) {
            uint32_t af[2][4], bf[8][2];
#pragma unroll
            for (int mi = 0; mi < 2; mi++) {
                const __nv_bfloat16* a0 = Ab + (mbase + mi * 16 + p) * HP + kk + 2 * q;
                af[mi][0] = *(const uint32_t*)(a0);
                af[mi][1] = *(const uint32_t*)(a0 + 8 * HP);
                af[mi][2] = *(const uint32_t*)(a0 + 8);
                af[mi][3] = *(const uint32_t*)(a0 + 8 * HP + 8);
            }
#pragma unroll
            for (int ni = 0; ni < 8; ni++) {
                const __nv_bfloat16* b0 = Bb + (nbase + ni * 8 + p) * HP + kk + 2 * q;
                bf[ni][0] = *(const uint32_t*)(b0);
                bf[ni][1] = *(const uint32_t*)(b0 + 8);
            }
#pragma unroll
            for (int mi = 0; mi < 2; mi++)
#pragma unroll
                for (int ni = 0; ni < 8; ni++)
                    mma_bf16(acc[mi][ni], af[mi], bf[ni]);
        }
    }
    __syncthreads();

    // ---------------- epilogue ----------------
    if (EPI == 0 || EPI == 2) {
#pragma unroll
        for (int mi = 0; mi < 2; mi++) {
            int r1 = row0 + mbase + mi * 16 + p;
            int r2 = r1 + 8;
#pragma unroll
            for (int ni = 0; ni < 8; ni++) {
                int cc = nbase + ni * 8 + 2 * q;
                float2 bv = *(const float2*)(bias + cc);
                float d0 = acc[mi][ni][0] + bv.x, d1 = acc[mi][ni][1] + bv.y;
                float d2 = acc[mi][ni][2] + bv.x, d3 = acc[mi][ni][3] + bv.y;
                if (EPI == 2) {
                    d0 = gelu_exact(d0); d1 = gelu_exact(d1);
                    d2 = gelu_exact(d2); d3 = gelu_exact(d3);
                }
                __nv_bfloat162 o1 = {__float2bfloat16(d0), __float2bfloat16(d1)};
                __nv_bfloat162 o2 = {__float2bfloat16(d2), __float2bfloat16(d3)};
                if (r1 < M) *(__nv_bfloat162*)(Dh + (size_t)r1 * ldD + cc) = o1;
                if (r2 < M) *(__nv_bfloat162*)(Dh + (size_t)r2 * ldD + cc) = o2;
            }
        }
    } else {
#pragma unroll 1
        for (int half = 0; half < 2; half++) {
            __syncthreads();
            if ((wm >> 1) == half) {
#pragma unroll
                for (int mi = 0; mi < 2; mi++) {
                    int lr1 = mbase + mi * 16 + p;
                    int lr2 = lr1 + 8;
                    int r1 = row0 + lr1, r2 = row0 + lr2;
                    int e1 = lr1 - half * 64, e2 = lr2 - half * 64;
#pragma unroll
                    for (int ni = 0; ni < 8; ni++) {
                        int cc = nbase + ni * 8 + 2 * q;
                        float2 bv = *(const float2*)(bias + cc);
                        float2 a1 = *(const float2*)(addm + (size_t)r1 * kC + cc);
                        float2 a2 = *(const float2*)(addm + (size_t)r2 * kC + cc);
                        float2 o1 = {acc[mi][ni][0] + bv.x + a1.x, acc[mi][ni][1] + bv.y + a1.y};
                        float2 o2 = {acc[mi][ni][2] + bv.x + a2.x, acc[mi][ni][3] + bv.y + a2.y};
                        if (EPI == 3) {
                            *(float2*)(D + (size_t)r1 * ldD + cc) = o1;   // attraw
                            *(float2*)(D + (size_t)r2 * ldD + cc) = o2;
                        }
                        *(float2*)(ep + e1 * BPITCH + cc) = o1;
                        *(float2*)(ep + e2 * BPITCH + cc) = o2;
                    }
                }
            }
            __syncthreads();
            if (EPI == 3) {   // fused LN over 64 staged rows -> bf16 Dh
                float gg[8], bb[8];
#pragma unroll
                for (int j = 0; j < 8; j++) {
                    int c = lane + 32 * j;
                    gg[j] = lng[c]; bb[j] = lnb[c];
                }
#pragma unroll
                for (int rr = 0; rr < 4; rr++) {
                    int lr = warp * 4 + rr;            // 0..63
                    float vals[8]; float s = 0.f, sq = 0.f;
#pragma unroll
                    for (int j = 0; j < 8; j++) {
                        float t = ep[lr * BPITCH + lane + 32 * j];
                        vals[j] = t; s += t; sq += t * t;
                    }
#pragma unroll
                    for (int o = 16; o; o >>= 1) {
                        s  += __shfl_xor_sync(0xffffffffu, s,  o);
                        sq += __shfl_xor_sync(0xffffffffu, sq, o);
                    }
                    float mean = s * (1.f / kC);
                    float var  = sq * (1.f / kC) - mean * mean;
                    float rstd = rsqrtf(var + 1e-5f);
                    int gr = row0 + half * 64 + lr;
#pragma unroll
                    for (int j = 0; j < 8; j++) {
                        int c = lane + 32 * j;
                        Dh[(size_t)gr * kC + c] = __float2bfloat16((vals[j] - mean) * rstd * gg[j] + bb[j]);
                    }
                }
            } else {          // EPI 4: transposed write to out (n,c,t,v)
#pragma unroll 1
                for (int it = 0; it < 32; it++) {
                    int j = it * 512 + tid;
                    int c = j >> 6, rr = j & 63;
                    unsigned R = (unsigned)(row0 + half * 64 + rr);
                    unsigned b = R / 25u;
                    unsigned v = R - b * 25u;
                    unsigned n = b >> 6, t = b & 63u;
                    D[(size_t)n * kXN + (size_t)c * kTV + t * kV + v] = ep[rr * BPITCH + c];
                }
            }
        }
    }
}

// ============ fused per-window pooling v3: 3 CTA/SM, lean smem, short reductions ============
constexpr int KAP = 12;
__global__ void __launch_bounds__(256, 3) k_pool(const float* __restrict__ ka_w,
                                                 const float* __restrict__ ka_b) {
    __shared__ int   su[kL];
    __shared__ float sqw[kH][128];
    __shared__ float skw[kH][128];
    __shared__ float spq[kC];
    __shared__ __align__(16) float skaw[kC * KAP];
    __shared__ float sred[kH][kH][9];   // per-warp partial staging
    int tid = threadIdx.x, lane = tid & 31, h = tid >> 5;
    int b = blockIdx.x, n = b / kT, t = b % kT;

    for (int i = tid; i < kC * kH; i += 256) {
        int c = i >> 3, e = i & 7;
        skaw[c * KAP + e] = ka_w[i];
    }
    if (tid < kL) {
        int w = tid / kV, v = tid - w * kV;
        int tp = t + w - 2;
        su[tid] = (tp >= 0 && tp < kT) ? (n * kT + tp) * kV + v : kU;
    }
    float kab = (lane < kH) ? ka_b[lane] : 0.f;
    __syncthreads();

    // ---- q-weight softmax (warp h over l) ----
    {
        float lv[4]; float mx = -1e30f;
#pragma unroll
        for (int i = 0; i < 4; i++) {
            int l = lane + 32 * i;
            lv[i] = (l < kL) ? g_ql[(size_t)su[l] * kH + h] : -1e30f;
            mx = fmaxf(mx, lv[i]);
        }
#pragma unroll
        for (int o = 16; o; o >>= 1) mx = fmaxf(mx, __shfl_xor_sync(0xffffffffu, mx, o));
        float sm = 0.f;
#pragma unroll
        for (int i = 0; i < 4; i++) {
            int l = lane + 32 * i;
            lv[i] = (l < kL) ? expf(lv[i] - mx) : 0.f;
            sm += lv[i];
        }
#pragma unroll
        for (int o = 16; o; o >>= 1) sm += __shfl_xor_sync(0xffffffffu, sm, o);
        float inv = 1.f / sm;
#pragma unroll
        for (int i = 0; i < 4; i++) {
            int l = lane + 32 * i;
            if (l < kL) sqw[h][l] = lv[i] * inv;
        }
    }
    __syncthreads();

    // ---- pass A: pq + mq (q slice) ----
    float pq = 0.f;
#pragma unroll 5
    for (int v = 0; v < kV; v++) {
        float a = 0.f;
#pragma unroll
        for (int w = 0; w < kWIN; w++) {
            int l = w * kV + v;
            float val = __bfloat162float(g_qkvh[(size_t)su[l] * kC3 + tid]);
            pq += sqw[h][l] * val;
            a  += val;
        }
        g_mqh[((size_t)b * kV + v) * kC + tid] = __float2bfloat16(a * 0.2f);
    }
    spq[tid] = pq;
    __syncthreads();

    // ---- pass B: k logits (k slice); 2-round butterfly + smem transpose ----
    float pqr[8];
#pragma unroll
    for (int j = 0; j < 8; j++) pqr[j] = spq[lane + 32 * j];
#pragma unroll 1
    for (int l = h; l < kL; l += kH) {
        const __nv_bfloat16* kr = g_qkvh + (size_t)su[l] * kC3 + 256;
        float acc[8] = {};
#pragma unroll
        for (int j = 0; j < 8; j++) {
            float kp = __bfloat162float(kr[lane + 32 * j]) * pqr[j];
            const float4* ka = (const float4*)(skaw + (lane + 32 * j) * KAP);
            float4 k0 = ka[0], k1 = ka[1];
            acc[0] += kp * k0.x; acc[1] += kp * k0.y;
            acc[2] += kp * k0.z; acc[3] += kp * k0.w;
            acc[4] += kp * k1.x; acc[5] += kp * k1.y;
            acc[6] += kp * k1.z; acc[7] += kp * k1.w;
        }
        // 2 butterfly rounds: every lane holds its mod-8 group partial
#pragma unroll
        for (int o = 16; o >= 8; o >>= 1)
#pragma unroll
            for (int e = 0; e < 8; e++)
                acc[e] += __shfl_xor_sync(0xffffffffu, acc[e], o);
        if (lane < 8) {
#pragma unroll
            for (int e = 0; e < 8; e++) sred[h][lane][e] = acc[e];
        }
        __syncwarp();
        if (lane < 8) {
            float s2 = 0.f;
#pragma unroll
            for (int m = 0; m < 8; m++) s2 += sred[h][m][lane];
            skw[lane][l] = (s2 + kab) * kSCALE;
        }
        __syncwarp();
    }
    __syncthreads();

    // ---- k-weight softmax ----
    {
        float lv[4]; float mx = -1e30f;
#pragma unroll
        for (int i = 0; i < 4; i++) {
            int l = lane + 32 * i;
            lv[i] = (l < kL) ? skw[h][l] : -1e30f;
            mx = fmaxf(mx, lv[i]);
        }
#pragma unroll
        for (int o = 16; o; o >>= 1) mx = fmaxf(mx, __shfl_xor_sync(0xffffffffu, mx, o));
        float sm = 0.f;
#pragma unroll
        for (int i = 0; i < 4; i++) {
            int l = lane + 32 * i;
            lv[i] = (l < kL) ? expf(lv[i] - mx) : 0.f;
            sm += lv[i];
        }
#pragma unroll
        for (int o = 16; o; o >>= 1) sm += __shfl_xor_sync(0xffffffffu, sm, o);
        float inv = 1.f / sm;
#pragma unroll
        for (int i = 0; i < 4; i++) {
            int l = lane + 32 * i;
            if (l < kL) skw[h][l] = lv[i] * inv;
        }
    }
    __syncthreads();

    // ---- pass C1: pk (k slice) ----
    float pk = 0.f;
#pragma unroll 5
    for (int v = 0; v < kV; v++) {
#pragma unroll
        for (int w = 0; w < kWIN; w++) {
            int l = w * kV + v;
            pk += skw[h][l] * __bfloat162float(g_qkvh[(size_t)su[l] * kC3 + 256 + tid]);
        }
    }
    // ---- pass C2: mv -> mkv = pk*mv (v slice, write-immediate) ----
#pragma unroll 5
    for (int v = 0; v < kV; v++) {
        float a = 0.f;
#pragma unroll
        for (int w = 0; w < kWIN; w++)
            a += __bfloat162float(g_qkvh[(size_t)su[w * kV + v] * kC3 + 512 + tid]);
        g_mkvh[((size_t)b * kV + v) * kC + tid] = __float2bfloat16(pk * a * 0.2f);
    }
}

// ===================================================================================
extern "C" void kernel_launch(void* const* d_in, const int* in_sizes, int n_in,
                              void* d_out, int out_size) {
    const float* x    = (const float*)d_in[0];
    const float* ln1g = (const float*)d_in[1];
    const float* ln1b = (const float*)d_in[2];
    const float* q_w  = (const float*)d_in[3];
    const float* q_b  = (const float*)d_in[4];
    const float* qa_w = (const float*)d_in[5];
    const float* qa_b = (const float*)d_in[6];
    const float* k_w  = (const float*)d_in[7];
    const float* k_b  = (const float*)d_in[8];
    const float* ka_w = (const float*)d_in[9];
    const float* ka_b = (const float*)d_in[10];
    const float* v_w  = (const float*)d_in[11];
    const float* v_b  = (const float*)d_in[12];
    const float* t_w  = (const float*)d_in[13];
    const float* t_b  = (const float*)d_in[14];
    const float* p_w  = (const float*)d_in[15];
    const float* p_b  = (const float*)d_in[16];
    const float* ffng = (const float*)d_in[17];
    const float* ffnb = (const float*)d_in[18];
    const float* w1   = (const float*)d_in[19];
    const float* b1   = (const float*)d_in[20];
    const float* w2   = (const float*)d_in[21];
    const float* b2   = (const float*)d_in[22];
    float* out = (float*)d_out;

    float *p_k, *p_xr, *p_tb, *p_qkvb;
    __nv_bfloat16 *p_nxh, *p_qkvh, *p_fh, *p_mkvh, *p_mqh, *p_h1h, *p_twT, *p_wqkvT, *p_wpT, *p_w1T, *p_w2T;
    cudaGetSymbolAddress((void**)&p_k,     g_k);
    cudaGetSymbolAddress((void**)&p_xr,    g_xr);
    cudaGetSymbolAddress((void**)&p_tb,    g_tb);
    cudaGetSymbolAddress((void**)&p_qkvb,  g_qkvb);
    cudaGetSymbolAddress((void**)&p_nxh,   g_nxh);
    cudaGetSymbolAddress((void**)&p_qkvh,  g_qkvh);
    cudaGetSymbolAddress((void**)&p_fh,    g_fh);
    cudaGetSymbolAddress((void**)&p_mkvh,  g_mkvh);
    cudaGetSymbolAddress((void**)&p_mqh,   g_mqh);
    cudaGetSymbolAddress((void**)&p_h1h,   g_h1h);
    cudaGetSymbolAddress((void**)&p_twT,   g_twT);
    cudaGetSymbolAddress((void**)&p_wqkvT, g_wqkvT);
    cudaGetSymbolAddress((void**)&p_wpT,   g_wpT);
    cudaGetSymbolAddress((void**)&p_w1T,   g_w1T);
    cudaGetSymbolAddress((void**)&p_w2T,   g_w2T);

    cudaFuncSetAttribute(k_gemm7<0,1>, cudaFuncAttributeMaxDynamicSharedMemorySize, GEMM_SMEM);
    cudaFuncSetAttribute(k_gemm7<2,1>, cudaFuncAttributeMaxDynamicSharedMemorySize, GEMM_SMEM);
    cudaFuncSetAttribute(k_gemm7<3,2>, cudaFuncAttributeMaxDynamicSharedMemorySize, GEMM_SMEM);
    cudaFuncSetAttribute(k_gemm7<4,1>, cudaFuncAttributeMaxDynamicSharedMemorySize, GEMM_SMEM);

    dim3 gqkv((kM1 + 127) / 128, 3);   // 401 x 3
    int g2 = kU / 128;                 // 400

    // 0) prep: tp_w/tp_b + transposed bf16 weights + qaw' + biases
    k_prep<<<257 + 384 + 3 + 1, 256>>>(t_w, p_w, t_b, p_b, q_w, k_w, v_w, w1, w2,
                                       q_b, k_b, v_b, qa_w, qa_b);
    // 1) LN of unique tokens -> bf16 nx + fp32 xr + fused qlog
    k_ln_x<<<(kM1 + 31) / 32, 256>>>(x, ln1g, ln1b);
    // 2) fused q|k|v projection -> g_qkvh bf16 (row pitch 768)
    k_gemm7<0,1><<<gqkv, 512, GEMM_SMEM>>>(p_nxh, p_wqkvT, nullptr, nullptr, p_qkvb, nullptr,
                                           nullptr, p_qkvh, nullptr, nullptr, kM1, kC3);
    // 3) fused pooling -> mq (bf16), mkv (bf16)
    k_pool<<<kB, 256>>>(ka_w, ka_b);
    // 4) attraw = mkv@tp_w + mq@p_w + tp_b + xr -> g_k fp32 ; fused LN -> f bf16
    k_gemm7<3,2><<<g2, 512, GEMM_SMEM>>>(p_mkvh, p_twT, p_mqh, p_wpT, p_tb, p_xr,
                                         p_k, p_fh, ffng, ffnb, kU, kC);
    // 5) h1 = gelu(f @ w1 + b1) -> bf16
    k_gemm7<2,1><<<g2, 512, GEMM_SMEM>>>(p_fh, p_w1T, nullptr, nullptr, b1, nullptr,
                                         nullptr, p_h1h, nullptr, nullptr, kU, kC);
    // 6) y = h1 @ w2 + b2 + attraw -> transposed out
    k_gemm7<4,1><<<g2, 512, GEMM_SMEM>>>(p_h1h, p_w2T, nullptr, nullptr, b2, p_k,
                                         out, nullptr, nullptr, nullptr, kU, kC);
}